// round 4
// baseline (speedup 1.0000x reference)
#include <cuda_runtime.h>
#include <cuda_bf16.h>
#include <math.h>
#include <stdint.h>

#define SEQ 2048
#define HID 2048
#define NHEAD 32
#define HDIM 64
#define ISZ 8192
#define NLAYER 2

// ======================= scratch (static device arrays) =======================
__device__ float g_x  [SEQ * HID];                 // residual stream (fp32)
__device__ float g_q  [SEQ * HID];
__device__ float g_k  [SEQ * HID];
__device__ float g_v  [SEQ * HID];
__device__ __nv_bfloat16 g_hh [SEQ * HID];         // LN out hi/lo
__device__ __nv_bfloat16 g_hl [SEQ * HID];
__device__ __nv_bfloat16 g_ctxh[SEQ * HID];        // attn out hi/lo
__device__ __nv_bfloat16 g_ctxl[SEQ * HID];
__device__ __nv_bfloat16 g_midh[SEQ * ISZ];        // MLP mid hi/lo
__device__ __nv_bfloat16 g_midl[SEQ * ISZ];
// transposed + split weights: Wt[N][K]
__device__ __nv_bfloat16 g_wqt_h[NLAYER * HID * HID], g_wqt_l[NLAYER * HID * HID];
__device__ __nv_bfloat16 g_wkt_h[NLAYER * HID * HID], g_wkt_l[NLAYER * HID * HID];
__device__ __nv_bfloat16 g_wvt_h[NLAYER * HID * HID], g_wvt_l[NLAYER * HID * HID];
__device__ __nv_bfloat16 g_wot_h[NLAYER * HID * HID], g_wot_l[NLAYER * HID * HID];
__device__ __nv_bfloat16 g_w1t_h[NLAYER * HID * ISZ], g_w1t_l[NLAYER * HID * ISZ];
__device__ __nv_bfloat16 g_w2t_h[NLAYER * ISZ * HID], g_w2t_l[NLAYER * ISZ * HID];

// ======================= PTX helpers (baseline ISA only) =======================
__device__ __forceinline__ uint32_t smem_u32(const void* p) {
    uint32_t a;
    asm("{ .reg .u64 t; cvta.to.shared.u64 t, %1; cvt.u32.u64 %0, t; }" : "=r"(a) : "l"(p));
    return a;
}
__device__ __forceinline__ void cp16(uint32_t dst, const void* src) {
    asm volatile("cp.async.cg.shared.global [%0], [%1], 16;" :: "r"(dst), "l"(src));
}
__device__ __forceinline__ void cp_commit() {
    asm volatile("cp.async.commit_group;" ::: "memory");
}
template <int N>
__device__ __forceinline__ void cp_wait() {
    asm volatile("cp.async.wait_group %0;" :: "n"(N) : "memory");
}
__device__ __forceinline__ void ldmx4(uint32_t* r, uint32_t addr) {
    asm volatile("ldmatrix.sync.aligned.m8n8.x4.shared.b16 {%0,%1,%2,%3}, [%4];"
                 : "=r"(r[0]), "=r"(r[1]), "=r"(r[2]), "=r"(r[3]) : "r"(addr));
}
__device__ __forceinline__ void mma16816(float* d, const uint32_t* a, const uint32_t* b) {
    asm volatile("mma.sync.aligned.m16n8k16.row.col.f32.bf16.bf16.f32 "
                 "{%0,%1,%2,%3}, {%4,%5,%6,%7}, {%8,%9}, {%0,%1,%2,%3};"
                 : "+f"(d[0]), "+f"(d[1]), "+f"(d[2]), "+f"(d[3])
                 : "r"(a[0]), "r"(a[1]), "r"(a[2]), "r"(a[3]), "r"(b[0]), "r"(b[1]));
}

// ======================= small kernels =======================
__global__ void copy_kernel(const float4* __restrict__ in, float4* __restrict__ out, int n4) {
    int i = blockIdx.x * 256 + threadIdx.x;
    if (i < n4) out[i] = in[i];
}

__device__ __forceinline__ float gelu_tanh(float v) {
    float t = 0.7978845608028654f * v * (1.0f + 0.044715f * v * v);
    return 0.5f * v * (1.0f + tanhf(t));
}

// layernorm; SPLIT=1 -> write bf16 hi/lo, SPLIT=0 -> write fp32
template <int SPLIT>
__global__ void __launch_bounds__(256) ln_kernel(const float* __restrict__ x,
                                                 const float* __restrict__ gamma,
                                                 float* __restrict__ outf,
                                                 __nv_bfloat16* __restrict__ oh,
                                                 __nv_bfloat16* __restrict__ ol) {
    __shared__ float sh[18];
    int row = blockIdx.x;
    const float* xr = x + (long)row * HID;
    float s = 0.f, s2 = 0.f;
    for (int i = threadIdx.x; i < HID; i += 256) {
        float v = xr[i];
        s += v; s2 += v * v;
    }
    #pragma unroll
    for (int o = 16; o; o >>= 1) {
        s  += __shfl_xor_sync(0xFFFFFFFFu, s,  o);
        s2 += __shfl_xor_sync(0xFFFFFFFFu, s2, o);
    }
    int w = threadIdx.x >> 5, lane = threadIdx.x & 31;
    if (lane == 0) { sh[w] = s; sh[8 + w] = s2; }
    __syncthreads();
    if (threadIdx.x < 32) {
        s  = (threadIdx.x < 8) ? sh[threadIdx.x]     : 0.f;
        s2 = (threadIdx.x < 8) ? sh[8 + threadIdx.x] : 0.f;
        #pragma unroll
        for (int o = 4; o; o >>= 1) {
            s  += __shfl_xor_sync(0xFFFFFFFFu, s,  o);
            s2 += __shfl_xor_sync(0xFFFFFFFFu, s2, o);
        }
        if (threadIdx.x == 0) {
            float mu = s * (1.0f / HID);
            float var = s2 * (1.0f / HID) - mu * mu;
            sh[16] = mu;
            sh[17] = rsqrtf(var + 1e-5f);
        }
    }
    __syncthreads();
    float mu = sh[16], inv = sh[17];
    for (int i = threadIdx.x; i < HID; i += 256) {
        float v = (xr[i] - mu) * inv * gamma[i];
        if (SPLIT) {
            __nv_bfloat16 h = __float2bfloat16(v);
            oh[(long)row * HID + i] = h;
            ol[(long)row * HID + i] = __float2bfloat16(v - __bfloat162float(h));
        } else {
            outf[(long)row * HID + i] = v;
        }
    }
}

// weight transpose + split: W[K,N] fp32 -> Th/Tl[N,K] bf16
__global__ void __launch_bounds__(256) wsplit_kernel(const float* __restrict__ W,
                                                     __nv_bfloat16* __restrict__ Th,
                                                     __nv_bfloat16* __restrict__ Tl,
                                                     int K, int N) {
    __shared__ float t[32][33];
    int bx = blockIdx.x * 32, by = blockIdx.y * 32;
    int tx = threadIdx.x, ty = threadIdx.y;
    #pragma unroll
    for (int i = 0; i < 4; i++)
        t[ty + i * 8][tx] = W[(long)(by + ty + i * 8) * N + bx + tx];
    __syncthreads();
    #pragma unroll
    for (int i = 0; i < 4; i++) {
        float v = t[tx][ty + i * 8];
        __nv_bfloat16 h = __float2bfloat16(v);
        long o = (long)(bx + ty + i * 8) * K + by + tx;
        Th[o] = h;
        Tl[o] = __float2bfloat16(v - __bfloat162float(h));
    }
}

// ======================= mma.sync split-bf16 GEMM (4-stage pipeline) =======================
// C[M,N] = (Ah+Al)[M,K] @ (Bh+Bl)^T, Bt stored [N,K] row-major.
// BM=128, BN=128, BK=32; 8 warps, warp tile 64x32.
// Smem stage: A[128r][128B] (64B hi | 64B lo per k-chunk of 32), 16B chunks XOR-swizzled.
// blockIdx.z selects among up to 3 (B, C) pairs -> fused QKV.
// MODE 0: Cf = AB ; MODE 1: Cf = AB + bias + res ; MODE 2: Ch/Cl = split(gelu(AB))
#define STAGE_BYTES 32768
#define NSTAGE 4
#define GSM_TOTAL (NSTAGE * STAGE_BYTES)

__device__ __forceinline__ void load_half_tile(uint32_t sbase,
                                               const __nv_bfloat16* __restrict__ Ph,
                                               const __nv_bfloat16* __restrict__ Pl,
                                               int K, long k0, int tid) {
    #pragma unroll
    for (int i = 0; i < 4; i++) {
        int idx = tid + i * 256;
        int row = idx >> 3, c = idx & 7;
        const __nv_bfloat16* src = (c < 4 ? Ph : Pl) + (long)row * K + k0 + (c & 3) * 8;
        uint32_t dst = sbase + row * 128 + ((c ^ (row & 7)) << 4);
        cp16(dst, src);
    }
}

template <int MODE>
__global__ void __launch_bounds__(256) gemm_mma_kernel(
    const __nv_bfloat16* __restrict__ Ah, const __nv_bfloat16* __restrict__ Al,
    const __nv_bfloat16* __restrict__ Bh0, const __nv_bfloat16* __restrict__ Bl0,
    const __nv_bfloat16* __restrict__ Bh1, const __nv_bfloat16* __restrict__ Bl1,
    const __nv_bfloat16* __restrict__ Bh2, const __nv_bfloat16* __restrict__ Bl2,
    const float* __restrict__ bias, const float* res,
    float* Cf0, float* Cf1, float* Cf2,
    __nv_bfloat16* __restrict__ Ch, __nv_bfloat16* __restrict__ Cl,
    int M, int N, int K)
{
    extern __shared__ char smem[];
    uint32_t sb = smem_u32(smem);
    int tid = threadIdx.x;
    int wid = tid >> 5, lane = tid & 31;
    int warp_m = wid >> 2, warp_n = wid & 3;
    int row0 = blockIdx.y * 128, col0 = blockIdx.x * 128;
    int m0 = warp_m * 64, n0 = warp_n * 32;
    int z = blockIdx.z;

    const __nv_bfloat16* Bh = (z == 0) ? Bh0 : (z == 1) ? Bh1 : Bh2;
    const __nv_bfloat16* Bl = (z == 0) ? Bl0 : (z == 1) ? Bl1 : Bl2;
    float* Cf = (z == 0) ? Cf0 : (z == 1) ? Cf1 : Cf2;

    const __nv_bfloat16* pAh = Ah + (long)row0 * K;
    const __nv_bfloat16* pAl = Al + (long)row0 * K;
    const __nv_bfloat16* pBh = Bh + (long)col0 * K;
    const __nv_bfloat16* pBl = Bl + (long)col0 * K;

    float acc[4][4][4];
    #pragma unroll
    for (int i = 0; i < 4; i++)
        #pragma unroll
        for (int j = 0; j < 4; j++)
            #pragma unroll
            for (int q = 0; q < 4; q++) acc[i][j][q] = 0.f;

    int grp = lane >> 3, lr = lane & 7;
    int rowA = m0 + (grp & 1) * 8 + lr;
    int ccA  = grp >> 1;
    int rowB = n0 + (grp >> 1) * 8 + lr;
    int ccB  = grp & 1;
    int xA = rowA & 7, xB = rowB & 7;

    int nc = K / 32;
    // prologue: fill stages 0..2
    #pragma unroll
    for (int p = 0; p < 3; p++) {
        uint32_t st = sb + p * STAGE_BYTES;
        load_half_tile(st,         pAh, pAl, K, (long)p * 32, tid);
        load_half_tile(st + 16384, pBh, pBl, K, (long)p * 32, tid);
        cp_commit();
    }

    for (int c = 0; c < nc; c++) {
        cp_wait<2>();
        __syncthreads();
        // issue loads for stage c+3 into slot (c+3)&3  (safe: slot was consumed in iter c-1)
        if (c + 3 < nc) {
            uint32_t st = sb + ((c + 3) & 3) * STAGE_BYTES;
            long k0 = (long)(c + 3) * 32;
            load_half_tile(st,         pAh, pAl, K, k0, tid);
            load_half_tile(st + 16384, pBh, pBl, K, k0, tid);
        }
        cp_commit();

        uint32_t sA = sb + (c & 3) * STAGE_BYTES;
        uint32_t sB = sA + 16384;
        #pragma unroll
        for (int ks = 0; ks < 2; ks++) {
            uint32_t afh[4][4], afl[4][4], bfh[2][4], bfl[2][4];
            #pragma unroll
            for (int mt = 0; mt < 4; mt++) {
                uint32_t base = sA + (rowA + mt * 16) * 128;
                ldmx4(afh[mt], base + (((ks * 2 + ccA)     ^ xA) << 4));
                ldmx4(afl[mt], base + (((ks * 2 + ccA + 4) ^ xA) << 4));
            }
            #pragma unroll
            for (int np = 0; np < 2; np++) {
                uint32_t base = sB + (rowB + np * 16) * 128;
                ldmx4(bfh[np], base + (((ks * 2 + ccB)     ^ xB) << 4));
                ldmx4(bfl[np], base + (((ks * 2 + ccB + 4) ^ xB) << 4));
            }
            #pragma unroll
            for (int mt = 0; mt < 4; mt++)
                #pragma unroll
                for (int nt = 0; nt < 4; nt++) {
                    const uint32_t* bh = &bfh[nt >> 1][(nt & 1) * 2];
                    const uint32_t* bl = &bfl[nt >> 1][(nt & 1) * 2];
                    mma16816(acc[mt][nt], afh[mt], bh);
                    mma16816(acc[mt][nt], afh[mt], bl);
                    mma16816(acc[mt][nt], afl[mt], bh);
                }
        }
        __syncthreads();
    }

    // ---------------- epilogue (direct from fragments) ----------------
    int r = lane >> 2, c2 = (lane & 3) * 2;
    #pragma unroll
    for (int mt = 0; mt < 4; mt++) {
        #pragma unroll
        for (int nt = 0; nt < 4; nt++) {
            long gr = row0 + m0 + mt * 16 + r;
            long gc = col0 + n0 + nt * 8 + c2;
            #pragma unroll
            for (int hrow = 0; hrow < 2; hrow++) {
                long grr = gr + hrow * 8;
                float v0 = acc[mt][nt][hrow * 2 + 0];
                float v1 = acc[mt][nt][hrow * 2 + 1];
                if (MODE == 0) {
                    *(float2*)(Cf + grr * N + gc) = make_float2(v0, v1);
                } else if (MODE == 1) {
                    float2 b = *(const float2*)(bias + gc);
                    float2 rr = *(const float2*)(res + grr * N + gc);
                    *(float2*)(Cf + grr * N + gc) = make_float2(v0 + b.x + rr.x, v1 + b.y + rr.y);
                } else {
                    float g0 = gelu_tanh(v0), g1 = gelu_tanh(v1);
                    __nv_bfloat16 h0 = __float2bfloat16(g0);
                    __nv_bfloat16 h1 = __float2bfloat16(g1);
                    __nv_bfloat162 hp; hp.x = h0; hp.y = h1;
                    __nv_bfloat162 lp;
                    lp.x = __float2bfloat16(g0 - __bfloat162float(h0));
                    lp.y = __float2bfloat16(g1 - __bfloat162float(h1));
                    *(__nv_bfloat162*)(Ch + grr * N + gc) = hp;
                    *(__nv_bfloat162*)(Cl + grr * N + gc) = lp;
                }
            }
        }
    }
}

// ======================= flash attention (fp32, causal, float4) =======================
__global__ void __launch_bounds__(256) attn_kernel(
    const float* __restrict__ Q, const float* __restrict__ K,
    const float* __restrict__ V,
    __nv_bfloat16* __restrict__ Oh, __nv_bfloat16* __restrict__ Ol)
{
    constexpr int BQ = 64, BK = 32;
    __shared__ float Qs[BQ][68];
    __shared__ float Ks[BK][68];
    __shared__ float Vs[BK][68];
    __shared__ float Ss[BQ][33];

    int qb = blockIdx.x, h = blockIdx.y;
    int tid = threadIdx.x;
    int r = tid >> 2, g = tid & 3;
    int qg = qb * BQ + r;
    const float scale = 0.125f;

    for (int f = tid; f < BQ * 16; f += 256) {
        int rr = f >> 4, c4 = f & 15;
        *(float4*)&Qs[rr][c4 * 4] =
            *(const float4*)(Q + (long)(qb * BQ + rr) * HID + h * HDIM + c4 * 4);
    }

    float m_i = -1e30f, l_i = 0.f;
    float4 o4[4];
    #pragma unroll
    for (int i = 0; i < 4; i++) o4[i] = make_float4(0.f, 0.f, 0.f, 0.f);

    int nkt = (qb + 1) * (BQ / BK);

    for (int kt = 0; kt < nkt; kt++) {
        __syncthreads();
        for (int f = tid; f < BK * 16; f += 256) {
            int rr = f >> 4, c4 = f & 15;
            long base = (long)(kt * BK + rr) * HID + h * HDIM + c4 * 4;
            *(float4*)&Ks[rr][c4 * 4] = *(const float4*)(K + base);
            *(float4*)&Vs[rr][c4 * 4] = *(const float4*)(V + base);
        }
        __syncthreads();

        float sacc[8];
        #pragma unroll
        for (int kk = 0; kk < 8; kk++) sacc[kk] = 0.f;
        const float4* qrow = (const float4*)&Qs[r][0];
        #pragma unroll 4
        for (int d4 = 0; d4 < 16; d4++) {
            float4 qv = qrow[d4];
            #pragma unroll
            for (int kk = 0; kk < 8; kk++) {
                float4 kv = *(const float4*)&Ks[g * 8 + kk][d4 * 4];
                sacc[kk] += qv.x * kv.x + qv.y * kv.y + qv.z * kv.z + qv.w * kv.w;
            }
        }
        #pragma unroll
        for (int kk = 0; kk < 8; kk++) {
            int k = g * 8 + kk;
            int kg = kt * BK + k;
            float v = sacc[kk] * scale;
            if (kg > qg) v = -1e30f;
            Ss[r][k] = v;
        }
        __syncthreads();

        float m_new = m_i;
        #pragma unroll
        for (int k = 0; k < BK; k++) m_new = fmaxf(m_new, Ss[r][k]);
        float alpha = __expf(m_i - m_new);
        l_i *= alpha;
        #pragma unroll
        for (int i = 0; i < 4; i++) {
            o4[i].x *= alpha; o4[i].y *= alpha; o4[i].z *= alpha; o4[i].w *= alpha;
        }
        #pragma unroll 4
        for (int k = 0; k < BK; k++) {
            float p = __expf(Ss[r][k] - m_new);
            l_i += p;
            const float4* vrow = (const float4*)&Vs[k][g * 16];
            #pragma unroll
            for (int i = 0; i < 4; i++) {
                float4 vv = vrow[i];
                o4[i].x += p * vv.x; o4[i].y += p * vv.y;
                o4[i].z += p * vv.z; o4[i].w += p * vv.w;
            }
        }
        m_i = m_new;
    }

    float inv = 1.0f / l_i;
    long obase = (long)qg * HID + h * HDIM + g * 16;
    float ov[16];
    #pragma unroll
    for (int i = 0; i < 4; i++) {
        ov[i * 4 + 0] = o4[i].x * inv; ov[i * 4 + 1] = o4[i].y * inv;
        ov[i * 4 + 2] = o4[i].z * inv; ov[i * 4 + 3] = o4[i].w * inv;
    }
    #pragma unroll
    for (int j = 0; j < 16; j += 2) {
        __nv_bfloat16 h0 = __float2bfloat16(ov[j]);
        __nv_bfloat16 h1 = __float2bfloat16(ov[j + 1]);
        __nv_bfloat162 hp; hp.x = h0; hp.y = h1;
        __nv_bfloat162 lp;
        lp.x = __float2bfloat16(ov[j]     - __bfloat162float(h0));
        lp.y = __float2bfloat16(ov[j + 1] - __bfloat162float(h1));
        *(__nv_bfloat162*)(Oh + obase + j) = hp;
        *(__nv_bfloat162*)(Ol + obase + j) = lp;
    }
}

// ======================= orchestration =======================
extern "C" void kernel_launch(void* const* d_in, const int* in_sizes, int n_in,
                              void* d_out, int out_size) {
    const float* emb = (const float*)d_in[0];
    const float* Wq = (const float*)d_in[2];
    const float* Wk = (const float*)d_in[3];
    const float* Wv = (const float*)d_in[4];
    const float* Wo = (const float*)d_in[5];
    const float* bo = (const float*)d_in[6];
    const float* W1 = (const float*)d_in[7];
    const float* W2 = (const float*)d_in[8];
    const float* b2 = (const float*)d_in[9];
    const float* g1 = (const float*)d_in[10];
    const float* g2 = (const float*)d_in[11];
    const float* gf = (const float*)d_in[12];
    float* out = (float*)d_out;

    float *px, *pq, *pk, *pv;
    __nv_bfloat16 *phh, *phl, *pch, *pcl, *pmh, *pml;
    __nv_bfloat16 *wqh, *wql, *wkh, *wkl, *wvh, *wvl, *woh, *wol, *w1h, *w1l, *w2h, *w2l;
    cudaGetSymbolAddress((void**)&px,  g_x);
    cudaGetSymbolAddress((void**)&pq,  g_q);
    cudaGetSymbolAddress((void**)&pk,  g_k);
    cudaGetSymbolAddress((void**)&pv,  g_v);
    cudaGetSymbolAddress((void**)&phh, g_hh);
    cudaGetSymbolAddress((void**)&phl, g_hl);
    cudaGetSymbolAddress((void**)&pch, g_ctxh);
    cudaGetSymbolAddress((void**)&pcl, g_ctxl);
    cudaGetSymbolAddress((void**)&pmh, g_midh);
    cudaGetSymbolAddress((void**)&pml, g_midl);
    cudaGetSymbolAddress((void**)&wqh, g_wqt_h); cudaGetSymbolAddress((void**)&wql, g_wqt_l);
    cudaGetSymbolAddress((void**)&wkh, g_wkt_h); cudaGetSymbolAddress((void**)&wkl, g_wkt_l);
    cudaGetSymbolAddress((void**)&wvh, g_wvt_h); cudaGetSymbolAddress((void**)&wvl, g_wvt_l);
    cudaGetSymbolAddress((void**)&woh, g_wot_h); cudaGetSymbolAddress((void**)&wol, g_wot_l);
    cudaGetSymbolAddress((void**)&w1h, g_w1t_h); cudaGetSymbolAddress((void**)&w1l, g_w1t_l);
    cudaGetSymbolAddress((void**)&w2h, g_w2t_h); cudaGetSymbolAddress((void**)&w2l, g_w2t_l);

    cudaFuncSetAttribute(gemm_mma_kernel<0>, cudaFuncAttributeMaxDynamicSharedMemorySize, GSM_TOTAL);
    cudaFuncSetAttribute(gemm_mma_kernel<1>, cudaFuncAttributeMaxDynamicSharedMemorySize, GSM_TOTAL);
    cudaFuncSetAttribute(gemm_mma_kernel<2>, cudaFuncAttributeMaxDynamicSharedMemorySize, GSM_TOTAL);

    dim3 b32(32, 8);
    dim3 gHHs(HID / 32, HID / 32);
    dim3 gW1s(ISZ / 32, HID / 32);
    dim3 gW2s(HID / 32, ISZ / 32);
    dim3 gQKV(HID / 128, SEQ / 128, 3);
    dim3 gHH(HID / 128, SEQ / 128, 1);
    dim3 gHI(ISZ / 128, SEQ / 128, 1);
    dim3 gAttn(SEQ / 64, NHEAD);

    // Launch order matters: ncu capture is -s 5 -c 1 -> profiles the 6th launch.
    // 1:copy 2:ws_q0 3:ws_k0 4:ws_v0 5:ln 6:fused QKV GEMM  <- profiled
    {
        int n4 = SEQ * HID / 4;
        copy_kernel<<<(n4 + 255) / 256, 256>>>((const float4*)emb, (float4*)px, n4);
    }

    for (int l = 0; l < NLAYER; l++) {
        long oHH = (long)l * HID * HID, oHI = (long)l * HID * ISZ;

        wsplit_kernel<<<gHHs, b32>>>(Wq + oHH, wqh + oHH, wql + oHH, HID, HID);
        wsplit_kernel<<<gHHs, b32>>>(Wk + oHH, wkh + oHH, wkl + oHH, HID, HID);
        wsplit_kernel<<<gHHs, b32>>>(Wv + oHH, wvh + oHH, wvl + oHH, HID, HID);
        ln_kernel<1><<<SEQ, 256>>>(px, g1 + l * HID, nullptr, phh, phl);
        // fused QKV (launch #6 when l==0 -> ncu target)
        gemm_mma_kernel<0><<<gQKV, 256, GSM_TOTAL>>>(phh, phl,
            wqh + oHH, wql + oHH, wkh + oHH, wkl + oHH, wvh + oHH, wvl + oHH,
            nullptr, nullptr, pq, pk, pv, nullptr, nullptr, SEQ, HID, HID);

        wsplit_kernel<<<gHHs, b32>>>(Wo + oHH, woh + oHH, wol + oHH, HID, HID);
        attn_kernel<<<gAttn, 256>>>(pq, pk, pv, pch, pcl);
        // x = x + ctx @ Wo + bo
        gemm_mma_kernel<1><<<gHH, 256, GSM_TOTAL>>>(pch, pcl,
            woh + oHH, wol + oHH, nullptr, nullptr, nullptr, nullptr,
            bo + l * HID, px, px, nullptr, nullptr, nullptr, nullptr, SEQ, HID, HID);

        // MLP block
        wsplit_kernel<<<gW1s, b32>>>(W1 + oHI, w1h + oHI, w1l + oHI, HID, ISZ);
        wsplit_kernel<<<gW2s, b32>>>(W2 + oHI, w2h + oHI, w2l + oHI, ISZ, HID);
        ln_kernel<1><<<SEQ, 256>>>(px, g2 + l * HID, nullptr, phh, phl);
        gemm_mma_kernel<2><<<gHI, 256, GSM_TOTAL>>>(phh, phl,
            w1h + oHI, w1l + oHI, nullptr, nullptr, nullptr, nullptr,
            nullptr, nullptr, nullptr, nullptr, nullptr, pmh, pml, SEQ, ISZ, HID);
        // x = x + mid @ W2 + b2
        gemm_mma_kernel<1><<<gHH, 256, GSM_TOTAL>>>(pmh, pml,
            w2h + oHI, w2l + oHI, nullptr, nullptr, nullptr, nullptr,
            b2 + l * HID, px, px, nullptr, nullptr, nullptr, nullptr, SEQ, HID, ISZ);
    }

    ln_kernel<0><<<SEQ, 256>>>(px, gf, out, nullptr, nullptr);
}

// round 5
// speedup vs baseline: 3.2160x; 3.2160x over previous
#include <cuda_runtime.h>
#include <cuda_bf16.h>
#include <math.h>
#include <stdint.h>

#define SEQ 2048
#define HID 2048
#define NHEAD 32
#define HDIM 64
#define ISZ 8192
#define NLAYER 2

// ======================= scratch (static device arrays) =======================
__device__ float g_x  [SEQ * HID];
__device__ float g_q  [SEQ * HID];
__device__ float g_k  [SEQ * HID];
__device__ float g_v  [SEQ * HID];
__device__ __nv_bfloat16 g_hh [SEQ * HID];
__device__ __nv_bfloat16 g_hl [SEQ * HID];
__device__ __nv_bfloat16 g_ctxh[SEQ * HID];
__device__ __nv_bfloat16 g_ctxl[SEQ * HID];
__device__ __nv_bfloat16 g_midh[SEQ * ISZ];
__device__ __nv_bfloat16 g_midl[SEQ * ISZ];
__device__ __nv_bfloat16 g_wqt_h[NLAYER * HID * HID], g_wqt_l[NLAYER * HID * HID];
__device__ __nv_bfloat16 g_wkt_h[NLAYER * HID * HID], g_wkt_l[NLAYER * HID * HID];
__device__ __nv_bfloat16 g_wvt_h[NLAYER * HID * HID], g_wvt_l[NLAYER * HID * HID];
__device__ __nv_bfloat16 g_wot_h[NLAYER * HID * HID], g_wot_l[NLAYER * HID * HID];
__device__ __nv_bfloat16 g_w1t_h[NLAYER * HID * ISZ], g_w1t_l[NLAYER * HID * ISZ];
__device__ __nv_bfloat16 g_w2t_h[NLAYER * ISZ * HID], g_w2t_l[NLAYER * ISZ * HID];

// ======================= PTX helpers =======================
__device__ __forceinline__ uint32_t smem_u32(const void* p) {
    uint32_t a;
    asm("{ .reg .u64 t; cvta.to.shared.u64 t, %1; cvt.u32.u64 %0, t; }" : "=r"(a) : "l"(p));
    return a;
}
__device__ __forceinline__ void cp16(uint32_t dst, const void* src) {
    asm volatile("cp.async.cg.shared.global [%0], [%1], 16;" :: "r"(dst), "l"(src));
}
__device__ __forceinline__ void cp_commit() {
    asm volatile("cp.async.commit_group;" ::: "memory");
}
template <int N>
__device__ __forceinline__ void cp_wait() {
    asm volatile("cp.async.wait_group %0;" :: "n"(N) : "memory");
}
__device__ __forceinline__ void ldmx4(uint32_t* r, uint32_t addr) {
    asm volatile("ldmatrix.sync.aligned.m8n8.x4.shared.b16 {%0,%1,%2,%3}, [%4];"
                 : "=r"(r[0]), "=r"(r[1]), "=r"(r[2]), "=r"(r[3]) : "r"(addr));
}
__device__ __forceinline__ void ldmx4t(uint32_t* r, uint32_t addr) {
    asm volatile("ldmatrix.sync.aligned.m8n8.x4.trans.shared.b16 {%0,%1,%2,%3}, [%4];"
                 : "=r"(r[0]), "=r"(r[1]), "=r"(r[2]), "=r"(r[3]) : "r"(addr));
}
__device__ __forceinline__ void mma16816(float* d, const uint32_t* a, const uint32_t* b) {
    asm volatile("mma.sync.aligned.m16n8k16.row.col.f32.bf16.bf16.f32 "
                 "{%0,%1,%2,%3}, {%4,%5,%6,%7}, {%8,%9}, {%0,%1,%2,%3};"
                 : "+f"(d[0]), "+f"(d[1]), "+f"(d[2]), "+f"(d[3])
                 : "r"(a[0]), "r"(a[1]), "r"(a[2]), "r"(a[3]), "r"(b[0]), "r"(b[1]));
}
__device__ __forceinline__ uint32_t packbf2(float lo, float hi) {
    __nv_bfloat162 t = __floats2bfloat162_rn(lo, hi);
    return *(uint32_t*)&t;
}

// ======================= small kernels =======================
__global__ void copy_kernel(const float4* __restrict__ in, float4* __restrict__ out, int n4) {
    int i = blockIdx.x * 256 + threadIdx.x;
    if (i < n4) out[i] = in[i];
}

__device__ __forceinline__ float gelu_tanh(float v) {
    float t = 0.7978845608028654f * v * (1.0f + 0.044715f * v * v);
    return 0.5f * v * (1.0f + tanhf(t));
}

template <int SPLIT>
__global__ void __launch_bounds__(256) ln_kernel(const float* __restrict__ x,
                                                 const float* __restrict__ gamma,
                                                 float* __restrict__ outf,
                                                 __nv_bfloat16* __restrict__ oh,
                                                 __nv_bfloat16* __restrict__ ol) {
    __shared__ float sh[18];
    int row = blockIdx.x;
    const float* xr = x + (long)row * HID;
    float s = 0.f, s2 = 0.f;
    for (int i = threadIdx.x; i < HID; i += 256) {
        float v = xr[i];
        s += v; s2 += v * v;
    }
    #pragma unroll
    for (int o = 16; o; o >>= 1) {
        s  += __shfl_xor_sync(0xFFFFFFFFu, s,  o);
        s2 += __shfl_xor_sync(0xFFFFFFFFu, s2, o);
    }
    int w = threadIdx.x >> 5, lane = threadIdx.x & 31;
    if (lane == 0) { sh[w] = s; sh[8 + w] = s2; }
    __syncthreads();
    if (threadIdx.x < 32) {
        s  = (threadIdx.x < 8) ? sh[threadIdx.x]     : 0.f;
        s2 = (threadIdx.x < 8) ? sh[8 + threadIdx.x] : 0.f;
        #pragma unroll
        for (int o = 4; o; o >>= 1) {
            s  += __shfl_xor_sync(0xFFFFFFFFu, s,  o);
            s2 += __shfl_xor_sync(0xFFFFFFFFu, s2, o);
        }
        if (threadIdx.x == 0) {
            float mu = s * (1.0f / HID);
            float var = s2 * (1.0f / HID) - mu * mu;
            sh[16] = mu;
            sh[17] = rsqrtf(var + 1e-5f);
        }
    }
    __syncthreads();
    float mu = sh[16], inv = sh[17];
    for (int i = threadIdx.x; i < HID; i += 256) {
        float v = (xr[i] - mu) * inv * gamma[i];
        if (SPLIT) {
            __nv_bfloat16 h = __float2bfloat16(v);
            oh[(long)row * HID + i] = h;
            ol[(long)row * HID + i] = __float2bfloat16(v - __bfloat162float(h));
        } else {
            outf[(long)row * HID + i] = v;
        }
    }
}

__global__ void __launch_bounds__(256) wsplit_kernel(const float* __restrict__ W,
                                                     __nv_bfloat16* __restrict__ Th,
                                                     __nv_bfloat16* __restrict__ Tl,
                                                     int K, int N) {
    __shared__ float t[32][33];
    int bx = blockIdx.x * 32, by = blockIdx.y * 32;
    int tx = threadIdx.x, ty = threadIdx.y;
    #pragma unroll
    for (int i = 0; i < 4; i++)
        t[ty + i * 8][tx] = W[(long)(by + ty + i * 8) * N + bx + tx];
    __syncthreads();
    #pragma unroll
    for (int i = 0; i < 4; i++) {
        float v = t[tx][ty + i * 8];
        __nv_bfloat16 h = __float2bfloat16(v);
        long o = (long)(bx + ty + i * 8) * K + by + tx;
        Th[o] = h;
        Tl[o] = __float2bfloat16(v - __bfloat162float(h));
    }
}

// ======================= mma.sync split-bf16 GEMM (R3-exact, 2-stage) =======================
#define STAGE_BYTES 32768
#define GSM_TOTAL   (2 * STAGE_BYTES)

__device__ __forceinline__ void load_half_tile(uint32_t sbase,
                                               const __nv_bfloat16* __restrict__ Ph,
                                               const __nv_bfloat16* __restrict__ Pl,
                                               int K, long k0, int tid) {
    #pragma unroll
    for (int i = 0; i < 4; i++) {
        int idx = tid + i * 256;
        int row = idx >> 3, c = idx & 7;
        const __nv_bfloat16* src = (c < 4 ? Ph : Pl) + (long)row * K + k0 + (c & 3) * 8;
        uint32_t dst = sbase + row * 128 + ((c ^ (row & 7)) << 4);
        cp16(dst, src);
    }
}

template <int MODE>
__global__ void __launch_bounds__(256) gemm_mma_kernel(
    const __nv_bfloat16* __restrict__ Ah, const __nv_bfloat16* __restrict__ Al,
    const __nv_bfloat16* __restrict__ Bh, const __nv_bfloat16* __restrict__ Bl,
    const float* __restrict__ bias, const float* res,
    float* Cf, __nv_bfloat16* __restrict__ Ch, __nv_bfloat16* __restrict__ Cl,
    int M, int N, int K)
{
    extern __shared__ char smem[];
    uint32_t sb = smem_u32(smem);
    int tid = threadIdx.x;
    int wid = tid >> 5, lane = tid & 31;
    int warp_m = wid >> 2, warp_n = wid & 3;
    int row0 = blockIdx.y * 128, col0 = blockIdx.x * 128;
    int m0 = warp_m * 64, n0 = warp_n * 32;

    const __nv_bfloat16* pAh = Ah + (long)row0 * K;
    const __nv_bfloat16* pAl = Al + (long)row0 * K;
    const __nv_bfloat16* pBh = Bh + (long)col0 * K;
    const __nv_bfloat16* pBl = Bl + (long)col0 * K;

    float acc[4][4][4];
    #pragma unroll
    for (int i = 0; i < 4; i++)
        #pragma unroll
        for (int j = 0; j < 4; j++)
            #pragma unroll
            for (int q = 0; q < 4; q++) acc[i][j][q] = 0.f;

    int grp = lane >> 3, lr = lane & 7;
    int rowA = m0 + (grp & 1) * 8 + lr;
    int ccA  = grp >> 1;
    int rowB = n0 + (grp >> 1) * 8 + lr;
    int ccB  = grp & 1;
    int xA = rowA & 7, xB = rowB & 7;

    int nc = K / 32;
    load_half_tile(sb,                 pAh, pAl, K, 0, tid);
    load_half_tile(sb + 16384,         pBh, pBl, K, 0, tid);
    cp_commit();
    load_half_tile(sb + STAGE_BYTES,         pAh, pAl, K, 32, tid);
    load_half_tile(sb + STAGE_BYTES + 16384, pBh, pBl, K, 32, tid);
    cp_commit();

    for (int c = 0; c < nc; c++) {
        cp_wait<1>();
        __syncthreads();
        uint32_t sA = sb + (c & 1) * STAGE_BYTES;
        uint32_t sB = sA + 16384;

        #pragma unroll
        for (int ks = 0; ks < 2; ks++) {
            uint32_t afh[4][4], afl[4][4], bfh[2][4], bfl[2][4];
            #pragma unroll
            for (int mt = 0; mt < 4; mt++) {
                uint32_t base = sA + (rowA + mt * 16) * 128;
                ldmx4(afh[mt], base + (((ks * 2 + ccA)     ^ xA) << 4));
                ldmx4(afl[mt], base + (((ks * 2 + ccA + 4) ^ xA) << 4));
            }
            #pragma unroll
            for (int np = 0; np < 2; np++) {
                uint32_t base = sB + (rowB + np * 16) * 128;
                ldmx4(bfh[np], base + (((ks * 2 + ccB)     ^ xB) << 4));
                ldmx4(bfl[np], base + (((ks * 2 + ccB + 4) ^ xB) << 4));
            }
            #pragma unroll
            for (int mt = 0; mt < 4; mt++)
                #pragma unroll
                for (int nt = 0; nt < 4; nt++) {
                    const uint32_t* bh = &bfh[nt >> 1][(nt & 1) * 2];
                    const uint32_t* bl = &bfl[nt >> 1][(nt & 1) * 2];
                    mma16816(acc[mt][nt], afh[mt], bh);
                    mma16816(acc[mt][nt], afh[mt], bl);
                    mma16816(acc[mt][nt], afl[mt], bh);
                }
        }
        __syncthreads();
        if (c + 2 < nc) {
            uint32_t st = sb + (c & 1) * STAGE_BYTES;
            long k0 = (long)(c + 2) * 32;
            load_half_tile(st,         pAh, pAl, K, k0, tid);
            load_half_tile(st + 16384, pBh, pBl, K, k0, tid);
        }
        cp_commit();
    }

    int r = lane >> 2, c2 = (lane & 3) * 2;
    #pragma unroll
    for (int mt = 0; mt < 4; mt++) {
        #pragma unroll
        for (int nt = 0; nt < 4; nt++) {
            long gr = row0 + m0 + mt * 16 + r;
            long gc = col0 + n0 + nt * 8 + c2;
            #pragma unroll
            for (int hrow = 0; hrow < 2; hrow++) {
                long grr = gr + hrow * 8;
                float v0 = acc[mt][nt][hrow * 2 + 0];
                float v1 = acc[mt][nt][hrow * 2 + 1];
                if (MODE == 0) {
                    *(float2*)(Cf + grr * N + gc) = make_float2(v0, v1);
                } else if (MODE == 1) {
                    float2 b = *(const float2*)(bias + gc);
                    float2 rr = *(const float2*)(res + grr * N + gc);
                    *(float2*)(Cf + grr * N + gc) = make_float2(v0 + b.x + rr.x, v1 + b.y + rr.y);
                } else {
                    float g0 = gelu_tanh(v0), g1 = gelu_tanh(v1);
                    __nv_bfloat16 h0 = __float2bfloat16(g0);
                    __nv_bfloat16 h1 = __float2bfloat16(g1);
                    __nv_bfloat162 hp; hp.x = h0; hp.y = h1;
                    __nv_bfloat162 lp;
                    lp.x = __float2bfloat16(g0 - __bfloat162float(h0));
                    lp.y = __float2bfloat16(g1 - __bfloat162float(h1));
                    *(__nv_bfloat162*)(Ch + grr * N + gc) = hp;
                    *(__nv_bfloat162*)(Cl + grr * N + gc) = lp;
                }
            }
        }
    }
}

// ======================= tensor-core flash attention (split-bf16) =======================
// Grid: (SEQ/128, NHEAD), 256 threads = 8 warps; warp owns 16 rows x all 128 keys.
// Q,K,V fp32 in global -> split bf16 hi/lo in smem. 3-term mma for S=Q@K^T and O=P@V.
// SMEM (bytes): QH 0, QL 16384, KH 32768, KL 49152, VH 65536, VL 81920,
//               KF 98304 (fp32, 272B rows), VF 133120.  Total 167936.
#define ASM_QH 0
#define ASM_QL 16384
#define ASM_KH 32768
#define ASM_KL 49152
#define ASM_VH 65536
#define ASM_VL 81920
#define ASM_KF 98304
#define ASM_VF 133120
#define ASM_TOTAL 167936

// convert fp32 staging tile (128 rows x 64 f32, 272B row stride) -> swizzled bf16 hi/lo tiles
__device__ __forceinline__ void cvt_tile(uint32_t fbase, uint32_t hbase, uint32_t lbase,
                                         int tid, float scale) {
    int row = tid >> 1, half = tid & 1;
    uint32_t fr = fbase + row * 272;
    uint32_t hr = hbase + row * 128;
    uint32_t lr_ = lbase + row * 128;
    #pragma unroll
    for (int j = 0; j < 4; j++) {
        float4 f0, f1;
        asm volatile("ld.shared.v4.f32 {%0,%1,%2,%3}, [%4];"
                     : "=f"(f0.x), "=f"(f0.y), "=f"(f0.z), "=f"(f0.w)
                     : "r"(fr + (half * 8 + j * 2) * 16));
        asm volatile("ld.shared.v4.f32 {%0,%1,%2,%3}, [%4];"
                     : "=f"(f1.x), "=f"(f1.y), "=f"(f1.z), "=f"(f1.w)
                     : "r"(fr + (half * 8 + j * 2 + 1) * 16));
        float v[8] = {f0.x * scale, f0.y * scale, f0.z * scale, f0.w * scale,
                      f1.x * scale, f1.y * scale, f1.z * scale, f1.w * scale};
        uint32_t hi[4], lo[4];
        #pragma unroll
        for (int q = 0; q < 4; q++) {
            float a = v[q * 2], b = v[q * 2 + 1];
            float ha = __bfloat162float(__float2bfloat16(a));
            float hb = __bfloat162float(__float2bfloat16(b));
            hi[q] = packbf2(ha, hb);
            lo[q] = packbf2(a - ha, b - hb);
        }
        int c = half * 4 + j;
        uint32_t sw = (uint32_t)((c ^ (row & 7)) << 4);
        asm volatile("st.shared.v4.b32 [%0], {%1,%2,%3,%4};"
                     :: "r"(hr + sw), "r"(hi[0]), "r"(hi[1]), "r"(hi[2]), "r"(hi[3]));
        asm volatile("st.shared.v4.b32 [%0], {%1,%2,%3,%4};"
                     :: "r"(lr_ + sw), "r"(lo[0]), "r"(lo[1]), "r"(lo[2]), "r"(lo[3]));
    }
}

__device__ __forceinline__ void stage_cp(uint32_t fbase, const float* __restrict__ src,
                                         int keyrow0, int h, int tid) {
    #pragma unroll
    for (int i = 0; i < 8; i++) {
        int idx = tid + i * 256;
        int r = idx >> 4, c = idx & 15;
        cp16(fbase + r * 272 + c * 16, src + (long)(keyrow0 + r) * HID + h * HDIM + c * 4);
    }
}

__global__ void __launch_bounds__(256) attn_mma_kernel(
    const float* __restrict__ Q, const float* __restrict__ K,
    const float* __restrict__ V,
    __nv_bfloat16* __restrict__ Oh, __nv_bfloat16* __restrict__ Ol)
{
    extern __shared__ char smem[];
    uint32_t sb = smem_u32(smem);
    int tid = threadIdx.x;
    int w = tid >> 5, lane = tid & 31;
    int qb = blockIdx.x, h = blockIdx.y;

    int grp = lane >> 3, lr = lane & 7;
    // Q frag geometry (A operand): rows m, chunk base grp>>1
    int rowQ = w * 16 + (grp & 1) * 8 + lr;
    int ccQ  = grp >> 1;
    int xQ = rowQ & 7;
    // K frag geometry (B operand): rows n (keys)
    int rowK_off = (grp >> 1) * 8 + lr;
    int ccK  = grp & 1;
    // V frag geometry (trans B): rows k (keys), chunk = d-group
    int rowV_off = (grp & 1) * 8 + lr;
    int ccV_off  = grp >> 1;

    // ---- prologue: load Q (scaled 1/8), split into QH/QL ----
    {
        int row = tid >> 1, half = tid & 1;
        const float* src = Q + (long)(qb * 128 + row) * HID + h * HDIM + half * 32;
        uint32_t hr = sb + ASM_QH + row * 128;
        uint32_t lr2 = sb + ASM_QL + row * 128;
        #pragma unroll
        for (int j = 0; j < 4; j++) {
            float4 f0 = *(const float4*)(src + j * 8);
            float4 f1 = *(const float4*)(src + j * 8 + 4);
            float v[8] = {f0.x, f0.y, f0.z, f0.w, f1.x, f1.y, f1.z, f1.w};
            uint32_t hi[4], lo[4];
            #pragma unroll
            for (int q = 0; q < 4; q++) {
                float a = v[q * 2] * 0.125f, b = v[q * 2 + 1] * 0.125f;
                float ha = __bfloat162float(__float2bfloat16(a));
                float hb = __bfloat162float(__float2bfloat16(b));
                hi[q] = packbf2(ha, hb);
                lo[q] = packbf2(a - ha, b - hb);
            }
            int c = half * 4 + j;
            uint32_t sw = (uint32_t)((c ^ (row & 7)) << 4);
            asm volatile("st.shared.v4.b32 [%0], {%1,%2,%3,%4};"
                         :: "r"(hr + sw), "r"(hi[0]), "r"(hi[1]), "r"(hi[2]), "r"(hi[3]));
            asm volatile("st.shared.v4.b32 [%0], {%1,%2,%3,%4};"
                         :: "r"(lr2 + sw), "r"(lo[0]), "r"(lo[1]), "r"(lo[2]), "r"(lo[3]));
        }
    }
    // stage K/V fp32 for kt=0
    stage_cp(sb + ASM_KF, K, 0, h, tid);
    stage_cp(sb + ASM_VF, V, 0, h, tid);
    cp_commit();
    __syncthreads();

    // cache Q fragments
    uint32_t qfh[4][4], qfl[4][4];
    #pragma unroll
    for (int ks = 0; ks < 4; ks++) {
        uint32_t base = sb + rowQ * 128;
        ldmx4(qfh[ks], base + ASM_QH + (((ks * 2 + ccQ) ^ xQ) << 4));
        ldmx4(qfl[ks], base + ASM_QL + (((ks * 2 + ccQ) ^ xQ) << 4));
    }

    float oacc[8][4];
    #pragma unroll
    for (int i = 0; i < 8; i++)
        #pragma unroll
        for (int q = 0; q < 4; q++) oacc[i][q] = 0.f;
    float m0 = -1e30f, m1 = -1e30f, l0 = 0.f, l1 = 0.f;

    int qg0 = qb * 128 + w * 16 + (lane >> 2);
    int qg1 = qg0 + 8;

    for (int kt = 0; kt <= qb; kt++) {
        cp_wait<0>();
        __syncthreads();
        // convert staged fp32 -> bf16 tiles
        cvt_tile(sb + ASM_KF, sb + ASM_KH, sb + ASM_KL, tid, 1.0f);
        cvt_tile(sb + ASM_VF, sb + ASM_VH, sb + ASM_VL, tid, 1.0f);
        __syncthreads();
        // prefetch next tile into staging (now free)
        if (kt < qb) {
            stage_cp(sb + ASM_KF, K, (kt + 1) * 128, h, tid);
            stage_cp(sb + ASM_VF, V, (kt + 1) * 128, h, tid);
        }
        cp_commit();

        // ---- S = Qs @ K^T ----
        float sacc[16][4];
        #pragma unroll
        for (int i = 0; i < 16; i++)
            #pragma unroll
            for (int q = 0; q < 4; q++) sacc[i][q] = 0.f;

        #pragma unroll
        for (int ks = 0; ks < 4; ks++) {
            #pragma unroll
            for (int nb = 0; nb < 8; nb++) {
                int rowK = nb * 16 + rowK_off;
                uint32_t base = sb + rowK * 128;
                uint32_t off = (uint32_t)(((ks * 2 + ccK) ^ (rowK & 7)) << 4);
                uint32_t bkh[4], bkl[4];
                ldmx4(bkh, base + ASM_KH + off);
                ldmx4(bkl, base + ASM_KL + off);
                #pragma unroll
                for (int sub = 0; sub < 2; sub++) {
                    float* d = sacc[nb * 2 + sub];
                    mma16816(d, qfh[ks], &bkh[sub * 2]);
                    mma16816(d, qfh[ks], &bkl[sub * 2]);
                    mma16816(d, qfl[ks], &bkh[sub * 2]);
                }
            }
        }

        // ---- causal mask on diagonal tile ----
        if (kt == qb) {
            #pragma unroll
            for (int nt = 0; nt < 16; nt++) {
                int kg = kt * 128 + nt * 8 + 2 * (lane & 3);
                #pragma unroll
                for (int e = 0; e < 2; e++) {
                    if (kg + e > qg0) sacc[nt][e]     = -1e30f;
                    if (kg + e > qg1) sacc[nt][2 + e] = -1e30f;
                }
            }
        }

        // ---- online softmax ----
        float rm0 = -1e30f, rm1 = -1e30f;
        #pragma unroll
        for (int nt = 0; nt < 16; nt++) {
            rm0 = fmaxf(rm0, fmaxf(sacc[nt][0], sacc[nt][1]));
            rm1 = fmaxf(rm1, fmaxf(sacc[nt][2], sacc[nt][3]));
        }
        rm0 = fmaxf(rm0, __shfl_xor_sync(0xFFFFFFFFu, rm0, 1));
        rm0 = fmaxf(rm0, __shfl_xor_sync(0xFFFFFFFFu, rm0, 2));
        rm1 = fmaxf(rm1, __shfl_xor_sync(0xFFFFFFFFu, rm1, 1));
        rm1 = fmaxf(rm1, __shfl_xor_sync(0xFFFFFFFFu, rm1, 2));
        float mn0 = fmaxf(m0, rm0), mn1 = fmaxf(m1, rm1);
        float al0 = __expf(m0 - mn0), al1 = __expf(m1 - mn1);
        m0 = mn0; m1 = mn1;

        float rs0 = 0.f, rs1 = 0.f;
        #pragma unroll
        for (int nt = 0; nt < 16; nt++) {
            sacc[nt][0] = __expf(sacc[nt][0] - mn0);
            sacc[nt][1] = __expf(sacc[nt][1] - mn0);
            sacc[nt][2] = __expf(sacc[nt][2] - mn1);
            sacc[nt][3] = __expf(sacc[nt][3] - mn1);
            rs0 += sacc[nt][0] + sacc[nt][1];
            rs1 += sacc[nt][2] + sacc[nt][3];
        }
        rs0 += __shfl_xor_sync(0xFFFFFFFFu, rs0, 1);
        rs0 += __shfl_xor_sync(0xFFFFFFFFu, rs0, 2);
        rs1 += __shfl_xor_sync(0xFFFFFFFFu, rs1, 1);
        rs1 += __shfl_xor_sync(0xFFFFFFFFu, rs1, 2);
        l0 = l0 * al0 + rs0;
        l1 = l1 * al1 + rs1;

        #pragma unroll
        for (int i = 0; i < 8; i++) {
            oacc[i][0] *= al0; oacc[i][1] *= al0;
            oacc[i][2] *= al1; oacc[i][3] *= al1;
        }

        // ---- O += P @ V ----
        #pragma unroll
        for (int ks2 = 0; ks2 < 8; ks2++) {
            // P fragments (hi/lo) from sacc
            uint32_t ah[4], al[4];
            {
                float p00 = sacc[2 * ks2][0],     p01 = sacc[2 * ks2][1];
                float p10 = sacc[2 * ks2][2],     p11 = sacc[2 * ks2][3];
                float p20 = sacc[2 * ks2 + 1][0], p21 = sacc[2 * ks2 + 1][1];
                float p30 = sacc[2 * ks2 + 1][2], p31 = sacc[2 * ks2 + 1][3];
                float h00 = __bfloat162float(__float2bfloat16(p00));
                float h01 = __bfloat162float(__float2bfloat16(p01));
                float h10 = __bfloat162float(__float2bfloat16(p10));
                float h11 = __bfloat162float(__float2bfloat16(p11));
                float h20 = __bfloat162float(__float2bfloat16(p20));
                float h21 = __bfloat162float(__float2bfloat16(p21));
                float h30 = __bfloat162float(__float2bfloat16(p30));
                float h31 = __bfloat162float(__float2bfloat16(p31));
                ah[0] = packbf2(h00, h01); ah[1] = packbf2(h10, h11);
                ah[2] = packbf2(h20, h21); ah[3] = packbf2(h30, h31);
                al[0] = packbf2(p00 - h00, p01 - h01);
                al[1] = packbf2(p10 - h10, p11 - h11);
                al[2] = packbf2(p20 - h20, p21 - h21);
                al[3] = packbf2(p30 - h30, p31 - h31);
            }
            #pragma unroll
            for (int db = 0; db < 4; db++) {
                int rowV = ks2 * 16 + rowV_off;
                int cc = db * 2 + ccV_off;
                uint32_t base = sb + rowV * 128;
                uint32_t off = (uint32_t)((cc ^ (rowV & 7)) << 4);
                uint32_t bvh[4], bvl[4];
                ldmx4t(bvh, base + ASM_VH + off);
                ldmx4t(bvl, base + ASM_VL + off);
                #pragma unroll
                for (int sub = 0; sub < 2; sub++) {
                    float* d = oacc[db * 2 + sub];
                    mma16816(d, ah, &bvh[sub * 2]);
                    mma16816(d, al, &bvh[sub * 2]);
                    mma16816(d, ah, &bvl[sub * 2]);
                }
            }
        }
    }

    // ---- epilogue ----
    float i0 = 1.0f / l0, i1 = 1.0f / l1;
    long gr0 = qb * 128 + w * 16 + (lane >> 2);
    long gc0 = h * HDIM + 2 * (lane & 3);
    #pragma unroll
    for (int nto = 0; nto < 8; nto++) {
        long gc = gc0 + nto * 8;
        float v0 = oacc[nto][0] * i0, v1 = oacc[nto][1] * i0;
        float v2 = oacc[nto][2] * i1, v3 = oacc[nto][3] * i1;
        float h0 = __bfloat162float(__float2bfloat16(v0));
        float h1 = __bfloat162float(__float2bfloat16(v1));
        float h2 = __bfloat162float(__float2bfloat16(v2));
        float h3 = __bfloat162float(__float2bfloat16(v3));
        *(uint32_t*)(Oh + gr0 * HID + gc)       = packbf2(h0, h1);
        *(uint32_t*)(Oh + (gr0 + 8) * HID + gc) = packbf2(h2, h3);
        *(uint32_t*)(Ol + gr0 * HID + gc)       = packbf2(v0 - h0, v1 - h1);
        *(uint32_t*)(Ol + (gr0 + 8) * HID + gc) = packbf2(v2 - h2, v3 - h3);
    }
}

// ======================= orchestration =======================
extern "C" void kernel_launch(void* const* d_in, const int* in_sizes, int n_in,
                              void* d_out, int out_size) {
    const float* emb = (const float*)d_in[0];
    const float* Wq = (const float*)d_in[2];
    const float* Wk = (const float*)d_in[3];
    const float* Wv = (const float*)d_in[4];
    const float* Wo = (const float*)d_in[5];
    const float* bo = (const float*)d_in[6];
    const float* W1 = (const float*)d_in[7];
    const float* W2 = (const float*)d_in[8];
    const float* b2 = (const float*)d_in[9];
    const float* g1 = (const float*)d_in[10];
    const float* g2 = (const float*)d_in[11];
    const float* gf = (const float*)d_in[12];
    float* out = (float*)d_out;

    float *px, *pq, *pk, *pv;
    __nv_bfloat16 *phh, *phl, *pch, *pcl, *pmh, *pml;
    __nv_bfloat16 *wqh, *wql, *wkh, *wkl, *wvh, *wvl, *woh, *wol, *w1h, *w1l, *w2h, *w2l;
    cudaGetSymbolAddress((void**)&px,  g_x);
    cudaGetSymbolAddress((void**)&pq,  g_q);
    cudaGetSymbolAddress((void**)&pk,  g_k);
    cudaGetSymbolAddress((void**)&pv,  g_v);
    cudaGetSymbolAddress((void**)&phh, g_hh);
    cudaGetSymbolAddress((void**)&phl, g_hl);
    cudaGetSymbolAddress((void**)&pch, g_ctxh);
    cudaGetSymbolAddress((void**)&pcl, g_ctxl);
    cudaGetSymbolAddress((void**)&pmh, g_midh);
    cudaGetSymbolAddress((void**)&pml, g_midl);
    cudaGetSymbolAddress((void**)&wqh, g_wqt_h); cudaGetSymbolAddress((void**)&wql, g_wqt_l);
    cudaGetSymbolAddress((void**)&wkh, g_wkt_h); cudaGetSymbolAddress((void**)&wkl, g_wkt_l);
    cudaGetSymbolAddress((void**)&wvh, g_wvt_h); cudaGetSymbolAddress((void**)&wvl, g_wvt_l);
    cudaGetSymbolAddress((void**)&woh, g_wot_h); cudaGetSymbolAddress((void**)&wol, g_wot_l);
    cudaGetSymbolAddress((void**)&w1h, g_w1t_h); cudaGetSymbolAddress((void**)&w1l, g_w1t_l);
    cudaGetSymbolAddress((void**)&w2h, g_w2t_h); cudaGetSymbolAddress((void**)&w2l, g_w2t_l);

    cudaFuncSetAttribute(gemm_mma_kernel<0>, cudaFuncAttributeMaxDynamicSharedMemorySize, GSM_TOTAL);
    cudaFuncSetAttribute(gemm_mma_kernel<1>, cudaFuncAttributeMaxDynamicSharedMemorySize, GSM_TOTAL);
    cudaFuncSetAttribute(gemm_mma_kernel<2>, cudaFuncAttributeMaxDynamicSharedMemorySize, GSM_TOTAL);
    cudaFuncSetAttribute(attn_mma_kernel, cudaFuncAttributeMaxDynamicSharedMemorySize, ASM_TOTAL);

    {
        int n4 = SEQ * HID / 4;
        copy_kernel<<<(n4 + 255) / 256, 256>>>((const float4*)emb, (float4*)px, n4);
    }

    {
        dim3 b(32, 8);
        dim3 gHH(HID / 32, HID / 32);
        dim3 gW1(ISZ / 32, HID / 32);
        dim3 gW2(HID / 32, ISZ / 32);
        for (int l = 0; l < NLAYER; l++) {
            long oHH = (long)l * HID * HID, oHI = (long)l * HID * ISZ;
            wsplit_kernel<<<gHH, b>>>(Wq + oHH, wqh + oHH, wql + oHH, HID, HID);
            wsplit_kernel<<<gHH, b>>>(Wk + oHH, wkh + oHH, wkl + oHH, HID, HID);
            wsplit_kernel<<<gHH, b>>>(Wv + oHH, wvh + oHH, wvl + oHH, HID, HID);
            wsplit_kernel<<<gHH, b>>>(Wo + oHH, woh + oHH, wol + oHH, HID, HID);
            wsplit_kernel<<<gW1, b>>>(W1 + oHI, w1h + oHI, w1l + oHI, HID, ISZ);
            wsplit_kernel<<<gW2, b>>>(W2 + oHI, w2h + oHI, w2l + oHI, ISZ, HID);
        }
    }

    dim3 gHH(HID / 128, SEQ / 128);
    dim3 gHI(ISZ / 128, SEQ / 128);
    dim3 gAttn(SEQ / 128, NHEAD);

    for (int l = 0; l < NLAYER; l++) {
        long oHH = (long)l * HID * HID, oHI = (long)l * HID * ISZ;

        ln_kernel<1><<<SEQ, 256>>>(px, g1 + l * HID, nullptr, phh, phl);
        gemm_mma_kernel<0><<<gHH, 256, GSM_TOTAL>>>(phh, phl, wqh + oHH, wql + oHH,
            nullptr, nullptr, pq, nullptr, nullptr, SEQ, HID, HID);
        gemm_mma_kernel<0><<<gHH, 256, GSM_TOTAL>>>(phh, phl, wkh + oHH, wkl + oHH,
            nullptr, nullptr, pk, nullptr, nullptr, SEQ, HID, HID);
        gemm_mma_kernel<0><<<gHH, 256, GSM_TOTAL>>>(phh, phl, wvh + oHH, wvl + oHH,
            nullptr, nullptr, pv, nullptr, nullptr, SEQ, HID, HID);
        attn_mma_kernel<<<gAttn, 256, ASM_TOTAL>>>(pq, pk, pv, pch, pcl);
        gemm_mma_kernel<1><<<gHH, 256, GSM_TOTAL>>>(pch, pcl, woh + oHH, wol + oHH,
            bo + l * HID, px, px, nullptr, nullptr, SEQ, HID, HID);

        ln_kernel<1><<<SEQ, 256>>>(px, g2 + l * HID, nullptr, phh, phl);
        gemm_mma_kernel<2><<<gHI, 256, GSM_TOTAL>>>(phh, phl, w1h + oHI, w1l + oHI,
            nullptr, nullptr, nullptr, pmh, pml, SEQ, ISZ, HID);
        gemm_mma_kernel<1><<<gHH, 256, GSM_TOTAL>>>(pmh, pml, w2h + oHI, w2l + oHI,
            b2 + l * HID, px, px, nullptr, nullptr, SEQ, HID, ISZ);
    }

    ln_kernel<0><<<SEQ, 256>>>(px, gf, out, nullptr, nullptr);
}

// round 6
// speedup vs baseline: 3.6348x; 1.1302x over previous
#include <cuda_runtime.h>
#include <cuda_fp16.h>
#include <cuda_bf16.h>
#include <math.h>
#include <stdint.h>

#define SEQ 2048
#define HID 2048
#define NHEAD 32
#define HDIM 64
#define ISZ 8192
#define NLAYER 2

// ======================= scratch (static device arrays) =======================
__device__ float g_x  [SEQ * HID];
__device__ float g_q  [SEQ * HID];
__device__ float g_k  [SEQ * HID];
__device__ float g_v  [SEQ * HID];
__device__ __half g_h  [SEQ * HID];     // LN out (fp16, single)
__device__ __half g_ctx[SEQ * HID];     // attn out (fp16, single)
__device__ __half g_mid[SEQ * ISZ];     // MLP mid (fp16, single)
// transposed + split weights: Wt[N][K], fp16 hi/lo
__device__ __half g_wqt_h[NLAYER * HID * HID], g_wqt_l[NLAYER * HID * HID];
__device__ __half g_wkt_h[NLAYER * HID * HID], g_wkt_l[NLAYER * HID * HID];
__device__ __half g_wvt_h[NLAYER * HID * HID], g_wvt_l[NLAYER * HID * HID];
__device__ __half g_wot_h[NLAYER * HID * HID], g_wot_l[NLAYER * HID * HID];
__device__ __half g_w1t_h[NLAYER * HID * ISZ], g_w1t_l[NLAYER * HID * ISZ];
__device__ __half g_w2t_h[NLAYER * ISZ * HID], g_w2t_l[NLAYER * ISZ * HID];

// ======================= PTX helpers =======================
__device__ __forceinline__ uint32_t smem_u32(const void* p) {
    uint32_t a;
    asm("{ .reg .u64 t; cvta.to.shared.u64 t, %1; cvt.u32.u64 %0, t; }" : "=r"(a) : "l"(p));
    return a;
}
__device__ __forceinline__ void cp16(uint32_t dst, const void* src) {
    asm volatile("cp.async.cg.shared.global [%0], [%1], 16;" :: "r"(dst), "l"(src));
}
__device__ __forceinline__ void cp_commit() {
    asm volatile("cp.async.commit_group;" ::: "memory");
}
template <int N>
__device__ __forceinline__ void cp_wait() {
    asm volatile("cp.async.wait_group %0;" :: "n"(N) : "memory");
}
__device__ __forceinline__ void ldmx4(uint32_t* r, uint32_t addr) {
    asm volatile("ldmatrix.sync.aligned.m8n8.x4.shared.b16 {%0,%1,%2,%3}, [%4];"
                 : "=r"(r[0]), "=r"(r[1]), "=r"(r[2]), "=r"(r[3]) : "r"(addr));
}
__device__ __forceinline__ void ldmx4t(uint32_t* r, uint32_t addr) {
    asm volatile("ldmatrix.sync.aligned.m8n8.x4.trans.shared.b16 {%0,%1,%2,%3}, [%4];"
                 : "=r"(r[0]), "=r"(r[1]), "=r"(r[2]), "=r"(r[3]) : "r"(addr));
}
// bf16 mma (attention)
__device__ __forceinline__ void mma16816(float* d, const uint32_t* a, const uint32_t* b) {
    asm volatile("mma.sync.aligned.m16n8k16.row.col.f32.bf16.bf16.f32 "
                 "{%0,%1,%2,%3}, {%4,%5,%6,%7}, {%8,%9}, {%0,%1,%2,%3};"
                 : "+f"(d[0]), "+f"(d[1]), "+f"(d[2]), "+f"(d[3])
                 : "r"(a[0]), "r"(a[1]), "r"(a[2]), "r"(a[3]), "r"(b[0]), "r"(b[1]));
}
// fp16 mma (GEMM)
__device__ __forceinline__ void mma16816h(float* d, const uint32_t* a, const uint32_t* b) {
    asm volatile("mma.sync.aligned.m16n8k16.row.col.f32.f16.f16.f32 "
                 "{%0,%1,%2,%3}, {%4,%5,%6,%7}, {%8,%9}, {%0,%1,%2,%3};"
                 : "+f"(d[0]), "+f"(d[1]), "+f"(d[2]), "+f"(d[3])
                 : "r"(a[0]), "r"(a[1]), "r"(a[2]), "r"(a[3]), "r"(b[0]), "r"(b[1]));
}
__device__ __forceinline__ uint32_t packbf2(float lo, float hi) {
    __nv_bfloat162 t = __floats2bfloat162_rn(lo, hi);
    return *(uint32_t*)&t;
}
__device__ __forceinline__ uint32_t packh2(float lo, float hi) {
    __half2 t = __floats2half2_rn(lo, hi);
    return *(uint32_t*)&t;
}

// ======================= small kernels =======================
__global__ void copy_kernel(const float4* __restrict__ in, float4* __restrict__ out, int n4) {
    int i = blockIdx.x * 256 + threadIdx.x;
    if (i < n4) out[i] = in[i];
}

__device__ __forceinline__ float gelu_tanh(float v) {
    float t = 0.7978845608028654f * v * (1.0f + 0.044715f * v * v);
    return 0.5f * v * (1.0f + tanhf(t));
}

// layernorm; HALF=1 -> fp16 out, else fp32 out
template <int HALF>
__global__ void __launch_bounds__(256) ln_kernel(const float* __restrict__ x,
                                                 const float* __restrict__ gamma,
                                                 float* __restrict__ outf,
                                                 __half* __restrict__ oh) {
    __shared__ float sh[18];
    int row = blockIdx.x;
    const float* xr = x + (long)row * HID;
    float s = 0.f, s2 = 0.f;
    for (int i = threadIdx.x; i < HID; i += 256) {
        float v = xr[i];
        s += v; s2 += v * v;
    }
    #pragma unroll
    for (int o = 16; o; o >>= 1) {
        s  += __shfl_xor_sync(0xFFFFFFFFu, s,  o);
        s2 += __shfl_xor_sync(0xFFFFFFFFu, s2, o);
    }
    int w = threadIdx.x >> 5, lane = threadIdx.x & 31;
    if (lane == 0) { sh[w] = s; sh[8 + w] = s2; }
    __syncthreads();
    if (threadIdx.x < 32) {
        s  = (threadIdx.x < 8) ? sh[threadIdx.x]     : 0.f;
        s2 = (threadIdx.x < 8) ? sh[8 + threadIdx.x] : 0.f;
        #pragma unroll
        for (int o = 4; o; o >>= 1) {
            s  += __shfl_xor_sync(0xFFFFFFFFu, s,  o);
            s2 += __shfl_xor_sync(0xFFFFFFFFu, s2, o);
        }
        if (threadIdx.x == 0) {
            float mu = s * (1.0f / HID);
            float var = s2 * (1.0f / HID) - mu * mu;
            sh[16] = mu;
            sh[17] = rsqrtf(var + 1e-5f);
        }
    }
    __syncthreads();
    float mu = sh[16], inv = sh[17];
    for (int i = threadIdx.x; i < HID; i += 256) {
        float v = (xr[i] - mu) * inv * gamma[i];
        if (HALF) oh[(long)row * HID + i] = __float2half(v);
        else      outf[(long)row * HID + i] = v;
    }
}

// weight transpose + split: W[K,N] fp32 -> Th/Tl[N,K] fp16
__global__ void __launch_bounds__(256) wsplit_kernel(const float* __restrict__ W,
                                                     __half* __restrict__ Th,
                                                     __half* __restrict__ Tl,
                                                     int K, int N) {
    __shared__ float t[32][33];
    int bx = blockIdx.x * 32, by = blockIdx.y * 32;
    int tx = threadIdx.x, ty = threadIdx.y;
    #pragma unroll
    for (int i = 0; i < 4; i++)
        t[ty + i * 8][tx] = W[(long)(by + ty + i * 8) * N + bx + tx];
    __syncthreads();
    #pragma unroll
    for (int i = 0; i < 4; i++) {
        float v = t[tx][ty + i * 8];
        __half h = __float2half(v);
        long o = (long)(bx + ty + i * 8) * K + by + tx;
        Th[o] = h;
        Tl[o] = __float2half(v - __half2float(h));
    }
}

// ======================= mma.sync fp16 GEMM (A plain, B hi/lo; 2 mma/tile) =======================
// C[M,N] = A[M,K] @ (Bh+Bl)^T, B stored [N,K] row-major fp16 hi/lo.
// BM=128, BN=128, BK=32; 8 warps, warp tile 64x32; 2-stage cp.async.
// A smem: 128 rows x 64B (4 chunks of 16B), phys_chunk = c ^ ((row>>1)&3).
// B smem: 128 rows x 128B (chunks 0-3 hi, 4-7 lo), phys_chunk = c ^ (row&7).
// blockIdx.z selects among up to 3 (B, C) pairs (fused QKV).
// MODE 0: Cf = AB ; MODE 1: Cf = AB + bias + res ; MODE 2: Ch = fp16(gelu(AB))
#define A_TILE 8192
#define B_TILE 16384
#define STAGE_BYTES (A_TILE + B_TILE)
#define GSM_TOTAL (2 * STAGE_BYTES)

__device__ __forceinline__ void load_A_tile(uint32_t sbase, const __half* __restrict__ A,
                                            int K, long k0, int tid) {
    #pragma unroll
    for (int i = 0; i < 2; i++) {
        int idx = tid + i * 256;
        int row = idx >> 2, c = idx & 3;
        const __half* src = A + (long)row * K + k0 + c * 8;
        uint32_t dst = sbase + row * 64 + ((c ^ ((row >> 1) & 3)) << 4);
        cp16(dst, src);
    }
}
__device__ __forceinline__ void load_B_tile(uint32_t sbase,
                                            const __half* __restrict__ Ph,
                                            const __half* __restrict__ Pl,
                                            int K, long k0, int tid) {
    #pragma unroll
    for (int i = 0; i < 4; i++) {
        int idx = tid + i * 256;
        int row = idx >> 3, c = idx & 7;
        const __half* src = (c < 4 ? Ph : Pl) + (long)row * K + k0 + (c & 3) * 8;
        uint32_t dst = sbase + row * 128 + ((c ^ (row & 7)) << 4);
        cp16(dst, src);
    }
}

template <int MODE>
__global__ void __launch_bounds__(256) gemm_mma_kernel(
    const __half* __restrict__ A,
    const __half* __restrict__ Bh0, const __half* __restrict__ Bl0,
    const __half* __restrict__ Bh1, const __half* __restrict__ Bl1,
    const __half* __restrict__ Bh2, const __half* __restrict__ Bl2,
    const float* __restrict__ bias, const float* res,
    float* Cf0, float* Cf1, float* Cf2,
    __half* __restrict__ Ch,
    int M, int N, int K)
{
    extern __shared__ char smem[];
    uint32_t sb = smem_u32(smem);
    int tid = threadIdx.x;
    int wid = tid >> 5, lane = tid & 31;
    int warp_m = wid >> 2, warp_n = wid & 3;
    int row0 = blockIdx.y * 128, col0 = blockIdx.x * 128;
    int m0 = warp_m * 64, n0 = warp_n * 32;
    int z = blockIdx.z;

    const __half* Bh = (z == 0) ? Bh0 : (z == 1) ? Bh1 : Bh2;
    const __half* Bl = (z == 0) ? Bl0 : (z == 1) ? Bl1 : Bl2;
    float* Cf = (z == 0) ? Cf0 : (z == 1) ? Cf1 : Cf2;

    const __half* pA  = A  + (long)row0 * K;
    const __half* pBh = Bh + (long)col0 * K;
    const __half* pBl = Bl + (long)col0 * K;

    float acc[4][4][4];
    #pragma unroll
    for (int i = 0; i < 4; i++)
        #pragma unroll
        for (int j = 0; j < 4; j++)
            #pragma unroll
            for (int q = 0; q < 4; q++) acc[i][j][q] = 0.f;

    int grp = lane >> 3, lr = lane & 7;
    int rowA = m0 + (grp & 1) * 8 + lr;
    int ccA  = grp >> 1;
    int rowB = n0 + (grp >> 1) * 8 + lr;
    int ccB  = grp & 1;
    int xB = rowB & 7;

    int nc = K / 32;
    load_A_tile(sb,          pA,       K, 0, tid);
    load_B_tile(sb + A_TILE, pBh, pBl, K, 0, tid);
    cp_commit();
    load_A_tile(sb + STAGE_BYTES,          pA,       K, 32, tid);
    load_B_tile(sb + STAGE_BYTES + A_TILE, pBh, pBl, K, 32, tid);
    cp_commit();

    for (int c = 0; c < nc; c++) {
        cp_wait<1>();
        __syncthreads();
        uint32_t sA = sb + (c & 1) * STAGE_BYTES;
        uint32_t sB = sA + A_TILE;

        #pragma unroll
        for (int ks = 0; ks < 2; ks++) {
            uint32_t af[4][4], bfh[2][4], bfl[2][4];
            #pragma unroll
            for (int mt = 0; mt < 4; mt++) {
                int ra = rowA + mt * 16;
                uint32_t base = sA + ra * 64;
                ldmx4(af[mt], base + (((ks * 2 + ccA) ^ ((ra >> 1) & 3)) << 4));
            }
            #pragma unroll
            for (int np = 0; np < 2; np++) {
                uint32_t base = sB + (rowB + np * 16) * 128;
                ldmx4(bfh[np], base + (((ks * 2 + ccB)     ^ xB) << 4));
                ldmx4(bfl[np], base + (((ks * 2 + ccB + 4) ^ xB) << 4));
            }
            #pragma unroll
            for (int mt = 0; mt < 4; mt++)
                #pragma unroll
                for (int nt = 0; nt < 4; nt++) {
                    const uint32_t* bh = &bfh[nt >> 1][(nt & 1) * 2];
                    const uint32_t* bl = &bfl[nt >> 1][(nt & 1) * 2];
                    mma16816h(acc[mt][nt], af[mt], bh);
                    mma16816h(acc[mt][nt], af[mt], bl);
                }
        }
        __syncthreads();
        if (c + 2 < nc) {
            uint32_t st = sb + (c & 1) * STAGE_BYTES;
            long k0 = (long)(c + 2) * 32;
            load_A_tile(st,          pA,       K, k0, tid);
            load_B_tile(st + A_TILE, pBh, pBl, K, k0, tid);
        }
        cp_commit();
    }

    int r = lane >> 2, c2 = (lane & 3) * 2;
    #pragma unroll
    for (int mt = 0; mt < 4; mt++) {
        #pragma unroll
        for (int nt = 0; nt < 4; nt++) {
            long gr = row0 + m0 + mt * 16 + r;
            long gc = col0 + n0 + nt * 8 + c2;
            #pragma unroll
            for (int hrow = 0; hrow < 2; hrow++) {
                long grr = gr + hrow * 8;
                float v0 = acc[mt][nt][hrow * 2 + 0];
                float v1 = acc[mt][nt][hrow * 2 + 1];
                if (MODE == 0) {
                    *(float2*)(Cf + grr * N + gc) = make_float2(v0, v1);
                } else if (MODE == 1) {
                    float2 b = *(const float2*)(bias + gc);
                    float2 rr = *(const float2*)(res + grr * N + gc);
                    *(float2*)(Cf + grr * N + gc) = make_float2(v0 + b.x + rr.x, v1 + b.y + rr.y);
                } else {
                    *(uint32_t*)(Ch + grr * N + gc) = packh2(gelu_tanh(v0), gelu_tanh(v1));
                }
            }
        }
    }
}

// ======================= tensor-core flash attention (split-bf16, fp16 out) =======================
#define ASM_QH 0
#define ASM_QL 16384
#define ASM_KH 32768
#define ASM_KL 49152
#define ASM_VH 65536
#define ASM_VL 81920
#define ASM_KF 98304
#define ASM_VF 133120
#define ASM_TOTAL 167936

__device__ __forceinline__ void cvt_tile(uint32_t fbase, uint32_t hbase, uint32_t lbase, int tid) {
    int row = tid >> 1, half = tid & 1;
    uint32_t fr = fbase + row * 272;
    uint32_t hr = hbase + row * 128;
    uint32_t lr_ = lbase + row * 128;
    #pragma unroll
    for (int j = 0; j < 4; j++) {
        float4 f0, f1;
        asm volatile("ld.shared.v4.f32 {%0,%1,%2,%3}, [%4];"
                     : "=f"(f0.x), "=f"(f0.y), "=f"(f0.z), "=f"(f0.w)
                     : "r"(fr + (half * 8 + j * 2) * 16));
        asm volatile("ld.shared.v4.f32 {%0,%1,%2,%3}, [%4];"
                     : "=f"(f1.x), "=f"(f1.y), "=f"(f1.z), "=f"(f1.w)
                     : "r"(fr + (half * 8 + j * 2 + 1) * 16));
        float v[8] = {f0.x, f0.y, f0.z, f0.w, f1.x, f1.y, f1.z, f1.w};
        uint32_t hi[4], lo[4];
        #pragma unroll
        for (int q = 0; q < 4; q++) {
            float a = v[q * 2], b = v[q * 2 + 1];
            float ha = __bfloat162float(__float2bfloat16(a));
            float hb = __bfloat162float(__float2bfloat16(b));
            hi[q] = packbf2(ha, hb);
            lo[q] = packbf2(a - ha, b - hb);
        }
        int c = half * 4 + j;
        uint32_t sw = (uint32_t)((c ^ (row & 7)) << 4);
        asm volatile("st.shared.v4.b32 [%0], {%1,%2,%3,%4};"
                     :: "r"(hr + sw), "r"(hi[0]), "r"(hi[1]), "r"(hi[2]), "r"(hi[3]));
        asm volatile("st.shared.v4.b32 [%0], {%1,%2,%3,%4};"
                     :: "r"(lr_ + sw), "r"(lo[0]), "r"(lo[1]), "r"(lo[2]), "r"(lo[3]));
    }
}

__device__ __forceinline__ void stage_cp(uint32_t fbase, const float* __restrict__ src,
                                         int keyrow0, int h, int tid) {
    #pragma unroll
    for (int i = 0; i < 8; i++) {
        int idx = tid + i * 256;
        int r = idx >> 4, c = idx & 15;
        cp16(fbase + r * 272 + c * 16, src + (long)(keyrow0 + r) * HID + h * HDIM + c * 4);
    }
}

__global__ void __launch_bounds__(256) attn_mma_kernel(
    const float* __restrict__ Q, const float* __restrict__ K,
    const float* __restrict__ V, __half* __restrict__ O)
{
    extern __shared__ char smem[];
    uint32_t sb = smem_u32(smem);
    int tid = threadIdx.x;
    int w = tid >> 5, lane = tid & 31;
    int qb = blockIdx.x, h = blockIdx.y;

    int grp = lane >> 3, lr = lane & 7;
    int rowQ = w * 16 + (grp & 1) * 8 + lr;
    int ccQ  = grp >> 1;
    int xQ = rowQ & 7;
    int rowK_off = (grp >> 1) * 8 + lr;
    int ccK  = grp & 1;
    int rowV_off = (grp & 1) * 8 + lr;
    int ccV_off  = grp >> 1;

    {
        int row = tid >> 1, half = tid & 1;
        const float* src = Q + (long)(qb * 128 + row) * HID + h * HDIM + half * 32;
        uint32_t hr = sb + ASM_QH + row * 128;
        uint32_t lr2 = sb + ASM_QL + row * 128;
        #pragma unroll
        for (int j = 0; j < 4; j++) {
            float4 f0 = *(const float4*)(src + j * 8);
            float4 f1 = *(const float4*)(src + j * 8 + 4);
            float v[8] = {f0.x, f0.y, f0.z, f0.w, f1.x, f1.y, f1.z, f1.w};
            uint32_t hi[4], lo[4];
            #pragma unroll
            for (int q = 0; q < 4; q++) {
                float a = v[q * 2] * 0.125f, b = v[q * 2 + 1] * 0.125f;
                float ha = __bfloat162float(__float2bfloat16(a));
                float hb = __bfloat162float(__float2bfloat16(b));
                hi[q] = packbf2(ha, hb);
                lo[q] = packbf2(a - ha, b - hb);
            }
            int c = half * 4 + j;
            uint32_t sw = (uint32_t)((c ^ (row & 7)) << 4);
            asm volatile("st.shared.v4.b32 [%0], {%1,%2,%3,%4};"
                         :: "r"(hr + sw), "r"(hi[0]), "r"(hi[1]), "r"(hi[2]), "r"(hi[3]));
            asm volatile("st.shared.v4.b32 [%0], {%1,%2,%3,%4};"
                         :: "r"(lr2 + sw), "r"(lo[0]), "r"(lo[1]), "r"(lo[2]), "r"(lo[3]));
        }
    }
    stage_cp(sb + ASM_KF, K, 0, h, tid);
    stage_cp(sb + ASM_VF, V, 0, h, tid);
    cp_commit();
    __syncthreads();

    uint32_t qfh[4][4], qfl[4][4];
    #pragma unroll
    for (int ks = 0; ks < 4; ks++) {
        uint32_t base = sb + rowQ * 128;
        ldmx4(qfh[ks], base + ASM_QH + (((ks * 2 + ccQ) ^ xQ) << 4));
        ldmx4(qfl[ks], base + ASM_QL + (((ks * 2 + ccQ) ^ xQ) << 4));
    }

    float oacc[8][4];
    #pragma unroll
    for (int i = 0; i < 8; i++)
        #pragma unroll
        for (int q = 0; q < 4; q++) oacc[i][q] = 0.f;
    float m0 = -1e30f, m1 = -1e30f, l0 = 0.f, l1 = 0.f;

    int qg0 = qb * 128 + w * 16 + (lane >> 2);
    int qg1 = qg0 + 8;

    for (int kt = 0; kt <= qb; kt++) {
        cp_wait<0>();
        __syncthreads();
        cvt_tile(sb + ASM_KF, sb + ASM_KH, sb + ASM_KL, tid);
        cvt_tile(sb + ASM_VF, sb + ASM_VH, sb + ASM_VL, tid);
        __syncthreads();
        if (kt < qb) {
            stage_cp(sb + ASM_KF, K, (kt + 1) * 128, h, tid);
            stage_cp(sb + ASM_VF, V, (kt + 1) * 128, h, tid);
        }
        cp_commit();

        float sacc[16][4];
        #pragma unroll
        for (int i = 0; i < 16; i++)
            #pragma unroll
            for (int q = 0; q < 4; q++) sacc[i][q] = 0.f;

        #pragma unroll
        for (int ks = 0; ks < 4; ks++) {
            #pragma unroll
            for (int nb = 0; nb < 8; nb++) {
                int rowK = nb * 16 + rowK_off;
                uint32_t base = sb + rowK * 128;
                uint32_t off = (uint32_t)(((ks * 2 + ccK) ^ (rowK & 7)) << 4);
                uint32_t bkh[4], bkl[4];
                ldmx4(bkh, base + ASM_KH + off);
                ldmx4(bkl, base + ASM_KL + off);
                #pragma unroll
                for (int sub = 0; sub < 2; sub++) {
                    float* d = sacc[nb * 2 + sub];
                    mma16816(d, qfh[ks], &bkh[sub * 2]);
                    mma16816(d, qfh[ks], &bkl[sub * 2]);
                    mma16816(d, qfl[ks], &bkh[sub * 2]);
                }
            }
        }

        if (kt == qb) {
            #pragma unroll
            for (int nt = 0; nt < 16; nt++) {
                int kg = kt * 128 + nt * 8 + 2 * (lane & 3);
                #pragma unroll
                for (int e = 0; e < 2; e++) {
                    if (kg + e > qg0) sacc[nt][e]     = -1e30f;
                    if (kg + e > qg1) sacc[nt][2 + e] = -1e30f;
                }
            }
        }

        float rm0 = -1e30f, rm1 = -1e30f;
        #pragma unroll
        for (int nt = 0; nt < 16; nt++) {
            rm0 = fmaxf(rm0, fmaxf(sacc[nt][0], sacc[nt][1]));
            rm1 = fmaxf(rm1, fmaxf(sacc[nt][2], sacc[nt][3]));
        }
        rm0 = fmaxf(rm0, __shfl_xor_sync(0xFFFFFFFFu, rm0, 1));
        rm0 = fmaxf(rm0, __shfl_xor_sync(0xFFFFFFFFu, rm0, 2));
        rm1 = fmaxf(rm1, __shfl_xor_sync(0xFFFFFFFFu, rm1, 1));
        rm1 = fmaxf(rm1, __shfl_xor_sync(0xFFFFFFFFu, rm1, 2));
        float mn0 = fmaxf(m0, rm0), mn1 = fmaxf(m1, rm1);
        float al0 = __expf(m0 - mn0), al1 = __expf(m1 - mn1);
        m0 = mn0; m1 = mn1;

        float rs0 = 0.f, rs1 = 0.f;
        #pragma unroll
        for (int nt = 0; nt < 16; nt++) {
            sacc[nt][0] = __expf(sacc[nt][0] - mn0);
            sacc[nt][1] = __expf(sacc[nt][1] - mn0);
            sacc[nt][2] = __expf(sacc[nt][2] - mn1);
            sacc[nt][3] = __expf(sacc[nt][3] - mn1);
            rs0 += sacc[nt][0] + sacc[nt][1];
            rs1 += sacc[nt][2] + sacc[nt][3];
        }
        rs0 += __shfl_xor_sync(0xFFFFFFFFu, rs0, 1);
        rs0 += __shfl_xor_sync(0xFFFFFFFFu, rs0, 2);
        rs1 += __shfl_xor_sync(0xFFFFFFFFu, rs1, 1);
        rs1 += __shfl_xor_sync(0xFFFFFFFFu, rs1, 2);
        l0 = l0 * al0 + rs0;
        l1 = l1 * al1 + rs1;

        #pragma unroll
        for (int i = 0; i < 8; i++) {
            oacc[i][0] *= al0; oacc[i][1] *= al0;
            oacc[i][2] *= al1; oacc[i][3] *= al1;
        }

        #pragma unroll
        for (int ks2 = 0; ks2 < 8; ks2++) {
            uint32_t ah[4], al[4];
            {
                float p00 = sacc[2 * ks2][0],     p01 = sacc[2 * ks2][1];
                float p10 = sacc[2 * ks2][2],     p11 = sacc[2 * ks2][3];
                float p20 = sacc[2 * ks2 + 1][0], p21 = sacc[2 * ks2 + 1][1];
                float p30 = sacc[2 * ks2 + 1][2], p31 = sacc[2 * ks2 + 1][3];
                float h00 = __bfloat162float(__float2bfloat16(p00));
                float h01 = __bfloat162float(__float2bfloat16(p01));
                float h10 = __bfloat162float(__float2bfloat16(p10));
                float h11 = __bfloat162float(__float2bfloat16(p11));
                float h20 = __bfloat162float(__float2bfloat16(p20));
                float h21 = __bfloat162float(__float2bfloat16(p21));
                float h30 = __bfloat162float(__float2bfloat16(p30));
                float h31 = __bfloat162float(__float2bfloat16(p31));
                ah[0] = packbf2(h00, h01); ah[1] = packbf2(h10, h11);
                ah[2] = packbf2(h20, h21); ah[3] = packbf2(h30, h31);
                al[0] = packbf2(p00 - h00, p01 - h01);
                al[1] = packbf2(p10 - h10, p11 - h11);
                al[2] = packbf2(p20 - h20, p21 - h21);
                al[3] = packbf2(p30 - h30, p31 - h31);
            }
            #pragma unroll
            for (int db = 0; db < 4; db++) {
                int rowV = ks2 * 16 + rowV_off;
                int cc = db * 2 + ccV_off;
                uint32_t base = sb + rowV * 128;
                uint32_t off = (uint32_t)((cc ^ (rowV & 7)) << 4);
                uint32_t bvh[4], bvl[4];
                ldmx4t(bvh, base + ASM_VH + off);
                ldmx4t(bvl, base + ASM_VL + off);
                #pragma unroll
                for (int sub = 0; sub < 2; sub++) {
                    float* d = oacc[db * 2 + sub];
                    mma16816(d, ah, &bvh[sub * 2]);
                    mma16816(d, al, &bvh[sub * 2]);
                    mma16816(d, ah, &bvl[sub * 2]);
                }
            }
        }
    }

    float i0 = 1.0f / l0, i1 = 1.0f / l1;
    long gr0 = qb * 128 + w * 16 + (lane >> 2);
    long gc0 = h * HDIM + 2 * (lane & 3);
    #pragma unroll
    for (int nto = 0; nto < 8; nto++) {
        long gc = gc0 + nto * 8;
        *(uint32_t*)(O + gr0 * HID + gc)       = packh2(oacc[nto][0] * i0, oacc[nto][1] * i0);
        *(uint32_t*)(O + (gr0 + 8) * HID + gc) = packh2(oacc[nto][2] * i1, oacc[nto][3] * i1);
    }
}

// ======================= orchestration =======================
extern "C" void kernel_launch(void* const* d_in, const int* in_sizes, int n_in,
                              void* d_out, int out_size) {
    const float* emb = (const float*)d_in[0];
    const float* Wq = (const float*)d_in[2];
    const float* Wk = (const float*)d_in[3];
    const float* Wv = (const float*)d_in[4];
    const float* Wo = (const float*)d_in[5];
    const float* bo = (const float*)d_in[6];
    const float* W1 = (const float*)d_in[7];
    const float* W2 = (const float*)d_in[8];
    const float* b2 = (const float*)d_in[9];
    const float* g1 = (const float*)d_in[10];
    const float* g2 = (const float*)d_in[11];
    const float* gf = (const float*)d_in[12];
    float* out = (float*)d_out;

    float *px, *pq, *pk, *pv;
    __half *ph, *pctx, *pmid;
    __half *wqh, *wql, *wkh, *wkl, *wvh, *wvl, *woh, *wol, *w1h, *w1l, *w2h, *w2l;
    cudaGetSymbolAddress((void**)&px,   g_x);
    cudaGetSymbolAddress((void**)&pq,   g_q);
    cudaGetSymbolAddress((void**)&pk,   g_k);
    cudaGetSymbolAddress((void**)&pv,   g_v);
    cudaGetSymbolAddress((void**)&ph,   g_h);
    cudaGetSymbolAddress((void**)&pctx, g_ctx);
    cudaGetSymbolAddress((void**)&pmid, g_mid);
    cudaGetSymbolAddress((void**)&wqh, g_wqt_h); cudaGetSymbolAddress((void**)&wql, g_wqt_l);
    cudaGetSymbolAddress((void**)&wkh, g_wkt_h); cudaGetSymbolAddress((void**)&wkl, g_wkt_l);
    cudaGetSymbolAddress((void**)&wvh, g_wvt_h); cudaGetSymbolAddress((void**)&wvl, g_wvt_l);
    cudaGetSymbolAddress((void**)&woh, g_wot_h); cudaGetSymbolAddress((void**)&wol, g_wot_l);
    cudaGetSymbolAddress((void**)&w1h, g_w1t_h); cudaGetSymbolAddress((void**)&w1l, g_w1t_l);
    cudaGetSymbolAddress((void**)&w2h, g_w2t_h); cudaGetSymbolAddress((void**)&w2l, g_w2t_l);

    cudaFuncSetAttribute(gemm_mma_kernel<0>, cudaFuncAttributeMaxDynamicSharedMemorySize, GSM_TOTAL);
    cudaFuncSetAttribute(gemm_mma_kernel<1>, cudaFuncAttributeMaxDynamicSharedMemorySize, GSM_TOTAL);
    cudaFuncSetAttribute(gemm_mma_kernel<2>, cudaFuncAttributeMaxDynamicSharedMemorySize, GSM_TOTAL);
    cudaFuncSetAttribute(attn_mma_kernel, cudaFuncAttributeMaxDynamicSharedMemorySize, ASM_TOTAL);

    {
        int n4 = SEQ * HID / 4;
        copy_kernel<<<(n4 + 255) / 256, 256>>>((const float4*)emb, (float4*)px, n4);
    }

    {
        dim3 b(32, 8);
        dim3 gHH(HID / 32, HID / 32);
        dim3 gW1(ISZ / 32, HID / 32);
        dim3 gW2(HID / 32, ISZ / 32);
        for (int l = 0; l < NLAYER; l++) {
            long oHH = (long)l * HID * HID, oHI = (long)l * HID * ISZ;
            wsplit_kernel<<<gHH, b>>>(Wq + oHH, wqh + oHH, wql + oHH, HID, HID);
            wsplit_kernel<<<gHH, b>>>(Wk + oHH, wkh + oHH, wkl + oHH, HID, HID);
            wsplit_kernel<<<gHH, b>>>(Wv + oHH, wvh + oHH, wvl + oHH, HID, HID);
            wsplit_kernel<<<gHH, b>>>(Wo + oHH, woh + oHH, wol + oHH, HID, HID);
            wsplit_kernel<<<gW1, b>>>(W1 + oHI, w1h + oHI, w1l + oHI, HID, ISZ);
            wsplit_kernel<<<gW2, b>>>(W2 + oHI, w2h + oHI, w2l + oHI, ISZ, HID);
        }
    }

    dim3 gQKV(HID / 128, SEQ / 128, 3);
    dim3 gHH(HID / 128, SEQ / 128, 1);
    dim3 gHI(ISZ / 128, SEQ / 128, 1);
    dim3 gAttn(SEQ / 128, NHEAD);

    for (int l = 0; l < NLAYER; l++) {
        long oHH = (long)l * HID * HID, oHI = (long)l * HID * ISZ;

        ln_kernel<1><<<SEQ, 256>>>(px, g1 + l * HID, nullptr, ph);
        gemm_mma_kernel<0><<<gQKV, 256, GSM_TOTAL>>>(ph,
            wqh + oHH, wql + oHH, wkh + oHH, wkl + oHH, wvh + oHH, wvl + oHH,
            nullptr, nullptr, pq, pk, pv, nullptr, SEQ, HID, HID);
        attn_mma_kernel<<<gAttn, 256, ASM_TOTAL>>>(pq, pk, pv, pctx);
        gemm_mma_kernel<1><<<gHH, 256, GSM_TOTAL>>>(pctx,
            woh + oHH, wol + oHH, nullptr, nullptr, nullptr, nullptr,
            bo + l * HID, px, px, nullptr, nullptr, nullptr, SEQ, HID, HID);

        ln_kernel<1><<<SEQ, 256>>>(px, g2 + l * HID, nullptr, ph);
        gemm_mma_kernel<2><<<gHI, 256, GSM_TOTAL>>>(ph,
            w1h + oHI, w1l + oHI, nullptr, nullptr, nullptr, nullptr,
            nullptr, nullptr, nullptr, nullptr, nullptr, pmid, SEQ, ISZ, HID);
        gemm_mma_kernel<1><<<gHH, 256, GSM_TOTAL>>>(pmid,
            w2h + oHI, w2l + oHI, nullptr, nullptr, nullptr, nullptr,
            b2 + l * HID, px, px, nullptr, nullptr, nullptr, SEQ, HID, ISZ);
    }

    ln_kernel<0><<<SEQ, 256>>>(px, gf, out, nullptr);
}

// round 7
// speedup vs baseline: 4.3846x; 1.2063x over previous
#include <cuda_runtime.h>
#include <cuda_fp16.h>
#include <cuda_bf16.h>
#include <math.h>
#include <stdint.h>

#define SEQ 2048
#define HID 2048
#define NHEAD 32
#define HDIM 64
#define ISZ 8192
#define NLAYER 2

// ======================= scratch (static device arrays) =======================
__device__ float g_x  [SEQ * HID];
__device__ float g_q  [SEQ * HID];
__device__ float g_k  [SEQ * HID];
__device__ float g_v  [SEQ * HID];
__device__ __half g_h  [SEQ * HID];
__device__ __half g_ctx[SEQ * HID];
__device__ __half g_mid[SEQ * ISZ];
__device__ __half g_wqt_h[NLAYER * HID * HID], g_wqt_l[NLAYER * HID * HID];
__device__ __half g_wkt_h[NLAYER * HID * HID], g_wkt_l[NLAYER * HID * HID];
__device__ __half g_wvt_h[NLAYER * HID * HID], g_wvt_l[NLAYER * HID * HID];
__device__ __half g_wot_h[NLAYER * HID * HID], g_wot_l[NLAYER * HID * HID];
__device__ __half g_w1t_h[NLAYER * HID * ISZ], g_w1t_l[NLAYER * HID * ISZ];
__device__ __half g_w2t_h[NLAYER * ISZ * HID], g_w2t_l[NLAYER * ISZ * HID];

// ======================= PTX helpers =======================
__device__ __forceinline__ uint32_t smem_u32(const void* p) {
    uint32_t a;
    asm("{ .reg .u64 t; cvta.to.shared.u64 t, %1; cvt.u32.u64 %0, t; }" : "=r"(a) : "l"(p));
    return a;
}
__device__ __forceinline__ void cp16(uint32_t dst, const void* src) {
    asm volatile("cp.async.cg.shared.global [%0], [%1], 16;" :: "r"(dst), "l"(src));
}
__device__ __forceinline__ void cp_commit() {
    asm volatile("cp.async.commit_group;" ::: "memory");
}
template <int N>
__device__ __forceinline__ void cp_wait() {
    asm volatile("cp.async.wait_group %0;" :: "n"(N) : "memory");
}
__device__ __forceinline__ void ldmx4(uint32_t* r, uint32_t addr) {
    asm volatile("ldmatrix.sync.aligned.m8n8.x4.shared.b16 {%0,%1,%2,%3}, [%4];"
                 : "=r"(r[0]), "=r"(r[1]), "=r"(r[2]), "=r"(r[3]) : "r"(addr));
}
__device__ __forceinline__ void ldmx4t(uint32_t* r, uint32_t addr) {
    asm volatile("ldmatrix.sync.aligned.m8n8.x4.trans.shared.b16 {%0,%1,%2,%3}, [%4];"
                 : "=r"(r[0]), "=r"(r[1]), "=r"(r[2]), "=r"(r[3]) : "r"(addr));
}
__device__ __forceinline__ void mma16816(float* d, const uint32_t* a, const uint32_t* b) {
    asm volatile("mma.sync.aligned.m16n8k16.row.col.f32.bf16.bf16.f32 "
                 "{%0,%1,%2,%3}, {%4,%5,%6,%7}, {%8,%9}, {%0,%1,%2,%3};"
                 : "+f"(d[0]), "+f"(d[1]), "+f"(d[2]), "+f"(d[3])
                 : "r"(a[0]), "r"(a[1]), "r"(a[2]), "r"(a[3]), "r"(b[0]), "r"(b[1]));
}
__device__ __forceinline__ void mma16816h(float* d, const uint32_t* a, const uint32_t* b) {
    asm volatile("mma.sync.aligned.m16n8k16.row.col.f32.f16.f16.f32 "
                 "{%0,%1,%2,%3}, {%4,%5,%6,%7}, {%8,%9}, {%0,%1,%2,%3};"
                 : "+f"(d[0]), "+f"(d[1]), "+f"(d[2]), "+f"(d[3])
                 : "r"(a[0]), "r"(a[1]), "r"(a[2]), "r"(a[3]), "r"(b[0]), "r"(b[1]));
}
__device__ __forceinline__ uint32_t packbf2(float lo, float hi) {
    __nv_bfloat162 t = __floats2bfloat162_rn(lo, hi);
    return *(uint32_t*)&t;
}
__device__ __forceinline__ uint32_t packh2(float lo, float hi) {
    __half2 t = __floats2half2_rn(lo, hi);
    return *(uint32_t*)&t;
}

// ======================= small kernels =======================
__global__ void copy_kernel(const float4* __restrict__ in, float4* __restrict__ out, int n4) {
    int i = blockIdx.x * 256 + threadIdx.x;
    if (i < n4) out[i] = in[i];
}

__device__ __forceinline__ float gelu_tanh(float v) {
    float t = 0.7978845608028654f * v * (1.0f + 0.044715f * v * v);
    return 0.5f * v * (1.0f + tanhf(t));
}

template <int HALF>
__global__ void __launch_bounds__(256) ln_kernel(const float* __restrict__ x,
                                                 const float* __restrict__ gamma,
                                                 float* __restrict__ outf,
                                                 __half* __restrict__ oh) {
    __shared__ float sh[18];
    int row = blockIdx.x;
    const float* xr = x + (long)row * HID;
    float s = 0.f, s2 = 0.f;
    for (int i = threadIdx.x; i < HID; i += 256) {
        float v = xr[i];
        s += v; s2 += v * v;
    }
    #pragma unroll
    for (int o = 16; o; o >>= 1) {
        s  += __shfl_xor_sync(0xFFFFFFFFu, s,  o);
        s2 += __shfl_xor_sync(0xFFFFFFFFu, s2, o);
    }
    int w = threadIdx.x >> 5, lane = threadIdx.x & 31;
    if (lane == 0) { sh[w] = s; sh[8 + w] = s2; }
    __syncthreads();
    if (threadIdx.x < 32) {
        s  = (threadIdx.x < 8) ? sh[threadIdx.x]     : 0.f;
        s2 = (threadIdx.x < 8) ? sh[8 + threadIdx.x] : 0.f;
        #pragma unroll
        for (int o = 4; o; o >>= 1) {
            s  += __shfl_xor_sync(0xFFFFFFFFu, s,  o);
            s2 += __shfl_xor_sync(0xFFFFFFFFu, s2, o);
        }
        if (threadIdx.x == 0) {
            float mu = s * (1.0f / HID);
            float var = s2 * (1.0f / HID) - mu * mu;
            sh[16] = mu;
            sh[17] = rsqrtf(var + 1e-5f);
        }
    }
    __syncthreads();
    float mu = sh[16], inv = sh[17];
    for (int i = threadIdx.x; i < HID; i += 256) {
        float v = (xr[i] - mu) * inv * gamma[i];
        if (HALF) oh[(long)row * HID + i] = __float2half(v);
        else      outf[(long)row * HID + i] = v;
    }
}

__global__ void __launch_bounds__(256) wsplit_kernel(const float* __restrict__ W,
                                                     __half* __restrict__ Th,
                                                     __half* __restrict__ Tl,
                                                     int K, int N) {
    __shared__ float t[32][33];
    int bx = blockIdx.x * 32, by = blockIdx.y * 32;
    int tx = threadIdx.x, ty = threadIdx.y;
    #pragma unroll
    for (int i = 0; i < 4; i++)
        t[ty + i * 8][tx] = W[(long)(by + ty + i * 8) * N + bx + tx];
    __syncthreads();
    #pragma unroll
    for (int i = 0; i < 4; i++) {
        float v = t[tx][ty + i * 8];
        __half h = __float2half(v);
        long o = (long)(bx + ty + i * 8) * K + by + tx;
        Th[o] = h;
        Tl[o] = __float2half(v - __half2float(h));
    }
}

// ======================= mma.sync fp16 GEMM (3-stage pipeline) =======================
// C[M,N] = A[M,K] @ (Bh+Bl)^T, B stored [N,K] row-major fp16 hi/lo.
// BM=128, BN=128, BK=32; 8 warps, warp tile 64x32; 3-stage cp.async (72KB), 2 CTA/SM.
// Mainloop order: wait(stage c) -> sync -> issue loads(stage c+2) -> compute c.
#define A_TILE 8192
#define B_TILE 16384
#define STAGE_BYTES (A_TILE + B_TILE)
#define GSM_TOTAL (3 * STAGE_BYTES)

__device__ __forceinline__ void load_A_tile(uint32_t sbase, const __half* __restrict__ A,
                                            int K, long k0, int tid) {
    #pragma unroll
    for (int i = 0; i < 2; i++) {
        int idx = tid + i * 256;
        int row = idx >> 2, c = idx & 3;
        const __half* src = A + (long)row * K + k0 + c * 8;
        uint32_t dst = sbase + row * 64 + ((c ^ ((row >> 1) & 3)) << 4);
        cp16(dst, src);
    }
}
__device__ __forceinline__ void load_B_tile(uint32_t sbase,
                                            const __half* __restrict__ Ph,
                                            const __half* __restrict__ Pl,
                                            int K, long k0, int tid) {
    #pragma unroll
    for (int i = 0; i < 4; i++) {
        int idx = tid + i * 256;
        int row = idx >> 3, c = idx & 7;
        const __half* src = (c < 4 ? Ph : Pl) + (long)row * K + k0 + (c & 3) * 8;
        uint32_t dst = sbase + row * 128 + ((c ^ (row & 7)) << 4);
        cp16(dst, src);
    }
}

template <int MODE>
__global__ void __launch_bounds__(256, 2) gemm_mma_kernel(
    const __half* __restrict__ A,
    const __half* __restrict__ Bh0, const __half* __restrict__ Bl0,
    const __half* __restrict__ Bh1, const __half* __restrict__ Bl1,
    const __half* __restrict__ Bh2, const __half* __restrict__ Bl2,
    const float* __restrict__ bias, const float* res,
    float* Cf0, float* Cf1, float* Cf2,
    __half* __restrict__ Ch,
    int M, int N, int K)
{
    extern __shared__ char smem[];
    uint32_t sb = smem_u32(smem);
    int tid = threadIdx.x;
    int wid = tid >> 5, lane = tid & 31;
    int warp_m = wid >> 2, warp_n = wid & 3;
    int row0 = blockIdx.y * 128, col0 = blockIdx.x * 128;
    int m0 = warp_m * 64, n0 = warp_n * 32;
    int z = blockIdx.z;

    const __half* Bh = (z == 0) ? Bh0 : (z == 1) ? Bh1 : Bh2;
    const __half* Bl = (z == 0) ? Bl0 : (z == 1) ? Bl1 : Bl2;
    float* Cf = (z == 0) ? Cf0 : (z == 1) ? Cf1 : Cf2;

    const __half* pA  = A  + (long)row0 * K;
    const __half* pBh = Bh + (long)col0 * K;
    const __half* pBl = Bl + (long)col0 * K;

    float acc[4][4][4];
    #pragma unroll
    for (int i = 0; i < 4; i++)
        #pragma unroll
        for (int j = 0; j < 4; j++)
            #pragma unroll
            for (int q = 0; q < 4; q++) acc[i][j][q] = 0.f;

    int grp = lane >> 3, lr = lane & 7;
    int rowA = m0 + (grp & 1) * 8 + lr;
    int ccA  = grp >> 1;
    int rowB = n0 + (grp >> 1) * 8 + lr;
    int ccB  = grp & 1;
    int xB = rowB & 7;

    int nc = K / 32;
    // prologue: stages 0, 1
    load_A_tile(sb,          pA,       K, 0, tid);
    load_B_tile(sb + A_TILE, pBh, pBl, K, 0, tid);
    cp_commit();
    load_A_tile(sb + STAGE_BYTES,          pA,       K, 32, tid);
    load_B_tile(sb + STAGE_BYTES + A_TILE, pBh, pBl, K, 32, tid);
    cp_commit();

    int s_comp = 0, s_load = 2;   // compute slot, load slot (mod 3)
    for (int c = 0; c < nc; c++) {
        cp_wait<1>();
        __syncthreads();
        // safe: slot s_load == (c-1)%3, all warps finished reading it (barrier above)
        if (c + 2 < nc) {
            uint32_t st = sb + s_load * STAGE_BYTES;
            long k0 = (long)(c + 2) * 32;
            load_A_tile(st,          pA,       K, k0, tid);
            load_B_tile(st + A_TILE, pBh, pBl, K, k0, tid);
        }
        cp_commit();

        uint32_t sA = sb + s_comp * STAGE_BYTES;
        uint32_t sB = sA + A_TILE;
        #pragma unroll
        for (int ks = 0; ks < 2; ks++) {
            uint32_t af[4][4], bfh[2][4], bfl[2][4];
            #pragma unroll
            for (int mt = 0; mt < 4; mt++) {
                int ra = rowA + mt * 16;
                uint32_t base = sA + ra * 64;
                ldmx4(af[mt], base + (((ks * 2 + ccA) ^ ((ra >> 1) & 3)) << 4));
            }
            #pragma unroll
            for (int np = 0; np < 2; np++) {
                uint32_t base = sB + (rowB + np * 16) * 128;
                ldmx4(bfh[np], base + (((ks * 2 + ccB)     ^ xB) << 4));
                ldmx4(bfl[np], base + (((ks * 2 + ccB + 4) ^ xB) << 4));
            }
            #pragma unroll
            for (int mt = 0; mt < 4; mt++)
                #pragma unroll
                for (int nt = 0; nt < 4; nt++) {
                    const uint32_t* bh = &bfh[nt >> 1][(nt & 1) * 2];
                    const uint32_t* bl = &bfl[nt >> 1][(nt & 1) * 2];
                    mma16816h(acc[mt][nt], af[mt], bh);
                    mma16816h(acc[mt][nt], af[mt], bl);
                }
        }
        s_comp = (s_comp == 2) ? 0 : s_comp + 1;
        s_load = (s_load == 2) ? 0 : s_load + 1;
    }

    int r = lane >> 2, c2 = (lane & 3) * 2;
    #pragma unroll
    for (int mt = 0; mt < 4; mt++) {
        #pragma unroll
        for (int nt = 0; nt < 4; nt++) {
            long gr = row0 + m0 + mt * 16 + r;
            long gc = col0 + n0 + nt * 8 + c2;
            #pragma unroll
            for (int hrow = 0; hrow < 2; hrow++) {
                long grr = gr + hrow * 8;
                float v0 = acc[mt][nt][hrow * 2 + 0];
                float v1 = acc[mt][nt][hrow * 2 + 1];
                if (MODE == 0) {
                    *(float2*)(Cf + grr * N + gc) = make_float2(v0, v1);
                } else if (MODE == 1) {
                    float2 b = *(const float2*)(bias + gc);
                    float2 rr = *(const float2*)(res + grr * N + gc);
                    *(float2*)(Cf + grr * N + gc) = make_float2(v0 + b.x + rr.x, v1 + b.y + rr.y);
                } else {
                    *(uint32_t*)(Ch + grr * N + gc) = packh2(gelu_tanh(v0), gelu_tanh(v1));
                }
            }
        }
    }
}

// ======================= tensor-core flash attention (split-bf16, fp16 out) =======================
#define ASM_QH 0
#define ASM_QL 16384
#define ASM_KH 32768
#define ASM_KL 49152
#define ASM_VH 65536
#define ASM_VL 81920
#define ASM_KF 98304
#define ASM_VF 133120
#define ASM_TOTAL 167936

__device__ __forceinline__ void cvt_tile(uint32_t fbase, uint32_t hbase, uint32_t lbase, int tid) {
    int row = tid >> 1, half = tid & 1;
    uint32_t fr = fbase + row * 272;
    uint32_t hr = hbase + row * 128;
    uint32_t lr_ = lbase + row * 128;
    #pragma unroll
    for (int j = 0; j < 4; j++) {
        float4 f0, f1;
        asm volatile("ld.shared.v4.f32 {%0,%1,%2,%3}, [%4];"
                     : "=f"(f0.x), "=f"(f0.y), "=f"(f0.z), "=f"(f0.w)
                     : "r"(fr + (half * 8 + j * 2) * 16));
        asm volatile("ld.shared.v4.f32 {%0,%1,%2,%3}, [%4];"
                     : "=f"(f1.x), "=f"(f1.y), "=f"(f1.z), "=f"(f1.w)
                     : "r"(fr + (half * 8 + j * 2 + 1) * 16));
        float v[8] = {f0.x, f0.y, f0.z, f0.w, f1.x, f1.y, f1.z, f1.w};
        uint32_t hi[4], lo[4];
        #pragma unroll
        for (int q = 0; q < 4; q++) {
            float a = v[q * 2], b = v[q * 2 + 1];
            float ha = __bfloat162float(__float2bfloat16(a));
            float hb = __bfloat162float(__float2bfloat16(b));
            hi[q] = packbf2(ha, hb);
            lo[q] = packbf2(a - ha, b - hb);
        }
        int c = half * 4 + j;
        uint32_t sw = (uint32_t)((c ^ (row & 7)) << 4);
        asm volatile("st.shared.v4.b32 [%0], {%1,%2,%3,%4};"
                     :: "r"(hr + sw), "r"(hi[0]), "r"(hi[1]), "r"(hi[2]), "r"(hi[3]));
        asm volatile("st.shared.v4.b32 [%0], {%1,%2,%3,%4};"
                     :: "r"(lr_ + sw), "r"(lo[0]), "r"(lo[1]), "r"(lo[2]), "r"(lo[3]));
    }
}

__device__ __forceinline__ void stage_cp(uint32_t fbase, const float* __restrict__ src,
                                         int keyrow0, int h, int tid) {
    #pragma unroll
    for (int i = 0; i < 8; i++) {
        int idx = tid + i * 256;
        int r = idx >> 4, c = idx & 15;
        cp16(fbase + r * 272 + c * 16, src + (long)(keyrow0 + r) * HID + h * HDIM + c * 4);
    }
}

__global__ void __launch_bounds__(256) attn_mma_kernel(
    const float* __restrict__ Q, const float* __restrict__ K,
    const float* __restrict__ V, __half* __restrict__ O)
{
    extern __shared__ char smem[];
    uint32_t sb = smem_u32(smem);
    int tid = threadIdx.x;
    int w = tid >> 5, lane = tid & 31;
    int qb = blockIdx.x, h = blockIdx.y;

    int grp = lane >> 3, lr = lane & 7;
    int rowQ = w * 16 + (grp & 1) * 8 + lr;
    int ccQ  = grp >> 1;
    int xQ = rowQ & 7;
    int rowK_off = (grp >> 1) * 8 + lr;
    int ccK  = grp & 1;
    int rowV_off = (grp & 1) * 8 + lr;
    int ccV_off  = grp >> 1;

    {
        int row = tid >> 1, half = tid & 1;
        const float* src = Q + (long)(qb * 128 + row) * HID + h * HDIM + half * 32;
        uint32_t hr = sb + ASM_QH + row * 128;
        uint32_t lr2 = sb + ASM_QL + row * 128;
        #pragma unroll
        for (int j = 0; j < 4; j++) {
            float4 f0 = *(const float4*)(src + j * 8);
            float4 f1 = *(const float4*)(src + j * 8 + 4);
            float v[8] = {f0.x, f0.y, f0.z, f0.w, f1.x, f1.y, f1.z, f1.w};
            uint32_t hi[4], lo[4];
            #pragma unroll
            for (int q = 0; q < 4; q++) {
                float a = v[q * 2] * 0.125f, b = v[q * 2 + 1] * 0.125f;
                float ha = __bfloat162float(__float2bfloat16(a));
                float hb = __bfloat162float(__float2bfloat16(b));
                hi[q] = packbf2(ha, hb);
                lo[q] = packbf2(a - ha, b - hb);
            }
            int c = half * 4 + j;
            uint32_t sw = (uint32_t)((c ^ (row & 7)) << 4);
            asm volatile("st.shared.v4.b32 [%0], {%1,%2,%3,%4};"
                         :: "r"(hr + sw), "r"(hi[0]), "r"(hi[1]), "r"(hi[2]), "r"(hi[3]));
            asm volatile("st.shared.v4.b32 [%0], {%1,%2,%3,%4};"
                         :: "r"(lr2 + sw), "r"(lo[0]), "r"(lo[1]), "r"(lo[2]), "r"(lo[3]));
        }
    }
    stage_cp(sb + ASM_KF, K, 0, h, tid);
    stage_cp(sb + ASM_VF, V, 0, h, tid);
    cp_commit();
    __syncthreads();

    uint32_t qfh[4][4], qfl[4][4];
    #pragma unroll
    for (int ks = 0; ks < 4; ks++) {
        uint32_t base = sb + rowQ * 128;
        ldmx4(qfh[ks], base + ASM_QH + (((ks * 2 + ccQ) ^ xQ) << 4));
        ldmx4(qfl[ks], base + ASM_QL + (((ks * 2 + ccQ) ^ xQ) << 4));
    }

    float oacc[8][4];
    #pragma unroll
    for (int i = 0; i < 8; i++)
        #pragma unroll
        for (int q = 0; q < 4; q++) oacc[i][q] = 0.f;
    float m0 = -1e30f, m1 = -1e30f, l0 = 0.f, l1 = 0.f;

    int qg0 = qb * 128 + w * 16 + (lane >> 2);
    int qg1 = qg0 + 8;

    for (int kt = 0; kt <= qb; kt++) {
        cp_wait<0>();
        __syncthreads();
        cvt_tile(sb + ASM_KF, sb + ASM_KH, sb + ASM_KL, tid);
        cvt_tile(sb + ASM_VF, sb + ASM_VH, sb + ASM_VL, tid);
        __syncthreads();
        if (kt < qb) {
            stage_cp(sb + ASM_KF, K, (kt + 1) * 128, h, tid);
            stage_cp(sb + ASM_VF, V, (kt + 1) * 128, h, tid);
        }
        cp_commit();

        float sacc[16][4];
        #pragma unroll
        for (int i = 0; i < 16; i++)
            #pragma unroll
            for (int q = 0; q < 4; q++) sacc[i][q] = 0.f;

        #pragma unroll
        for (int ks = 0; ks < 4; ks++) {
            #pragma unroll
            for (int nb = 0; nb < 8; nb++) {
                int rowK = nb * 16 + rowK_off;
                uint32_t base = sb + rowK * 128;
                uint32_t off = (uint32_t)(((ks * 2 + ccK) ^ (rowK & 7)) << 4);
                uint32_t bkh[4], bkl[4];
                ldmx4(bkh, base + ASM_KH + off);
                ldmx4(bkl, base + ASM_KL + off);
                #pragma unroll
                for (int sub = 0; sub < 2; sub++) {
                    float* d = sacc[nb * 2 + sub];
                    mma16816(d, qfh[ks], &bkh[sub * 2]);
                    mma16816(d, qfh[ks], &bkl[sub * 2]);
                    mma16816(d, qfl[ks], &bkh[sub * 2]);
                }
            }
        }

        if (kt == qb) {
            #pragma unroll
            for (int nt = 0; nt < 16; nt++) {
                int kg = kt * 128 + nt * 8 + 2 * (lane & 3);
                #pragma unroll
                for (int e = 0; e < 2; e++) {
                    if (kg + e > qg0) sacc[nt][e]     = -1e30f;
                    if (kg + e > qg1) sacc[nt][2 + e] = -1e30f;
                }
            }
        }

        float rm0 = -1e30f, rm1 = -1e30f;
        #pragma unroll
        for (int nt = 0; nt < 16; nt++) {
            rm0 = fmaxf(rm0, fmaxf(sacc[nt][0], sacc[nt][1]));
            rm1 = fmaxf(rm1, fmaxf(sacc[nt][2], sacc[nt][3]));
        }
        rm0 = fmaxf(rm0, __shfl_xor_sync(0xFFFFFFFFu, rm0, 1));
        rm0 = fmaxf(rm0, __shfl_xor_sync(0xFFFFFFFFu, rm0, 2));
        rm1 = fmaxf(rm1, __shfl_xor_sync(0xFFFFFFFFu, rm1, 1));
        rm1 = fmaxf(rm1, __shfl_xor_sync(0xFFFFFFFFu, rm1, 2));
        float mn0 = fmaxf(m0, rm0), mn1 = fmaxf(m1, rm1);
        float al0 = __expf(m0 - mn0), al1 = __expf(m1 - mn1);
        m0 = mn0; m1 = mn1;

        float rs0 = 0.f, rs1 = 0.f;
        #pragma unroll
        for (int nt = 0; nt < 16; nt++) {
            sacc[nt][0] = __expf(sacc[nt][0] - mn0);
            sacc[nt][1] = __expf(sacc[nt][1] - mn0);
            sacc[nt][2] = __expf(sacc[nt][2] - mn1);
            sacc[nt][3] = __expf(sacc[nt][3] - mn1);
            rs0 += sacc[nt][0] + sacc[nt][1];
            rs1 += sacc[nt][2] + sacc[nt][3];
        }
        rs0 += __shfl_xor_sync(0xFFFFFFFFu, rs0, 1);
        rs0 += __shfl_xor_sync(0xFFFFFFFFu, rs0, 2);
        rs1 += __shfl_xor_sync(0xFFFFFFFFu, rs1, 1);
        rs1 += __shfl_xor_sync(0xFFFFFFFFu, rs1, 2);
        l0 = l0 * al0 + rs0;
        l1 = l1 * al1 + rs1;

        #pragma unroll
        for (int i = 0; i < 8; i++) {
            oacc[i][0] *= al0; oacc[i][1] *= al0;
            oacc[i][2] *= al1; oacc[i][3] *= al1;
        }

        #pragma unroll
        for (int ks2 = 0; ks2 < 8; ks2++) {
            uint32_t ah[4], al[4];
            {
                float p00 = sacc[2 * ks2][0],     p01 = sacc[2 * ks2][1];
                float p10 = sacc[2 * ks2][2],     p11 = sacc[2 * ks2][3];
                float p20 = sacc[2 * ks2 + 1][0], p21 = sacc[2 * ks2 + 1][1];
                float p30 = sacc[2 * ks2 + 1][2], p31 = sacc[2 * ks2 + 1][3];
                float h00 = __bfloat162float(__float2bfloat16(p00));
                float h01 = __bfloat162float(__float2bfloat16(p01));
                float h10 = __bfloat162float(__float2bfloat16(p10));
                float h11 = __bfloat162float(__float2bfloat16(p11));
                float h20 = __bfloat162float(__float2bfloat16(p20));
                float h21 = __bfloat162float(__float2bfloat16(p21));
                float h30 = __bfloat162float(__float2bfloat16(p30));
                float h31 = __bfloat162float(__float2bfloat16(p31));
                ah[0] = packbf2(h00, h01); ah[1] = packbf2(h10, h11);
                ah[2] = packbf2(h20, h21); ah[3] = packbf2(h30, h31);
                al[0] = packbf2(p00 - h00, p01 - h01);
                al[1] = packbf2(p10 - h10, p11 - h11);
                al[2] = packbf2(p20 - h20, p21 - h21);
                al[3] = packbf2(p30 - h30, p31 - h31);
            }
            #pragma unroll
            for (int db = 0; db < 4; db++) {
                int rowV = ks2 * 16 + rowV_off;
                int cc = db * 2 + ccV_off;
                uint32_t base = sb + rowV * 128;
                uint32_t off = (uint32_t)((cc ^ (rowV & 7)) << 4);
                uint32_t bvh[4], bvl[4];
                ldmx4t(bvh, base + ASM_VH + off);
                ldmx4t(bvl, base + ASM_VL + off);
                #pragma unroll
                for (int sub = 0; sub < 2; sub++) {
                    float* d = oacc[db * 2 + sub];
                    mma16816(d, ah, &bvh[sub * 2]);
                    mma16816(d, al, &bvh[sub * 2]);
                    mma16816(d, ah, &bvl[sub * 2]);
                }
            }
        }
    }

    float i0 = 1.0f / l0, i1 = 1.0f / l1;
    long gr0 = qb * 128 + w * 16 + (lane >> 2);
    long gc0 = h * HDIM + 2 * (lane & 3);
    #pragma unroll
    for (int nto = 0; nto < 8; nto++) {
        long gc = gc0 + nto * 8;
        *(uint32_t*)(O + gr0 * HID + gc)       = packh2(oacc[nto][0] * i0, oacc[nto][1] * i0);
        *(uint32_t*)(O + (gr0 + 8) * HID + gc) = packh2(oacc[nto][2] * i1, oacc[nto][3] * i1);
    }
}

// ======================= orchestration =======================
extern "C" void kernel_launch(void* const* d_in, const int* in_sizes, int n_in,
                              void* d_out, int out_size) {
    const float* emb = (const float*)d_in[0];
    const float* Wq = (const float*)d_in[2];
    const float* Wk = (const float*)d_in[3];
    const float* Wv = (const float*)d_in[4];
    const float* Wo = (const float*)d_in[5];
    const float* bo = (const float*)d_in[6];
    const float* W1 = (const float*)d_in[7];
    const float* W2 = (const float*)d_in[8];
    const float* b2 = (const float*)d_in[9];
    const float* g1 = (const float*)d_in[10];
    const float* g2 = (const float*)d_in[11];
    const float* gf = (const float*)d_in[12];
    float* out = (float*)d_out;

    float *px, *pq, *pk, *pv;
    __half *ph, *pctx, *pmid;
    __half *wqh, *wql, *wkh, *wkl, *wvh, *wvl, *woh, *wol, *w1h, *w1l, *w2h, *w2l;
    cudaGetSymbolAddress((void**)&px,   g_x);
    cudaGetSymbolAddress((void**)&pq,   g_q);
    cudaGetSymbolAddress((void**)&pk,   g_k);
    cudaGetSymbolAddress((void**)&pv,   g_v);
    cudaGetSymbolAddress((void**)&ph,   g_h);
    cudaGetSymbolAddress((void**)&pctx, g_ctx);
    cudaGetSymbolAddress((void**)&pmid, g_mid);
    cudaGetSymbolAddress((void**)&wqh, g_wqt_h); cudaGetSymbolAddress((void**)&wql, g_wqt_l);
    cudaGetSymbolAddress((void**)&wkh, g_wkt_h); cudaGetSymbolAddress((void**)&wkl, g_wkt_l);
    cudaGetSymbolAddress((void**)&wvh, g_wvt_h); cudaGetSymbolAddress((void**)&wvl, g_wvt_l);
    cudaGetSymbolAddress((void**)&woh, g_wot_h); cudaGetSymbolAddress((void**)&wol, g_wot_l);
    cudaGetSymbolAddress((void**)&w1h, g_w1t_h); cudaGetSymbolAddress((void**)&w1l, g_w1t_l);
    cudaGetSymbolAddress((void**)&w2h, g_w2t_h); cudaGetSymbolAddress((void**)&w2l, g_w2t_l);

    cudaFuncSetAttribute(gemm_mma_kernel<0>, cudaFuncAttributeMaxDynamicSharedMemorySize, GSM_TOTAL);
    cudaFuncSetAttribute(gemm_mma_kernel<1>, cudaFuncAttributeMaxDynamicSharedMemorySize, GSM_TOTAL);
    cudaFuncSetAttribute(gemm_mma_kernel<2>, cudaFuncAttributeMaxDynamicSharedMemorySize, GSM_TOTAL);
    cudaFuncSetAttribute(attn_mma_kernel, cudaFuncAttributeMaxDynamicSharedMemorySize, ASM_TOTAL);

    {
        int n4 = SEQ * HID / 4;
        copy_kernel<<<(n4 + 255) / 256, 256>>>((const float4*)emb, (float4*)px, n4);
    }

    {
        dim3 b(32, 8);
        dim3 gHH(HID / 32, HID / 32);
        dim3 gW1(ISZ / 32, HID / 32);
        dim3 gW2(HID / 32, ISZ / 32);
        for (int l = 0; l < NLAYER; l++) {
            long oHH = (long)l * HID * HID, oHI = (long)l * HID * ISZ;
            wsplit_kernel<<<gHH, b>>>(Wq + oHH, wqh + oHH, wql + oHH, HID, HID);
            wsplit_kernel<<<gHH, b>>>(Wk + oHH, wkh + oHH, wkl + oHH, HID, HID);
            wsplit_kernel<<<gHH, b>>>(Wv + oHH, wvh + oHH, wvl + oHH, HID, HID);
            wsplit_kernel<<<gHH, b>>>(Wo + oHH, woh + oHH, wol + oHH, HID, HID);
            wsplit_kernel<<<gW1, b>>>(W1 + oHI, w1h + oHI, w1l + oHI, HID, ISZ);
            wsplit_kernel<<<gW2, b>>>(W2 + oHI, w2h + oHI, w2l + oHI, ISZ, HID);
        }
    }

    dim3 gQKV(HID / 128, SEQ / 128, 3);
    dim3 gHH(HID / 128, SEQ / 128, 1);
    dim3 gHI(ISZ / 128, SEQ / 128, 1);
    dim3 gAttn(SEQ / 128, NHEAD);

    for (int l = 0; l < NLAYER; l++) {
        long oHH = (long)l * HID * HID, oHI = (long)l * HID * ISZ;

        ln_kernel<1><<<SEQ, 256>>>(px, g1 + l * HID, nullptr, ph);
        gemm_mma_kernel<0><<<gQKV, 256, GSM_TOTAL>>>(ph,
            wqh + oHH, wql + oHH, wkh + oHH, wkl + oHH, wvh + oHH, wvl + oHH,
            nullptr, nullptr, pq, pk, pv, nullptr, SEQ, HID, HID);
        attn_mma_kernel<<<gAttn, 256, ASM_TOTAL>>>(pq, pk, pv, pctx);
        gemm_mma_kernel<1><<<gHH, 256, GSM_TOTAL>>>(pctx,
            woh + oHH, wol + oHH, nullptr, nullptr, nullptr, nullptr,
            bo + l * HID, px, px, nullptr, nullptr, nullptr, SEQ, HID, HID);

        ln_kernel<1><<<SEQ, 256>>>(px, g2 + l * HID, nullptr, ph);
        gemm_mma_kernel<2><<<gHI, 256, GSM_TOTAL>>>(ph,
            w1h + oHI, w1l + oHI, nullptr, nullptr, nullptr, nullptr,
            nullptr, nullptr, nullptr, nullptr, nullptr, pmid, SEQ, ISZ, HID);
        gemm_mma_kernel<1><<<gHH, 256, GSM_TOTAL>>>(pmid,
            w2h + oHI, w2l + oHI, nullptr, nullptr, nullptr, nullptr,
            b2 + l * HID, px, px, nullptr, nullptr, nullptr, SEQ, HID, ISZ);
    }

    ln_kernel<0><<<SEQ, 256>>>(px, gf, out, nullptr);
}

// round 8
// speedup vs baseline: 4.4147x; 1.0069x over previous
#include <cuda_runtime.h>
#include <cuda_fp16.h>
#include <cuda_bf16.h>
#include <math.h>
#include <stdint.h>

#define SEQ 2048
#define HID 2048
#define NHEAD 32
#define HDIM 64
#define ISZ 8192
#define NLAYER 2

// ======================= scratch (static device arrays) =======================
__device__ float g_x  [SEQ * HID];
__device__ float g_q  [SEQ * HID];
__device__ float g_k  [SEQ * HID];
__device__ float g_v  [SEQ * HID];
__device__ __half g_h  [SEQ * HID];
__device__ __half g_ctx[SEQ * HID];
__device__ __half g_mid[SEQ * ISZ];
__device__ __half g_wqt_h[NLAYER * HID * HID], g_wqt_l[NLAYER * HID * HID];
__device__ __half g_wkt_h[NLAYER * HID * HID], g_wkt_l[NLAYER * HID * HID];
__device__ __half g_wvt_h[NLAYER * HID * HID], g_wvt_l[NLAYER * HID * HID];
__device__ __half g_wot_h[NLAYER * HID * HID], g_wot_l[NLAYER * HID * HID];
__device__ __half g_w1t_h[NLAYER * HID * ISZ], g_w1t_l[NLAYER * HID * ISZ];
__device__ __half g_w2t_h[NLAYER * ISZ * HID], g_w2t_l[NLAYER * ISZ * HID];

// ======================= PTX helpers =======================
__device__ __forceinline__ uint32_t smem_u32(const void* p) {
    uint32_t a;
    asm("{ .reg .u64 t; cvta.to.shared.u64 t, %1; cvt.u32.u64 %0, t; }" : "=r"(a) : "l"(p));
    return a;
}
__device__ __forceinline__ void cp16(uint32_t dst, const void* src) {
    asm volatile("cp.async.cg.shared.global [%0], [%1], 16;" :: "r"(dst), "l"(src));
}
__device__ __forceinline__ void cp_commit() {
    asm volatile("cp.async.commit_group;" ::: "memory");
}
template <int N>
__device__ __forceinline__ void cp_wait() {
    asm volatile("cp.async.wait_group %0;" :: "n"(N) : "memory");
}
__device__ __forceinline__ void ldmx4(uint32_t* r, uint32_t addr) {
    asm volatile("ldmatrix.sync.aligned.m8n8.x4.shared.b16 {%0,%1,%2,%3}, [%4];"
                 : "=r"(r[0]), "=r"(r[1]), "=r"(r[2]), "=r"(r[3]) : "r"(addr));
}
__device__ __forceinline__ void ldmx4t(uint32_t* r, uint32_t addr) {
    asm volatile("ldmatrix.sync.aligned.m8n8.x4.trans.shared.b16 {%0,%1,%2,%3}, [%4];"
                 : "=r"(r[0]), "=r"(r[1]), "=r"(r[2]), "=r"(r[3]) : "r"(addr));
}
__device__ __forceinline__ void mma16816(float* d, const uint32_t* a, const uint32_t* b) {
    asm volatile("mma.sync.aligned.m16n8k16.row.col.f32.bf16.bf16.f32 "
                 "{%0,%1,%2,%3}, {%4,%5,%6,%7}, {%8,%9}, {%0,%1,%2,%3};"
                 : "+f"(d[0]), "+f"(d[1]), "+f"(d[2]), "+f"(d[3])
                 : "r"(a[0]), "r"(a[1]), "r"(a[2]), "r"(a[3]), "r"(b[0]), "r"(b[1]));
}
__device__ __forceinline__ void mma16816h(float* d, const uint32_t* a, const uint32_t* b) {
    asm volatile("mma.sync.aligned.m16n8k16.row.col.f32.f16.f16.f32 "
                 "{%0,%1,%2,%3}, {%4,%5,%6,%7}, {%8,%9}, {%0,%1,%2,%3};"
                 : "+f"(d[0]), "+f"(d[1]), "+f"(d[2]), "+f"(d[3])
                 : "r"(a[0]), "r"(a[1]), "r"(a[2]), "r"(a[3]), "r"(b[0]), "r"(b[1]));
}
__device__ __forceinline__ uint32_t packbf2(float lo, float hi) {
    __nv_bfloat162 t = __floats2bfloat162_rn(lo, hi);
    return *(uint32_t*)&t;
}
__device__ __forceinline__ uint32_t packh2(float lo, float hi) {
    __half2 t = __floats2half2_rn(lo, hi);
    return *(uint32_t*)&t;
}

// ======================= small kernels =======================
__global__ void copy_kernel(const float4* __restrict__ in, float4* __restrict__ out, int n4) {
    int i = blockIdx.x * 256 + threadIdx.x;
    if (i < n4) out[i] = in[i];
}

__device__ __forceinline__ float gelu_tanh(float v) {
    float t = 0.7978845608028654f * v * (1.0f + 0.044715f * v * v);
    return 0.5f * v * (1.0f + tanhf(t));
}

template <int HALF>
__global__ void __launch_bounds__(256) ln_kernel(const float* __restrict__ x,
                                                 const float* __restrict__ gamma,
                                                 float* __restrict__ outf,
                                                 __half* __restrict__ oh) {
    __shared__ float sh[18];
    int row = blockIdx.x;
    const float* xr = x + (long)row * HID;
    float s = 0.f, s2 = 0.f;
    for (int i = threadIdx.x; i < HID; i += 256) {
        float v = xr[i];
        s += v; s2 += v * v;
    }
    #pragma unroll
    for (int o = 16; o; o >>= 1) {
        s  += __shfl_xor_sync(0xFFFFFFFFu, s,  o);
        s2 += __shfl_xor_sync(0xFFFFFFFFu, s2, o);
    }
    int w = threadIdx.x >> 5, lane = threadIdx.x & 31;
    if (lane == 0) { sh[w] = s; sh[8 + w] = s2; }
    __syncthreads();
    if (threadIdx.x < 32) {
        s  = (threadIdx.x < 8) ? sh[threadIdx.x]     : 0.f;
        s2 = (threadIdx.x < 8) ? sh[8 + threadIdx.x] : 0.f;
        #pragma unroll
        for (int o = 4; o; o >>= 1) {
            s  += __shfl_xor_sync(0xFFFFFFFFu, s,  o);
            s2 += __shfl_xor_sync(0xFFFFFFFFu, s2, o);
        }
        if (threadIdx.x == 0) {
            float mu = s * (1.0f / HID);
            float var = s2 * (1.0f / HID) - mu * mu;
            sh[16] = mu;
            sh[17] = rsqrtf(var + 1e-5f);
        }
    }
    __syncthreads();
    float mu = sh[16], inv = sh[17];
    for (int i = threadIdx.x; i < HID; i += 256) {
        float v = (xr[i] - mu) * inv * gamma[i];
        if (HALF) oh[(long)row * HID + i] = __float2half(v);
        else      outf[(long)row * HID + i] = v;
    }
}

__global__ void __launch_bounds__(256) wsplit_kernel(const float* __restrict__ W,
                                                     __half* __restrict__ Th,
                                                     __half* __restrict__ Tl,
                                                     int K, int N) {
    __shared__ float t[32][33];
    int bx = blockIdx.x * 32, by = blockIdx.y * 32;
    int tx = threadIdx.x, ty = threadIdx.y;
    #pragma unroll
    for (int i = 0; i < 4; i++)
        t[ty + i * 8][tx] = W[(long)(by + ty + i * 8) * N + bx + tx];
    __syncthreads();
    #pragma unroll
    for (int i = 0; i < 4; i++) {
        float v = t[tx][ty + i * 8];
        __half h = __float2half(v);
        long o = (long)(bx + ty + i * 8) * K + by + tx;
        Th[o] = h;
        Tl[o] = __float2half(v - __half2float(h));
    }
}

// ======================= mma.sync fp16 GEMM (4-stage pipeline) =======================
// C[M,N] = A[M,K] @ (Bh+Bl)^T, B stored [N,K] row-major fp16 hi/lo.
// BM=128, BN=128, BK=32; 8 warps, warp tile 64x32; 4-stage cp.async (96KB), 2 CTA/SM.
// Mainloop order: wait(stage c) -> sync -> issue loads(stage c+3) -> compute c.
#define A_TILE 8192
#define B_TILE 16384
#define STAGE_BYTES (A_TILE + B_TILE)
#define NSTAGE 4
#define GSM_TOTAL (NSTAGE * STAGE_BYTES)

__device__ __forceinline__ void load_A_tile(uint32_t sbase, const __half* __restrict__ A,
                                            int K, long k0, int tid) {
    #pragma unroll
    for (int i = 0; i < 2; i++) {
        int idx = tid + i * 256;
        int row = idx >> 2, c = idx & 3;
        const __half* src = A + (long)row * K + k0 + c * 8;
        uint32_t dst = sbase + row * 64 + ((c ^ ((row >> 1) & 3)) << 4);
        cp16(dst, src);
    }
}
__device__ __forceinline__ void load_B_tile(uint32_t sbase,
                                            const __half* __restrict__ Ph,
                                            const __half* __restrict__ Pl,
                                            int K, long k0, int tid) {
    #pragma unroll
    for (int i = 0; i < 4; i++) {
        int idx = tid + i * 256;
        int row = idx >> 3, c = idx & 7;
        const __half* src = (c < 4 ? Ph : Pl) + (long)row * K + k0 + (c & 3) * 8;
        uint32_t dst = sbase + row * 128 + ((c ^ (row & 7)) << 4);
        cp16(dst, src);
    }
}

template <int MODE>
__global__ void __launch_bounds__(256, 2) gemm_mma_kernel(
    const __half* __restrict__ A,
    const __half* __restrict__ Bh0, const __half* __restrict__ Bl0,
    const __half* __restrict__ Bh1, const __half* __restrict__ Bl1,
    const __half* __restrict__ Bh2, const __half* __restrict__ Bl2,
    const float* __restrict__ bias, const float* res,
    float* Cf0, float* Cf1, float* Cf2,
    __half* __restrict__ Ch,
    int M, int N, int K)
{
    extern __shared__ char smem[];
    uint32_t sb = smem_u32(smem);
    int tid = threadIdx.x;
    int wid = tid >> 5, lane = tid & 31;
    int warp_m = wid >> 2, warp_n = wid & 3;
    int row0 = blockIdx.y * 128, col0 = blockIdx.x * 128;
    int m0 = warp_m * 64, n0 = warp_n * 32;
    int z = blockIdx.z;

    const __half* Bh = (z == 0) ? Bh0 : (z == 1) ? Bh1 : Bh2;
    const __half* Bl = (z == 0) ? Bl0 : (z == 1) ? Bl1 : Bl2;
    float* Cf = (z == 0) ? Cf0 : (z == 1) ? Cf1 : Cf2;

    const __half* pA  = A  + (long)row0 * K;
    const __half* pBh = Bh + (long)col0 * K;
    const __half* pBl = Bl + (long)col0 * K;

    float acc[4][4][4];
    #pragma unroll
    for (int i = 0; i < 4; i++)
        #pragma unroll
        for (int j = 0; j < 4; j++)
            #pragma unroll
            for (int q = 0; q < 4; q++) acc[i][j][q] = 0.f;

    int grp = lane >> 3, lr = lane & 7;
    int rowA = m0 + (grp & 1) * 8 + lr;
    int ccA  = grp >> 1;
    int rowB = n0 + (grp >> 1) * 8 + lr;
    int ccB  = grp & 1;
    int xB = rowB & 7;

    int nc = K / 32;
    // prologue: stages 0, 1, 2
    #pragma unroll
    for (int p = 0; p < 3; p++) {
        uint32_t st = sb + p * STAGE_BYTES;
        load_A_tile(st,          pA,       K, (long)p * 32, tid);
        load_B_tile(st + A_TILE, pBh, pBl, K, (long)p * 32, tid);
        cp_commit();
    }

    int s_comp = 0, s_load = 3;   // compute slot, load slot (mod 4)
    for (int c = 0; c < nc; c++) {
        cp_wait<2>();
        __syncthreads();
        // safe: slot s_load == (c-1)%4; all warps finished reading it (barrier above)
        if (c + 3 < nc) {
            uint32_t st = sb + s_load * STAGE_BYTES;
            long k0 = (long)(c + 3) * 32;
            load_A_tile(st,          pA,       K, k0, tid);
            load_B_tile(st + A_TILE, pBh, pBl, K, k0, tid);
        }
        cp_commit();

        uint32_t sA = sb + s_comp * STAGE_BYTES;
        uint32_t sB = sA + A_TILE;
        #pragma unroll
        for (int ks = 0; ks < 2; ks++) {
            uint32_t af[4][4], bfh[2][4], bfl[2][4];
            #pragma unroll
            for (int mt = 0; mt < 4; mt++) {
                int ra = rowA + mt * 16;
                uint32_t base = sA + ra * 64;
                ldmx4(af[mt], base + (((ks * 2 + ccA) ^ ((ra >> 1) & 3)) << 4));
            }
            #pragma unroll
            for (int np = 0; np < 2; np++) {
                uint32_t base = sB + (rowB + np * 16) * 128;
                ldmx4(bfh[np], base + (((ks * 2 + ccB)     ^ xB) << 4));
                ldmx4(bfl[np], base + (((ks * 2 + ccB + 4) ^ xB) << 4));
            }
            #pragma unroll
            for (int mt = 0; mt < 4; mt++)
                #pragma unroll
                for (int nt = 0; nt < 4; nt++) {
                    const uint32_t* bh = &bfh[nt >> 1][(nt & 1) * 2];
                    const uint32_t* bl = &bfl[nt >> 1][(nt & 1) * 2];
                    mma16816h(acc[mt][nt], af[mt], bh);
                    mma16816h(acc[mt][nt], af[mt], bl);
                }
        }
        s_comp = (s_comp + 1) & 3;
        s_load = (s_load + 1) & 3;
    }

    int r = lane >> 2, c2 = (lane & 3) * 2;
    #pragma unroll
    for (int mt = 0; mt < 4; mt++) {
        #pragma unroll
        for (int nt = 0; nt < 4; nt++) {
            long gr = row0 + m0 + mt * 16 + r;
            long gc = col0 + n0 + nt * 8 + c2;
            #pragma unroll
            for (int hrow = 0; hrow < 2; hrow++) {
                long grr = gr + hrow * 8;
                float v0 = acc[mt][nt][hrow * 2 + 0];
                float v1 = acc[mt][nt][hrow * 2 + 1];
                if (MODE == 0) {
                    *(float2*)(Cf + grr * N + gc) = make_float2(v0, v1);
                } else if (MODE == 1) {
                    float2 b = *(const float2*)(bias + gc);
                    float2 rr = *(const float2*)(res + grr * N + gc);
                    *(float2*)(Cf + grr * N + gc) = make_float2(v0 + b.x + rr.x, v1 + b.y + rr.y);
                } else {
                    *(uint32_t*)(Ch + grr * N + gc) = packh2(gelu_tanh(v0), gelu_tanh(v1));
                }
            }
        }
    }
}

// ======================= tensor-core flash attention (split-bf16, fp16 out) =======================
#define ASM_QH 0
#define ASM_QL 16384
#define ASM_KH 32768
#define ASM_KL 49152
#define ASM_VH 65536
#define ASM_VL 81920
#define ASM_KF 98304
#define ASM_VF 133120
#define ASM_TOTAL 167936

__device__ __forceinline__ void cvt_tile(uint32_t fbase, uint32_t hbase, uint32_t lbase, int tid) {
    int row = tid >> 1, half = tid & 1;
    uint32_t fr = fbase + row * 272;
    uint32_t hr = hbase + row * 128;
    uint32_t lr_ = lbase + row * 128;
    #pragma unroll
    for (int j = 0; j < 4; j++) {
        float4 f0, f1;
        asm volatile("ld.shared.v4.f32 {%0,%1,%2,%3}, [%4];"
                     : "=f"(f0.x), "=f"(f0.y), "=f"(f0.z), "=f"(f0.w)
                     : "r"(fr + (half * 8 + j * 2) * 16));
        asm volatile("ld.shared.v4.f32 {%0,%1,%2,%3}, [%4];"
                     : "=f"(f1.x), "=f"(f1.y), "=f"(f1.z), "=f"(f1.w)
                     : "r"(fr + (half * 8 + j * 2 + 1) * 16));
        float v[8] = {f0.x, f0.y, f0.z, f0.w, f1.x, f1.y, f1.z, f1.w};
        uint32_t hi[4], lo[4];
        #pragma unroll
        for (int q = 0; q < 4; q++) {
            float a = v[q * 2], b = v[q * 2 + 1];
            float ha = __bfloat162float(__float2bfloat16(a));
            float hb = __bfloat162float(__float2bfloat16(b));
            hi[q] = packbf2(ha, hb);
            lo[q] = packbf2(a - ha, b - hb);
        }
        int c = half * 4 + j;
        uint32_t sw = (uint32_t)((c ^ (row & 7)) << 4);
        asm volatile("st.shared.v4.b32 [%0], {%1,%2,%3,%4};"
                     :: "r"(hr + sw), "r"(hi[0]), "r"(hi[1]), "r"(hi[2]), "r"(hi[3]));
        asm volatile("st.shared.v4.b32 [%0], {%1,%2,%3,%4};"
                     :: "r"(lr_ + sw), "r"(lo[0]), "r"(lo[1]), "r"(lo[2]), "r"(lo[3]));
    }
}

__device__ __forceinline__ void stage_cp(uint32_t fbase, const float* __restrict__ src,
                                         int keyrow0, int h, int tid) {
    #pragma unroll
    for (int i = 0; i < 8; i++) {
        int idx = tid + i * 256;
        int r = idx >> 4, c = idx & 15;
        cp16(fbase + r * 272 + c * 16, src + (long)(keyrow0 + r) * HID + h * HDIM + c * 4);
    }
}

__global__ void __launch_bounds__(256) attn_mma_kernel(
    const float* __restrict__ Q, const float* __restrict__ K,
    const float* __restrict__ V, __half* __restrict__ O)
{
    extern __shared__ char smem[];
    uint32_t sb = smem_u32(smem);
    int tid = threadIdx.x;
    int w = tid >> 5, lane = tid & 31;
    int qb = blockIdx.x, h = blockIdx.y;

    int grp = lane >> 3, lr = lane & 7;
    int rowQ = w * 16 + (grp & 1) * 8 + lr;
    int ccQ  = grp >> 1;
    int xQ = rowQ & 7;
    int rowK_off = (grp >> 1) * 8 + lr;
    int ccK  = grp & 1;
    int rowV_off = (grp & 1) * 8 + lr;
    int ccV_off  = grp >> 1;

    {
        int row = tid >> 1, half = tid & 1;
        const float* src = Q + (long)(qb * 128 + row) * HID + h * HDIM + half * 32;
        uint32_t hr = sb + ASM_QH + row * 128;
        uint32_t lr2 = sb + ASM_QL + row * 128;
        #pragma unroll
        for (int j = 0; j < 4; j++) {
            float4 f0 = *(const float4*)(src + j * 8);
            float4 f1 = *(const float4*)(src + j * 8 + 4);
            float v[8] = {f0.x, f0.y, f0.z, f0.w, f1.x, f1.y, f1.z, f1.w};
            uint32_t hi[4], lo[4];
            #pragma unroll
            for (int q = 0; q < 4; q++) {
                float a = v[q * 2] * 0.125f, b = v[q * 2 + 1] * 0.125f;
                float ha = __bfloat162float(__float2bfloat16(a));
                float hb = __bfloat162float(__float2bfloat16(b));
                hi[q] = packbf2(ha, hb);
                lo[q] = packbf2(a - ha, b - hb);
            }
            int c = half * 4 + j;
            uint32_t sw = (uint32_t)((c ^ (row & 7)) << 4);
            asm volatile("st.shared.v4.b32 [%0], {%1,%2,%3,%4};"
                         :: "r"(hr + sw), "r"(hi[0]), "r"(hi[1]), "r"(hi[2]), "r"(hi[3]));
            asm volatile("st.shared.v4.b32 [%0], {%1,%2,%3,%4};"
                         :: "r"(lr2 + sw), "r"(lo[0]), "r"(lo[1]), "r"(lo[2]), "r"(lo[3]));
        }
    }
    stage_cp(sb + ASM_KF, K, 0, h, tid);
    stage_cp(sb + ASM_VF, V, 0, h, tid);
    cp_commit();
    __syncthreads();

    uint32_t qfh[4][4], qfl[4][4];
    #pragma unroll
    for (int ks = 0; ks < 4; ks++) {
        uint32_t base = sb + rowQ * 128;
        ldmx4(qfh[ks], base + ASM_QH + (((ks * 2 + ccQ) ^ xQ) << 4));
        ldmx4(qfl[ks], base + ASM_QL + (((ks * 2 + ccQ) ^ xQ) << 4));
    }

    float oacc[8][4];
    #pragma unroll
    for (int i = 0; i < 8; i++)
        #pragma unroll
        for (int q = 0; q < 4; q++) oacc[i][q] = 0.f;
    float m0 = -1e30f, m1 = -1e30f, l0 = 0.f, l1 = 0.f;

    int qg0 = qb * 128 + w * 16 + (lane >> 2);
    int qg1 = qg0 + 8;

    for (int kt = 0; kt <= qb; kt++) {
        cp_wait<0>();
        __syncthreads();
        cvt_tile(sb + ASM_KF, sb + ASM_KH, sb + ASM_KL, tid);
        cvt_tile(sb + ASM_VF, sb + ASM_VH, sb + ASM_VL, tid);
        __syncthreads();
        if (kt < qb) {
            stage_cp(sb + ASM_KF, K, (kt + 1) * 128, h, tid);
            stage_cp(sb + ASM_VF, V, (kt + 1) * 128, h, tid);
        }
        cp_commit();

        float sacc[16][4];
        #pragma unroll
        for (int i = 0; i < 16; i++)
            #pragma unroll
            for (int q = 0; q < 4; q++) sacc[i][q] = 0.f;

        #pragma unroll
        for (int ks = 0; ks < 4; ks++) {
            #pragma unroll
            for (int nb = 0; nb < 8; nb++) {
                int rowK = nb * 16 + rowK_off;
                uint32_t base = sb + rowK * 128;
                uint32_t off = (uint32_t)(((ks * 2 + ccK) ^ (rowK & 7)) << 4);
                uint32_t bkh[4], bkl[4];
                ldmx4(bkh, base + ASM_KH + off);
                ldmx4(bkl, base + ASM_KL + off);
                #pragma unroll
                for (int sub = 0; sub < 2; sub++) {
                    float* d = sacc[nb * 2 + sub];
                    mma16816(d, qfh[ks], &bkh[sub * 2]);
                    mma16816(d, qfh[ks], &bkl[sub * 2]);
                    mma16816(d, qfl[ks], &bkh[sub * 2]);
                }
            }
        }

        if (kt == qb) {
            #pragma unroll
            for (int nt = 0; nt < 16; nt++) {
                int kg = kt * 128 + nt * 8 + 2 * (lane & 3);
                #pragma unroll
                for (int e = 0; e < 2; e++) {
                    if (kg + e > qg0) sacc[nt][e]     = -1e30f;
                    if (kg + e > qg1) sacc[nt][2 + e] = -1e30f;
                }
            }
        }

        float rm0 = -1e30f, rm1 = -1e30f;
        #pragma unroll
        for (int nt = 0; nt < 16; nt++) {
            rm0 = fmaxf(rm0, fmaxf(sacc[nt][0], sacc[nt][1]));
            rm1 = fmaxf(rm1, fmaxf(sacc[nt][2], sacc[nt][3]));
        }
        rm0 = fmaxf(rm0, __shfl_xor_sync(0xFFFFFFFFu, rm0, 1));
        rm0 = fmaxf(rm0, __shfl_xor_sync(0xFFFFFFFFu, rm0, 2));
        rm1 = fmaxf(rm1, __shfl_xor_sync(0xFFFFFFFFu, rm1, 1));
        rm1 = fmaxf(rm1, __shfl_xor_sync(0xFFFFFFFFu, rm1, 2));
        float mn0 = fmaxf(m0, rm0), mn1 = fmaxf(m1, rm1);
        float al0 = __expf(m0 - mn0), al1 = __expf(m1 - mn1);
        m0 = mn0; m1 = mn1;

        float rs0 = 0.f, rs1 = 0.f;
        #pragma unroll
        for (int nt = 0; nt < 16; nt++) {
            sacc[nt][0] = __expf(sacc[nt][0] - mn0);
            sacc[nt][1] = __expf(sacc[nt][1] - mn0);
            sacc[nt][2] = __expf(sacc[nt][2] - mn1);
            sacc[nt][3] = __expf(sacc[nt][3] - mn1);
            rs0 += sacc[nt][0] + sacc[nt][1];
            rs1 += sacc[nt][2] + sacc[nt][3];
        }
        rs0 += __shfl_xor_sync(0xFFFFFFFFu, rs0, 1);
        rs0 += __shfl_xor_sync(0xFFFFFFFFu, rs0, 2);
        rs1 += __shfl_xor_sync(0xFFFFFFFFu, rs1, 1);
        rs1 += __shfl_xor_sync(0xFFFFFFFFu, rs1, 2);
        l0 = l0 * al0 + rs0;
        l1 = l1 * al1 + rs1;

        #pragma unroll
        for (int i = 0; i < 8; i++) {
            oacc[i][0] *= al0; oacc[i][1] *= al0;
            oacc[i][2] *= al1; oacc[i][3] *= al1;
        }

        #pragma unroll
        for (int ks2 = 0; ks2 < 8; ks2++) {
            uint32_t ah[4], al[4];
            {
                float p00 = sacc[2 * ks2][0],     p01 = sacc[2 * ks2][1];
                float p10 = sacc[2 * ks2][2],     p11 = sacc[2 * ks2][3];
                float p20 = sacc[2 * ks2 + 1][0], p21 = sacc[2 * ks2 + 1][1];
                float p30 = sacc[2 * ks2 + 1][2], p31 = sacc[2 * ks2 + 1][3];
                float h00 = __bfloat162float(__float2bfloat16(p00));
                float h01 = __bfloat162float(__float2bfloat16(p01));
                float h10 = __bfloat162float(__float2bfloat16(p10));
                float h11 = __bfloat162float(__float2bfloat16(p11));
                float h20 = __bfloat162float(__float2bfloat16(p20));
                float h21 = __bfloat162float(__float2bfloat16(p21));
                float h30 = __bfloat162float(__float2bfloat16(p30));
                float h31 = __bfloat162float(__float2bfloat16(p31));
                ah[0] = packbf2(h00, h01); ah[1] = packbf2(h10, h11);
                ah[2] = packbf2(h20, h21); ah[3] = packbf2(h30, h31);
                al[0] = packbf2(p00 - h00, p01 - h01);
                al[1] = packbf2(p10 - h10, p11 - h11);
                al[2] = packbf2(p20 - h20, p21 - h21);
                al[3] = packbf2(p30 - h30, p31 - h31);
            }
            #pragma unroll
            for (int db = 0; db < 4; db++) {
                int rowV = ks2 * 16 + rowV_off;
                int cc = db * 2 + ccV_off;
                uint32_t base = sb + rowV * 128;
                uint32_t off = (uint32_t)((cc ^ (rowV & 7)) << 4);
                uint32_t bvh[4], bvl[4];
                ldmx4t(bvh, base + ASM_VH + off);
                ldmx4t(bvl, base + ASM_VL + off);
                #pragma unroll
                for (int sub = 0; sub < 2; sub++) {
                    float* d = oacc[db * 2 + sub];
                    mma16816(d, ah, &bvh[sub * 2]);
                    mma16816(d, al, &bvh[sub * 2]);
                    mma16816(d, ah, &bvl[sub * 2]);
                }
            }
        }
    }

    float i0 = 1.0f / l0, i1 = 1.0f / l1;
    long gr0 = qb * 128 + w * 16 + (lane >> 2);
    long gc0 = h * HDIM + 2 * (lane & 3);
    #pragma unroll
    for (int nto = 0; nto < 8; nto++) {
        long gc = gc0 + nto * 8;
        *(uint32_t*)(O + gr0 * HID + gc)       = packh2(oacc[nto][0] * i0, oacc[nto][1] * i0);
        *(uint32_t*)(O + (gr0 + 8) * HID + gc) = packh2(oacc[nto][2] * i1, oacc[nto][3] * i1);
    }
}

// ======================= orchestration =======================
extern "C" void kernel_launch(void* const* d_in, const int* in_sizes, int n_in,
                              void* d_out, int out_size) {
    const float* emb = (const float*)d_in[0];
    const float* Wq = (const float*)d_in[2];
    const float* Wk = (const float*)d_in[3];
    const float* Wv = (const float*)d_in[4];
    const float* Wo = (const float*)d_in[5];
    const float* bo = (const float*)d_in[6];
    const float* W1 = (const float*)d_in[7];
    const float* W2 = (const float*)d_in[8];
    const float* b2 = (const float*)d_in[9];
    const float* g1 = (const float*)d_in[10];
    const float* g2 = (const float*)d_in[11];
    const float* gf = (const float*)d_in[12];
    float* out = (float*)d_out;

    float *px, *pq, *pk, *pv;
    __half *ph, *pctx, *pmid;
    __half *wqh, *wql, *wkh, *wkl, *wvh, *wvl, *woh, *wol, *w1h, *w1l, *w2h, *w2l;
    cudaGetSymbolAddress((void**)&px,   g_x);
    cudaGetSymbolAddress((void**)&pq,   g_q);
    cudaGetSymbolAddress((void**)&pk,   g_k);
    cudaGetSymbolAddress((void**)&pv,   g_v);
    cudaGetSymbolAddress((void**)&ph,   g_h);
    cudaGetSymbolAddress((void**)&pctx, g_ctx);
    cudaGetSymbolAddress((void**)&pmid, g_mid);
    cudaGetSymbolAddress((void**)&wqh, g_wqt_h); cudaGetSymbolAddress((void**)&wql, g_wqt_l);
    cudaGetSymbolAddress((void**)&wkh, g_wkt_h); cudaGetSymbolAddress((void**)&wkl, g_wkt_l);
    cudaGetSymbolAddress((void**)&wvh, g_wvt_h); cudaGetSymbolAddress((void**)&wvl, g_wvt_l);
    cudaGetSymbolAddress((void**)&woh, g_wot_h); cudaGetSymbolAddress((void**)&wol, g_wot_l);
    cudaGetSymbolAddress((void**)&w1h, g_w1t_h); cudaGetSymbolAddress((void**)&w1l, g_w1t_l);
    cudaGetSymbolAddress((void**)&w2h, g_w2t_h); cudaGetSymbolAddress((void**)&w2l, g_w2t_l);

    cudaFuncSetAttribute(gemm_mma_kernel<0>, cudaFuncAttributeMaxDynamicSharedMemorySize, GSM_TOTAL);
    cudaFuncSetAttribute(gemm_mma_kernel<1>, cudaFuncAttributeMaxDynamicSharedMemorySize, GSM_TOTAL);
    cudaFuncSetAttribute(gemm_mma_kernel<2>, cudaFuncAttributeMaxDynamicSharedMemorySize, GSM_TOTAL);
    cudaFuncSetAttribute(attn_mma_kernel, cudaFuncAttributeMaxDynamicSharedMemorySize, ASM_TOTAL);

    {
        int n4 = SEQ * HID / 4;
        copy_kernel<<<(n4 + 255) / 256, 256>>>((const float4*)emb, (float4*)px, n4);
    }

    {
        dim3 b(32, 8);
        dim3 gHH(HID / 32, HID / 32);
        dim3 gW1(ISZ / 32, HID / 32);
        dim3 gW2(HID / 32, ISZ / 32);
        for (int l = 0; l < NLAYER; l++) {
            long oHH = (long)l * HID * HID, oHI = (long)l * HID * ISZ;
            wsplit_kernel<<<gHH, b>>>(Wq + oHH, wqh + oHH, wql + oHH, HID, HID);
            wsplit_kernel<<<gHH, b>>>(Wk + oHH, wkh + oHH, wkl + oHH, HID, HID);
            wsplit_kernel<<<gHH, b>>>(Wv + oHH, wvh + oHH, wvl + oHH, HID, HID);
            wsplit_kernel<<<gHH, b>>>(Wo + oHH, woh + oHH, wol + oHH, HID, HID);
            wsplit_kernel<<<gW1, b>>>(W1 + oHI, w1h + oHI, w1l + oHI, HID, ISZ);
            wsplit_kernel<<<gW2, b>>>(W2 + oHI, w2h + oHI, w2l + oHI, ISZ, HID);
        }
    }

    dim3 gQKV(HID / 128, SEQ / 128, 3);
    dim3 gHH(HID / 128, SEQ / 128, 1);
    dim3 gHI(ISZ / 128, SEQ / 128, 1);
    dim3 gAttn(SEQ / 128, NHEAD);

    for (int l = 0; l < NLAYER; l++) {
        long oHH = (long)l * HID * HID, oHI = (long)l * HID * ISZ;

        ln_kernel<1><<<SEQ, 256>>>(px, g1 + l * HID, nullptr, ph);
        gemm_mma_kernel<0><<<gQKV, 256, GSM_TOTAL>>>(ph,
            wqh + oHH, wql + oHH, wkh + oHH, wkl + oHH, wvh + oHH, wvl + oHH,
            nullptr, nullptr, pq, pk, pv, nullptr, SEQ, HID, HID);
        attn_mma_kernel<<<gAttn, 256, ASM_TOTAL>>>(pq, pk, pv, pctx);
        gemm_mma_kernel<1><<<gHH, 256, GSM_TOTAL>>>(pctx,
            woh + oHH, wol + oHH, nullptr, nullptr, nullptr, nullptr,
            bo + l * HID, px, px, nullptr, nullptr, nullptr, SEQ, HID, HID);

        ln_kernel<1><<<SEQ, 256>>>(px, g2 + l * HID, nullptr, ph);
        gemm_mma_kernel<2><<<gHI, 256, GSM_TOTAL>>>(ph,
            w1h + oHI, w1l + oHI, nullptr, nullptr, nullptr, nullptr,
            nullptr, nullptr, nullptr, nullptr, nullptr, pmid, SEQ, ISZ, HID);
        gemm_mma_kernel<1><<<gHH, 256, GSM_TOTAL>>>(pmid,
            w2h + oHI, w2l + oHI, nullptr, nullptr, nullptr, nullptr,
            b2 + l * HID, px, px, nullptr, nullptr, nullptr, SEQ, HID, ISZ);
    }

    ln_kernel<0><<<SEQ, 256>>>(px, gf, out, nullptr);
}

// round 9
// speedup vs baseline: 4.4205x; 1.0013x over previous
#include <cuda_runtime.h>
#include <cuda_fp16.h>
#include <cuda_bf16.h>
#include <math.h>
#include <stdint.h>

#define SEQ 2048
#define HID 2048
#define NHEAD 32
#define HDIM 64
#define ISZ 8192
#define NLAYER 2

// ======================= scratch (static device arrays) =======================
__device__ float g_x  [SEQ * HID];
__device__ float g_q  [SEQ * HID];
__device__ float g_k  [SEQ * HID];
__device__ float g_v  [SEQ * HID];
__device__ __half g_h  [SEQ * HID];
__device__ __half g_ctx[SEQ * HID];
__device__ __half g_mid[SEQ * ISZ];
__device__ __half g_wqt_h[NLAYER * HID * HID], g_wqt_l[NLAYER * HID * HID];
__device__ __half g_wkt_h[NLAYER * HID * HID], g_wkt_l[NLAYER * HID * HID];
__device__ __half g_wvt_h[NLAYER * HID * HID], g_wvt_l[NLAYER * HID * HID];
__device__ __half g_wot_h[NLAYER * HID * HID], g_wot_l[NLAYER * HID * HID];
__device__ __half g_w1t_h[NLAYER * HID * ISZ], g_w1t_l[NLAYER * HID * ISZ];
__device__ __half g_w2t_h[NLAYER * ISZ * HID], g_w2t_l[NLAYER * ISZ * HID];

// ======================= PTX helpers =======================
__device__ __forceinline__ uint32_t smem_u32(const void* p) {
    uint32_t a;
    asm("{ .reg .u64 t; cvta.to.shared.u64 t, %1; cvt.u32.u64 %0, t; }" : "=r"(a) : "l"(p));
    return a;
}
__device__ __forceinline__ void cp16(uint32_t dst, const void* src) {
    asm volatile("cp.async.cg.shared.global [%0], [%1], 16;" :: "r"(dst), "l"(src));
}
__device__ __forceinline__ void cp_commit() {
    asm volatile("cp.async.commit_group;" ::: "memory");
}
template <int N>
__device__ __forceinline__ void cp_wait() {
    asm volatile("cp.async.wait_group %0;" :: "n"(N) : "memory");
}
__device__ __forceinline__ void ldmx4(uint32_t* r, uint32_t addr) {
    asm volatile("ldmatrix.sync.aligned.m8n8.x4.shared.b16 {%0,%1,%2,%3}, [%4];"
                 : "=r"(r[0]), "=r"(r[1]), "=r"(r[2]), "=r"(r[3]) : "r"(addr));
}
__device__ __forceinline__ void ldmx4t(uint32_t* r, uint32_t addr) {
    asm volatile("ldmatrix.sync.aligned.m8n8.x4.trans.shared.b16 {%0,%1,%2,%3}, [%4];"
                 : "=r"(r[0]), "=r"(r[1]), "=r"(r[2]), "=r"(r[3]) : "r"(addr));
}
__device__ __forceinline__ void mma16816(float* d, const uint32_t* a, const uint32_t* b) {
    asm volatile("mma.sync.aligned.m16n8k16.row.col.f32.bf16.bf16.f32 "
                 "{%0,%1,%2,%3}, {%4,%5,%6,%7}, {%8,%9}, {%0,%1,%2,%3};"
                 : "+f"(d[0]), "+f"(d[1]), "+f"(d[2]), "+f"(d[3])
                 : "r"(a[0]), "r"(a[1]), "r"(a[2]), "r"(a[3]), "r"(b[0]), "r"(b[1]));
}
__device__ __forceinline__ void mma16816h(float* d, const uint32_t* a, const uint32_t* b) {
    asm volatile("mma.sync.aligned.m16n8k16.row.col.f32.f16.f16.f32 "
                 "{%0,%1,%2,%3}, {%4,%5,%6,%7}, {%8,%9}, {%0,%1,%2,%3};"
                 : "+f"(d[0]), "+f"(d[1]), "+f"(d[2]), "+f"(d[3])
                 : "r"(a[0]), "r"(a[1]), "r"(a[2]), "r"(a[3]), "r"(b[0]), "r"(b[1]));
}
__device__ __forceinline__ uint32_t packbf2(float lo, float hi) {
    __nv_bfloat162 t = __floats2bfloat162_rn(lo, hi);
    return *(uint32_t*)&t;
}
__device__ __forceinline__ uint32_t packh2(float lo, float hi) {
    __half2 t = __floats2half2_rn(lo, hi);
    return *(uint32_t*)&t;
}

// ======================= small kernels =======================
__global__ void copy_kernel(const float4* __restrict__ in, float4* __restrict__ out, int n4) {
    int i = blockIdx.x * 256 + threadIdx.x;
    if (i < n4) out[i] = in[i];
}

__device__ __forceinline__ float gelu_tanh(float v) {
    float t = 0.7978845608028654f * v * (1.0f + 0.044715f * v * v);
    return 0.5f * v * (1.0f + tanhf(t));
}

template <int HALF>
__global__ void __launch_bounds__(256) ln_kernel(const float* __restrict__ x,
                                                 const float* __restrict__ gamma,
                                                 float* __restrict__ outf,
                                                 __half* __restrict__ oh) {
    __shared__ float sh[18];
    int row = blockIdx.x;
    const float* xr = x + (long)row * HID;
    float s = 0.f, s2 = 0.f;
    for (int i = threadIdx.x; i < HID; i += 256) {
        float v = xr[i];
        s += v; s2 += v * v;
    }
    #pragma unroll
    for (int o = 16; o; o >>= 1) {
        s  += __shfl_xor_sync(0xFFFFFFFFu, s,  o);
        s2 += __shfl_xor_sync(0xFFFFFFFFu, s2, o);
    }
    int w = threadIdx.x >> 5, lane = threadIdx.x & 31;
    if (lane == 0) { sh[w] = s; sh[8 + w] = s2; }
    __syncthreads();
    if (threadIdx.x < 32) {
        s  = (threadIdx.x < 8) ? sh[threadIdx.x]     : 0.f;
        s2 = (threadIdx.x < 8) ? sh[8 + threadIdx.x] : 0.f;
        #pragma unroll
        for (int o = 4; o; o >>= 1) {
            s  += __shfl_xor_sync(0xFFFFFFFFu, s,  o);
            s2 += __shfl_xor_sync(0xFFFFFFFFu, s2, o);
        }
        if (threadIdx.x == 0) {
            float mu = s * (1.0f / HID);
            float var = s2 * (1.0f / HID) - mu * mu;
            sh[16] = mu;
            sh[17] = rsqrtf(var + 1e-5f);
        }
    }
    __syncthreads();
    float mu = sh[16], inv = sh[17];
    for (int i = threadIdx.x; i < HID; i += 256) {
        float v = (xr[i] - mu) * inv * gamma[i];
        if (HALF) oh[(long)row * HID + i] = __float2half(v);
        else      outf[(long)row * HID + i] = v;
    }
}

__global__ void __launch_bounds__(256) wsplit_kernel(const float* __restrict__ W,
                                                     __half* __restrict__ Th,
                                                     __half* __restrict__ Tl,
                                                     int K, int N) {
    __shared__ float t[32][33];
    int bx = blockIdx.x * 32, by = blockIdx.y * 32;
    int tx = threadIdx.x, ty = threadIdx.y;
    #pragma unroll
    for (int i = 0; i < 4; i++)
        t[ty + i * 8][tx] = W[(long)(by + ty + i * 8) * N + bx + tx];
    __syncthreads();
    #pragma unroll
    for (int i = 0; i < 4; i++) {
        float v = t[tx][ty + i * 8];
        __half h = __float2half(v);
        long o = (long)(bx + ty + i * 8) * K + by + tx;
        Th[o] = h;
        Tl[o] = __float2half(v - __half2float(h));
    }
}

// ======================= persistent mma.sync fp16 GEMM (4-stage pipeline) =======================
// C[M,N] = A[M,K] @ (Bh+Bl)^T, B stored [N,K] row-major fp16 hi/lo.
// BM=128, BN=128, BK=32; 8 warps, warp tile 64x32; 4-stage cp.async (96KB), 2 CTA/SM.
// Persistent: grid = min(ntiles, 296); each CTA loops over flattened (z, by, bx) tiles.
#define A_TILE 8192
#define B_TILE 16384
#define STAGE_BYTES (A_TILE + B_TILE)
#define NSTAGE 4
#define GSM_TOTAL (NSTAGE * STAGE_BYTES)
#define PERSIST_GRID 296

__device__ __forceinline__ void load_A_tile(uint32_t sbase, const __half* __restrict__ A,
                                            int K, long k0, int tid) {
    #pragma unroll
    for (int i = 0; i < 2; i++) {
        int idx = tid + i * 256;
        int row = idx >> 2, c = idx & 3;
        const __half* src = A + (long)row * K + k0 + c * 8;
        uint32_t dst = sbase + row * 64 + ((c ^ ((row >> 1) & 3)) << 4);
        cp16(dst, src);
    }
}
__device__ __forceinline__ void load_B_tile(uint32_t sbase,
                                            const __half* __restrict__ Ph,
                                            const __half* __restrict__ Pl,
                                            int K, long k0, int tid) {
    #pragma unroll
    for (int i = 0; i < 4; i++) {
        int idx = tid + i * 256;
        int row = idx >> 3, c = idx & 7;
        const __half* src = (c < 4 ? Ph : Pl) + (long)row * K + k0 + (c & 3) * 8;
        uint32_t dst = sbase + row * 128 + ((c ^ (row & 7)) << 4);
        cp16(dst, src);
    }
}

template <int MODE>
__global__ void __launch_bounds__(256, 2) gemm_mma_kernel(
    const __half* __restrict__ A,
    const __half* __restrict__ Bh0, const __half* __restrict__ Bl0,
    const __half* __restrict__ Bh1, const __half* __restrict__ Bl1,
    const __half* __restrict__ Bh2, const __half* __restrict__ Bl2,
    const float* __restrict__ bias, const float* res,
    float* Cf0, float* Cf1, float* Cf2,
    __half* __restrict__ Ch,
    int M, int N, int K, int ntx, int nty, int ntz)
{
    extern __shared__ char smem[];
    uint32_t sb = smem_u32(smem);
    int tid = threadIdx.x;
    int wid = tid >> 5, lane = tid & 31;
    int warp_m = wid >> 2, warp_n = wid & 3;
    int m0 = warp_m * 64, n0 = warp_n * 32;

    int grp = lane >> 3, lr = lane & 7;
    int rowA0 = m0 + (grp & 1) * 8 + lr;
    int ccA   = grp >> 1;
    int rowB0 = n0 + (grp >> 1) * 8 + lr;
    int ccB   = grp & 1;
    int xB = rowB0 & 7;
    int nc = K / 32;
    int ntot = ntx * nty * ntz;

    for (int t = blockIdx.x; t < ntot; t += gridDim.x) {
        int z   = t / (ntx * nty);
        int rem = t - z * (ntx * nty);
        int by  = rem / ntx;
        int bx  = rem - by * ntx;
        int row0 = by * 128, col0 = bx * 128;

        const __half* Bh = (z == 0) ? Bh0 : (z == 1) ? Bh1 : Bh2;
        const __half* Bl = (z == 0) ? Bl0 : (z == 1) ? Bl1 : Bl2;
        float* Cf = (z == 0) ? Cf0 : (z == 1) ? Cf1 : Cf2;

        const __half* pA  = A  + (long)row0 * K;
        const __half* pBh = Bh + (long)col0 * K;
        const __half* pBl = Bl + (long)col0 * K;

        float acc[4][4][4];
        #pragma unroll
        for (int i = 0; i < 4; i++)
            #pragma unroll
            for (int j = 0; j < 4; j++)
                #pragma unroll
                for (int q = 0; q < 4; q++) acc[i][j][q] = 0.f;

        __syncthreads();   // previous tile's stragglers done reading smem

        // prologue: stages 0, 1, 2
        #pragma unroll
        for (int p = 0; p < 3; p++) {
            uint32_t st = sb + p * STAGE_BYTES;
            load_A_tile(st,          pA,       K, (long)p * 32, tid);
            load_B_tile(st + A_TILE, pBh, pBl, K, (long)p * 32, tid);
            cp_commit();
        }

        int s_comp = 0, s_load = 3;
        for (int c = 0; c < nc; c++) {
            cp_wait<2>();
            __syncthreads();
            if (c + 3 < nc) {
                uint32_t st = sb + s_load * STAGE_BYTES;
                long k0 = (long)(c + 3) * 32;
                load_A_tile(st,          pA,       K, k0, tid);
                load_B_tile(st + A_TILE, pBh, pBl, K, k0, tid);
            }
            cp_commit();

            uint32_t sA = sb + s_comp * STAGE_BYTES;
            uint32_t sB = sA + A_TILE;
            #pragma unroll
            for (int ks = 0; ks < 2; ks++) {
                uint32_t af[4][4], bfh[2][4], bfl[2][4];
                #pragma unroll
                for (int mt = 0; mt < 4; mt++) {
                    int ra = rowA0 + mt * 16;
                    uint32_t base = sA + ra * 64;
                    ldmx4(af[mt], base + (((ks * 2 + ccA) ^ ((ra >> 1) & 3)) << 4));
                }
                #pragma unroll
                for (int np = 0; np < 2; np++) {
                    uint32_t base = sB + (rowB0 + np * 16) * 128;
                    ldmx4(bfh[np], base + (((ks * 2 + ccB)     ^ xB) << 4));
                    ldmx4(bfl[np], base + (((ks * 2 + ccB + 4) ^ xB) << 4));
                }
                #pragma unroll
                for (int mt = 0; mt < 4; mt++)
                    #pragma unroll
                    for (int nt = 0; nt < 4; nt++) {
                        const uint32_t* bh = &bfh[nt >> 1][(nt & 1) * 2];
                        const uint32_t* bl = &bfl[nt >> 1][(nt & 1) * 2];
                        mma16816h(acc[mt][nt], af[mt], bh);
                        mma16816h(acc[mt][nt], af[mt], bl);
                    }
            }
            s_comp = (s_comp + 1) & 3;
            s_load = (s_load + 1) & 3;
        }

        int r = lane >> 2, c2 = (lane & 3) * 2;
        #pragma unroll
        for (int mt = 0; mt < 4; mt++) {
            #pragma unroll
            for (int nt = 0; nt < 4; nt++) {
                long gr = row0 + m0 + mt * 16 + r;
                long gc = col0 + n0 + nt * 8 + c2;
                #pragma unroll
                for (int hrow = 0; hrow < 2; hrow++) {
                    long grr = gr + hrow * 8;
                    float v0 = acc[mt][nt][hrow * 2 + 0];
                    float v1 = acc[mt][nt][hrow * 2 + 1];
                    if (MODE == 0) {
                        *(float2*)(Cf + grr * N + gc) = make_float2(v0, v1);
                    } else if (MODE == 1) {
                        float2 b = *(const float2*)(bias + gc);
                        float2 rr = *(const float2*)(res + grr * N + gc);
                        *(float2*)(Cf + grr * N + gc) = make_float2(v0 + b.x + rr.x, v1 + b.y + rr.y);
                    } else {
                        *(uint32_t*)(Ch + grr * N + gc) = packh2(gelu_tanh(v0), gelu_tanh(v1));
                    }
                }
            }
        }
    }
}

// ======================= tensor-core flash attention (split-bf16, fp16 out) =======================
#define ASM_QH 0
#define ASM_QL 16384
#define ASM_KH 32768
#define ASM_KL 49152
#define ASM_VH 65536
#define ASM_VL 81920
#define ASM_KF 98304
#define ASM_VF 133120
#define ASM_TOTAL 167936

__device__ __forceinline__ void cvt_tile(uint32_t fbase, uint32_t hbase, uint32_t lbase, int tid) {
    int row = tid >> 1, half = tid & 1;
    uint32_t fr = fbase + row * 272;
    uint32_t hr = hbase + row * 128;
    uint32_t lr_ = lbase + row * 128;
    #pragma unroll
    for (int j = 0; j < 4; j++) {
        float4 f0, f1;
        asm volatile("ld.shared.v4.f32 {%0,%1,%2,%3}, [%4];"
                     : "=f"(f0.x), "=f"(f0.y), "=f"(f0.z), "=f"(f0.w)
                     : "r"(fr + (half * 8 + j * 2) * 16));
        asm volatile("ld.shared.v4.f32 {%0,%1,%2,%3}, [%4];"
                     : "=f"(f1.x), "=f"(f1.y), "=f"(f1.z), "=f"(f1.w)
                     : "r"(fr + (half * 8 + j * 2 + 1) * 16));
        float v[8] = {f0.x, f0.y, f0.z, f0.w, f1.x, f1.y, f1.z, f1.w};
        uint32_t hi[4], lo[4];
        #pragma unroll
        for (int q = 0; q < 4; q++) {
            float a = v[q * 2], b = v[q * 2 + 1];
            float ha = __bfloat162float(__float2bfloat16(a));
            float hb = __bfloat162float(__float2bfloat16(b));
            hi[q] = packbf2(ha, hb);
            lo[q] = packbf2(a - ha, b - hb);
        }
        int c = half * 4 + j;
        uint32_t sw = (uint32_t)((c ^ (row & 7)) << 4);
        asm volatile("st.shared.v4.b32 [%0], {%1,%2,%3,%4};"
                     :: "r"(hr + sw), "r"(hi[0]), "r"(hi[1]), "r"(hi[2]), "r"(hi[3]));
        asm volatile("st.shared.v4.b32 [%0], {%1,%2,%3,%4};"
                     :: "r"(lr_ + sw), "r"(lo[0]), "r"(lo[1]), "r"(lo[2]), "r"(lo[3]));
    }
}

__device__ __forceinline__ void stage_cp(uint32_t fbase, const float* __restrict__ src,
                                         int keyrow0, int h, int tid) {
    #pragma unroll
    for (int i = 0; i < 8; i++) {
        int idx = tid + i * 256;
        int r = idx >> 4, c = idx & 15;
        cp16(fbase + r * 272 + c * 16, src + (long)(keyrow0 + r) * HID + h * HDIM + c * 4);
    }
}

__global__ void __launch_bounds__(256) attn_mma_kernel(
    const float* __restrict__ Q, const float* __restrict__ K,
    const float* __restrict__ V, __half* __restrict__ O)
{
    extern __shared__ char smem[];
    uint32_t sb = smem_u32(smem);
    int tid = threadIdx.x;
    int w = tid >> 5, lane = tid & 31;
    int qb = blockIdx.x, h = blockIdx.y;

    int grp = lane >> 3, lr = lane & 7;
    int rowQ = w * 16 + (grp & 1) * 8 + lr;
    int ccQ  = grp >> 1;
    int xQ = rowQ & 7;
    int rowK_off = (grp >> 1) * 8 + lr;
    int ccK  = grp & 1;
    int rowV_off = (grp & 1) * 8 + lr;
    int ccV_off  = grp >> 1;

    {
        int row = tid >> 1, half = tid & 1;
        const float* src = Q + (long)(qb * 128 + row) * HID + h * HDIM + half * 32;
        uint32_t hr = sb + ASM_QH + row * 128;
        uint32_t lr2 = sb + ASM_QL + row * 128;
        #pragma unroll
        for (int j = 0; j < 4; j++) {
            float4 f0 = *(const float4*)(src + j * 8);
            float4 f1 = *(const float4*)(src + j * 8 + 4);
            float v[8] = {f0.x, f0.y, f0.z, f0.w, f1.x, f1.y, f1.z, f1.w};
            uint32_t hi[4], lo[4];
            #pragma unroll
            for (int q = 0; q < 4; q++) {
                float a = v[q * 2] * 0.125f, b = v[q * 2 + 1] * 0.125f;
                float ha = __bfloat162float(__float2bfloat16(a));
                float hb = __bfloat162float(__float2bfloat16(b));
                hi[q] = packbf2(ha, hb);
                lo[q] = packbf2(a - ha, b - hb);
            }
            int c = half * 4 + j;
            uint32_t sw = (uint32_t)((c ^ (row & 7)) << 4);
            asm volatile("st.shared.v4.b32 [%0], {%1,%2,%3,%4};"
                         :: "r"(hr + sw), "r"(hi[0]), "r"(hi[1]), "r"(hi[2]), "r"(hi[3]));
            asm volatile("st.shared.v4.b32 [%0], {%1,%2,%3,%4};"
                         :: "r"(lr2 + sw), "r"(lo[0]), "r"(lo[1]), "r"(lo[2]), "r"(lo[3]));
        }
    }
    stage_cp(sb + ASM_KF, K, 0, h, tid);
    stage_cp(sb + ASM_VF, V, 0, h, tid);
    cp_commit();
    __syncthreads();

    uint32_t qfh[4][4], qfl[4][4];
    #pragma unroll
    for (int ks = 0; ks < 4; ks++) {
        uint32_t base = sb + rowQ * 128;
        ldmx4(qfh[ks], base + ASM_QH + (((ks * 2 + ccQ) ^ xQ) << 4));
        ldmx4(qfl[ks], base + ASM_QL + (((ks * 2 + ccQ) ^ xQ) << 4));
    }

    float oacc[8][4];
    #pragma unroll
    for (int i = 0; i < 8; i++)
        #pragma unroll
        for (int q = 0; q < 4; q++) oacc[i][q] = 0.f;
    float m0 = -1e30f, m1 = -1e30f, l0 = 0.f, l1 = 0.f;

    int qg0 = qb * 128 + w * 16 + (lane >> 2);
    int qg1 = qg0 + 8;

    for (int kt = 0; kt <= qb; kt++) {
        cp_wait<0>();
        __syncthreads();
        cvt_tile(sb + ASM_KF, sb + ASM_KH, sb + ASM_KL, tid);
        cvt_tile(sb + ASM_VF, sb + ASM_VH, sb + ASM_VL, tid);
        __syncthreads();
        if (kt < qb) {
            stage_cp(sb + ASM_KF, K, (kt + 1) * 128, h, tid);
            stage_cp(sb + ASM_VF, V, (kt + 1) * 128, h, tid);
        }
        cp_commit();

        float sacc[16][4];
        #pragma unroll
        for (int i = 0; i < 16; i++)
            #pragma unroll
            for (int q = 0; q < 4; q++) sacc[i][q] = 0.f;

        #pragma unroll
        for (int ks = 0; ks < 4; ks++) {
            #pragma unroll
            for (int nb = 0; nb < 8; nb++) {
                int rowK = nb * 16 + rowK_off;
                uint32_t base = sb + rowK * 128;
                uint32_t off = (uint32_t)(((ks * 2 + ccK) ^ (rowK & 7)) << 4);
                uint32_t bkh[4], bkl[4];
                ldmx4(bkh, base + ASM_KH + off);
                ldmx4(bkl, base + ASM_KL + off);
                #pragma unroll
                for (int sub = 0; sub < 2; sub++) {
                    float* d = sacc[nb * 2 + sub];
                    mma16816(d, qfh[ks], &bkh[sub * 2]);
                    mma16816(d, qfh[ks], &bkl[sub * 2]);
                    mma16816(d, qfl[ks], &bkh[sub * 2]);
                }
            }
        }

        if (kt == qb) {
            #pragma unroll
            for (int nt = 0; nt < 16; nt++) {
                int kg = kt * 128 + nt * 8 + 2 * (lane & 3);
                #pragma unroll
                for (int e = 0; e < 2; e++) {
                    if (kg + e > qg0) sacc[nt][e]     = -1e30f;
                    if (kg + e > qg1) sacc[nt][2 + e] = -1e30f;
                }
            }
        }

        float rm0 = -1e30f, rm1 = -1e30f;
        #pragma unroll
        for (int nt = 0; nt < 16; nt++) {
            rm0 = fmaxf(rm0, fmaxf(sacc[nt][0], sacc[nt][1]));
            rm1 = fmaxf(rm1, fmaxf(sacc[nt][2], sacc[nt][3]));
        }
        rm0 = fmaxf(rm0, __shfl_xor_sync(0xFFFFFFFFu, rm0, 1));
        rm0 = fmaxf(rm0, __shfl_xor_sync(0xFFFFFFFFu, rm0, 2));
        rm1 = fmaxf(rm1, __shfl_xor_sync(0xFFFFFFFFu, rm1, 1));
        rm1 = fmaxf(rm1, __shfl_xor_sync(0xFFFFFFFFu, rm1, 2));
        float mn0 = fmaxf(m0, rm0), mn1 = fmaxf(m1, rm1);
        float al0 = __expf(m0 - mn0), al1 = __expf(m1 - mn1);
        m0 = mn0; m1 = mn1;

        float rs0 = 0.f, rs1 = 0.f;
        #pragma unroll
        for (int nt = 0; nt < 16; nt++) {
            sacc[nt][0] = __expf(sacc[nt][0] - mn0);
            sacc[nt][1] = __expf(sacc[nt][1] - mn0);
            sacc[nt][2] = __expf(sacc[nt][2] - mn1);
            sacc[nt][3] = __expf(sacc[nt][3] - mn1);
            rs0 += sacc[nt][0] + sacc[nt][1];
            rs1 += sacc[nt][2] + sacc[nt][3];
        }
        rs0 += __shfl_xor_sync(0xFFFFFFFFu, rs0, 1);
        rs0 += __shfl_xor_sync(0xFFFFFFFFu, rs0, 2);
        rs1 += __shfl_xor_sync(0xFFFFFFFFu, rs1, 1);
        rs1 += __shfl_xor_sync(0xFFFFFFFFu, rs1, 2);
        l0 = l0 * al0 + rs0;
        l1 = l1 * al1 + rs1;

        #pragma unroll
        for (int i = 0; i < 8; i++) {
            oacc[i][0] *= al0; oacc[i][1] *= al0;
            oacc[i][2] *= al1; oacc[i][3] *= al1;
        }

        #pragma unroll
        for (int ks2 = 0; ks2 < 8; ks2++) {
            uint32_t ah[4], al[4];
            {
                float p00 = sacc[2 * ks2][0],     p01 = sacc[2 * ks2][1];
                float p10 = sacc[2 * ks2][2],     p11 = sacc[2 * ks2][3];
                float p20 = sacc[2 * ks2 + 1][0], p21 = sacc[2 * ks2 + 1][1];
                float p30 = sacc[2 * ks2 + 1][2], p31 = sacc[2 * ks2 + 1][3];
                float h00 = __bfloat162float(__float2bfloat16(p00));
                float h01 = __bfloat162float(__float2bfloat16(p01));
                float h10 = __bfloat162float(__float2bfloat16(p10));
                float h11 = __bfloat162float(__float2bfloat16(p11));
                float h20 = __bfloat162float(__float2bfloat16(p20));
                float h21 = __bfloat162float(__float2bfloat16(p21));
                float h30 = __bfloat162float(__float2bfloat16(p30));
                float h31 = __bfloat162float(__float2bfloat16(p31));
                ah[0] = packbf2(h00, h01); ah[1] = packbf2(h10, h11);
                ah[2] = packbf2(h20, h21); ah[3] = packbf2(h30, h31);
                al[0] = packbf2(p00 - h00, p01 - h01);
                al[1] = packbf2(p10 - h10, p11 - h11);
                al[2] = packbf2(p20 - h20, p21 - h21);
                al[3] = packbf2(p30 - h30, p31 - h31);
            }
            #pragma unroll
            for (int db = 0; db < 4; db++) {
                int rowV = ks2 * 16 + rowV_off;
                int cc = db * 2 + ccV_off;
                uint32_t base = sb + rowV * 128;
                uint32_t off = (uint32_t)((cc ^ (rowV & 7)) << 4);
                uint32_t bvh[4], bvl[4];
                ldmx4t(bvh, base + ASM_VH + off);
                ldmx4t(bvl, base + ASM_VL + off);
                #pragma unroll
                for (int sub = 0; sub < 2; sub++) {
                    float* d = oacc[db * 2 + sub];
                    mma16816(d, ah, &bvh[sub * 2]);
                    mma16816(d, al, &bvh[sub * 2]);
                    mma16816(d, ah, &bvl[sub * 2]);
                }
            }
        }
    }

    float i0 = 1.0f / l0, i1 = 1.0f / l1;
    long gr0 = qb * 128 + w * 16 + (lane >> 2);
    long gc0 = h * HDIM + 2 * (lane & 3);
    #pragma unroll
    for (int nto = 0; nto < 8; nto++) {
        long gc = gc0 + nto * 8;
        *(uint32_t*)(O + gr0 * HID + gc)       = packh2(oacc[nto][0] * i0, oacc[nto][1] * i0);
        *(uint32_t*)(O + (gr0 + 8) * HID + gc) = packh2(oacc[nto][2] * i1, oacc[nto][3] * i1);
    }
}

// ======================= orchestration =======================
extern "C" void kernel_launch(void* const* d_in, const int* in_sizes, int n_in,
                              void* d_out, int out_size) {
    const float* emb = (const float*)d_in[0];
    const float* Wq = (const float*)d_in[2];
    const float* Wk = (const float*)d_in[3];
    const float* Wv = (const float*)d_in[4];
    const float* Wo = (const float*)d_in[5];
    const float* bo = (const float*)d_in[6];
    const float* W1 = (const float*)d_in[7];
    const float* W2 = (const float*)d_in[8];
    const float* b2 = (const float*)d_in[9];
    const float* g1 = (const float*)d_in[10];
    const float* g2 = (const float*)d_in[11];
    const float* gf = (const float*)d_in[12];
    float* out = (float*)d_out;

    float *px, *pq, *pk, *pv;
    __half *ph, *pctx, *pmid;
    __half *wqh, *wql, *wkh, *wkl, *wvh, *wvl, *woh, *wol, *w1h, *w1l, *w2h, *w2l;
    cudaGetSymbolAddress((void**)&px,   g_x);
    cudaGetSymbolAddress((void**)&pq,   g_q);
    cudaGetSymbolAddress((void**)&pk,   g_k);
    cudaGetSymbolAddress((void**)&pv,   g_v);
    cudaGetSymbolAddress((void**)&ph,   g_h);
    cudaGetSymbolAddress((void**)&pctx, g_ctx);
    cudaGetSymbolAddress((void**)&pmid, g_mid);
    cudaGetSymbolAddress((void**)&wqh, g_wqt_h); cudaGetSymbolAddress((void**)&wql, g_wqt_l);
    cudaGetSymbolAddress((void**)&wkh, g_wkt_h); cudaGetSymbolAddress((void**)&wkl, g_wkt_l);
    cudaGetSymbolAddress((void**)&wvh, g_wvt_h); cudaGetSymbolAddress((void**)&wvl, g_wvt_l);
    cudaGetSymbolAddress((void**)&woh, g_wot_h); cudaGetSymbolAddress((void**)&wol, g_wot_l);
    cudaGetSymbolAddress((void**)&w1h, g_w1t_h); cudaGetSymbolAddress((void**)&w1l, g_w1t_l);
    cudaGetSymbolAddress((void**)&w2h, g_w2t_h); cudaGetSymbolAddress((void**)&w2l, g_w2t_l);

    cudaFuncSetAttribute(gemm_mma_kernel<0>, cudaFuncAttributeMaxDynamicSharedMemorySize, GSM_TOTAL);
    cudaFuncSetAttribute(gemm_mma_kernel<1>, cudaFuncAttributeMaxDynamicSharedMemorySize, GSM_TOTAL);
    cudaFuncSetAttribute(gemm_mma_kernel<2>, cudaFuncAttributeMaxDynamicSharedMemorySize, GSM_TOTAL);
    cudaFuncSetAttribute(attn_mma_kernel, cudaFuncAttributeMaxDynamicSharedMemorySize, ASM_TOTAL);

    {
        int n4 = SEQ * HID / 4;
        copy_kernel<<<(n4 + 255) / 256, 256>>>((const float4*)emb, (float4*)px, n4);
    }

    {
        dim3 b(32, 8);
        dim3 gHH(HID / 32, HID / 32);
        dim3 gW1(ISZ / 32, HID / 32);
        dim3 gW2(HID / 32, ISZ / 32);
        for (int l = 0; l < NLAYER; l++) {
            long oHH = (long)l * HID * HID, oHI = (long)l * HID * ISZ;
            wsplit_kernel<<<gHH, b>>>(Wq + oHH, wqh + oHH, wql + oHH, HID, HID);
            wsplit_kernel<<<gHH, b>>>(Wk + oHH, wkh + oHH, wkl + oHH, HID, HID);
            wsplit_kernel<<<gHH, b>>>(Wv + oHH, wvh + oHH, wvl + oHH, HID, HID);
            wsplit_kernel<<<gHH, b>>>(Wo + oHH, woh + oHH, wol + oHH, HID, HID);
            wsplit_kernel<<<gW1, b>>>(W1 + oHI, w1h + oHI, w1l + oHI, HID, ISZ);
            wsplit_kernel<<<gW2, b>>>(W2 + oHI, w2h + oHI, w2l + oHI, ISZ, HID);
        }
    }

    dim3 gAttn(SEQ / 128, NHEAD);
    const int ntHH = (HID / 128) * (SEQ / 128);          // 256
    const int ntQKV = ntHH * 3;                          // 768
    const int ntHI = (ISZ / 128) * (SEQ / 128);          // 1024
    int gQKV = ntQKV < PERSIST_GRID ? ntQKV : PERSIST_GRID;
    int gHH  = ntHH  < PERSIST_GRID ? ntHH  : PERSIST_GRID;
    int gHI  = ntHI  < PERSIST_GRID ? ntHI  : PERSIST_GRID;

    for (int l = 0; l < NLAYER; l++) {
        long oHH = (long)l * HID * HID, oHI = (long)l * HID * ISZ;

        ln_kernel<1><<<SEQ, 256>>>(px, g1 + l * HID, nullptr, ph);
        gemm_mma_kernel<0><<<gQKV, 256, GSM_TOTAL>>>(ph,
            wqh + oHH, wql + oHH, wkh + oHH, wkl + oHH, wvh + oHH, wvl + oHH,
            nullptr, nullptr, pq, pk, pv, nullptr,
            SEQ, HID, HID, HID / 128, SEQ / 128, 3);
        attn_mma_kernel<<<gAttn, 256, ASM_TOTAL>>>(pq, pk, pv, pctx);
        gemm_mma_kernel<1><<<gHH, 256, GSM_TOTAL>>>(pctx,
            woh + oHH, wol + oHH, nullptr, nullptr, nullptr, nullptr,
            bo + l * HID, px, px, nullptr, nullptr, nullptr,
            SEQ, HID, HID, HID / 128, SEQ / 128, 1);

        ln_kernel<1><<<SEQ, 256>>>(px, g2 + l * HID, nullptr, ph);
        gemm_mma_kernel<2><<<gHI, 256, GSM_TOTAL>>>(ph,
            w1h + oHI, w1l + oHI, nullptr, nullptr, nullptr, nullptr,
            nullptr, nullptr, nullptr, nullptr, nullptr, pmid,
            SEQ, ISZ, HID, ISZ / 128, SEQ / 128, 1);
        gemm_mma_kernel<1><<<gHH, 256, GSM_TOTAL>>>(pmid,
            w2h + oHI, w2l + oHI, nullptr, nullptr, nullptr, nullptr,
            b2 + l * HID, px, px, nullptr, nullptr, nullptr,
            SEQ, HID, ISZ, HID / 128, SEQ / 128, 1);
    }

    ln_kernel<0><<<SEQ, 256>>>(px, gf, out, nullptr);
}

// round 10
// speedup vs baseline: 6.8310x; 1.5453x over previous
#include <cuda_runtime.h>
#include <cuda_fp16.h>
#include <cuda_bf16.h>
#include <math.h>
#include <stdint.h>

#define SEQ 2048
#define HID 2048
#define NHEAD 32
#define HDIM 64
#define ISZ 8192
#define NLAYER 2

// ======================= scratch (static device arrays) =======================
__device__ float g_x  [SEQ * HID];
__device__ float g_q  [SEQ * HID];
__device__ float g_k  [SEQ * HID];
__device__ float g_v  [SEQ * HID];
__device__ __half g_h  [SEQ * HID];
__device__ __half g_ctx[SEQ * HID];
__device__ __half g_mid[SEQ * ISZ];
// transposed weights: Wt[N][K], plain fp16
__device__ __half g_wqt[NLAYER * HID * HID];
__device__ __half g_wkt[NLAYER * HID * HID];
__device__ __half g_wvt[NLAYER * HID * HID];
__device__ __half g_wot[NLAYER * HID * HID];
__device__ __half g_w1t[NLAYER * HID * ISZ];
__device__ __half g_w2t[NLAYER * ISZ * HID];

// ======================= PTX helpers =======================
__device__ __forceinline__ uint32_t smem_u32(const void* p) {
    uint32_t a;
    asm("{ .reg .u64 t; cvta.to.shared.u64 t, %1; cvt.u32.u64 %0, t; }" : "=r"(a) : "l"(p));
    return a;
}
__device__ __forceinline__ void cp16(uint32_t dst, const void* src) {
    asm volatile("cp.async.cg.shared.global [%0], [%1], 16;" :: "r"(dst), "l"(src));
}
__device__ __forceinline__ void cp_commit() {
    asm volatile("cp.async.commit_group;" ::: "memory");
}
template <int N>
__device__ __forceinline__ void cp_wait() {
    asm volatile("cp.async.wait_group %0;" :: "n"(N) : "memory");
}
__device__ __forceinline__ void ldmx4(uint32_t* r, uint32_t addr) {
    asm volatile("ldmatrix.sync.aligned.m8n8.x4.shared.b16 {%0,%1,%2,%3}, [%4];"
                 : "=r"(r[0]), "=r"(r[1]), "=r"(r[2]), "=r"(r[3]) : "r"(addr));
}
__device__ __forceinline__ void ldmx4t(uint32_t* r, uint32_t addr) {
    asm volatile("ldmatrix.sync.aligned.m8n8.x4.trans.shared.b16 {%0,%1,%2,%3}, [%4];"
                 : "=r"(r[0]), "=r"(r[1]), "=r"(r[2]), "=r"(r[3]) : "r"(addr));
}
__device__ __forceinline__ void mma16816(float* d, const uint32_t* a, const uint32_t* b) {
    asm volatile("mma.sync.aligned.m16n8k16.row.col.f32.bf16.bf16.f32 "
                 "{%0,%1,%2,%3}, {%4,%5,%6,%7}, {%8,%9}, {%0,%1,%2,%3};"
                 : "+f"(d[0]), "+f"(d[1]), "+f"(d[2]), "+f"(d[3])
                 : "r"(a[0]), "r"(a[1]), "r"(a[2]), "r"(a[3]), "r"(b[0]), "r"(b[1]));
}
__device__ __forceinline__ void mma16816h(float* d, const uint32_t* a, const uint32_t* b) {
    asm volatile("mma.sync.aligned.m16n8k16.row.col.f32.f16.f16.f32 "
                 "{%0,%1,%2,%3}, {%4,%5,%6,%7}, {%8,%9}, {%0,%1,%2,%3};"
                 : "+f"(d[0]), "+f"(d[1]), "+f"(d[2]), "+f"(d[3])
                 : "r"(a[0]), "r"(a[1]), "r"(a[2]), "r"(a[3]), "r"(b[0]), "r"(b[1]));
}
__device__ __forceinline__ uint32_t packbf2(float lo, float hi) {
    __nv_bfloat162 t = __floats2bfloat162_rn(lo, hi);
    return *(uint32_t*)&t;
}
__device__ __forceinline__ uint32_t packh2(float lo, float hi) {
    __half2 t = __floats2half2_rn(lo, hi);
    return *(uint32_t*)&t;
}

// ======================= small kernels =======================
__global__ void copy_kernel(const float4* __restrict__ in, float4* __restrict__ out, int n4) {
    int i = blockIdx.x * 256 + threadIdx.x;
    if (i < n4) out[i] = in[i];
}

__device__ __forceinline__ float gelu_tanh(float v) {
    float t = 0.7978845608028654f * v * (1.0f + 0.044715f * v * v);
    return 0.5f * v * (1.0f + tanhf(t));
}

template <int HALF>
__global__ void __launch_bounds__(256) ln_kernel(const float* __restrict__ x,
                                                 const float* __restrict__ gamma,
                                                 float* __restrict__ outf,
                                                 __half* __restrict__ oh) {
    __shared__ float sh[18];
    int row = blockIdx.x;
    const float* xr = x + (long)row * HID;
    float s = 0.f, s2 = 0.f;
    for (int i = threadIdx.x; i < HID; i += 256) {
        float v = xr[i];
        s += v; s2 += v * v;
    }
    #pragma unroll
    for (int o = 16; o; o >>= 1) {
        s  += __shfl_xor_sync(0xFFFFFFFFu, s,  o);
        s2 += __shfl_xor_sync(0xFFFFFFFFu, s2, o);
    }
    int w = threadIdx.x >> 5, lane = threadIdx.x & 31;
    if (lane == 0) { sh[w] = s; sh[8 + w] = s2; }
    __syncthreads();
    if (threadIdx.x < 32) {
        s  = (threadIdx.x < 8) ? sh[threadIdx.x]     : 0.f;
        s2 = (threadIdx.x < 8) ? sh[8 + threadIdx.x] : 0.f;
        #pragma unroll
        for (int o = 4; o; o >>= 1) {
            s  += __shfl_xor_sync(0xFFFFFFFFu, s,  o);
            s2 += __shfl_xor_sync(0xFFFFFFFFu, s2, o);
        }
        if (threadIdx.x == 0) {
            float mu = s * (1.0f / HID);
            float var = s2 * (1.0f / HID) - mu * mu;
            sh[16] = mu;
            sh[17] = rsqrtf(var + 1e-5f);
        }
    }
    __syncthreads();
    float mu = sh[16], inv = sh[17];
    for (int i = threadIdx.x; i < HID; i += 256) {
        float v = (xr[i] - mu) * inv * gamma[i];
        if (HALF) oh[(long)row * HID + i] = __float2half(v);
        else      outf[(long)row * HID + i] = v;
    }
}

// weight transpose: W[K,N] fp32 -> Th[N,K] fp16
__global__ void __launch_bounds__(256) wsplit_kernel(const float* __restrict__ W,
                                                     __half* __restrict__ Th,
                                                     int K, int N) {
    __shared__ float t[32][33];
    int bx = blockIdx.x * 32, by = blockIdx.y * 32;
    int tx = threadIdx.x, ty = threadIdx.y;
    #pragma unroll
    for (int i = 0; i < 4; i++)
        t[ty + i * 8][tx] = W[(long)(by + ty + i * 8) * N + bx + tx];
    __syncthreads();
    #pragma unroll
    for (int i = 0; i < 4; i++) {
        float v = t[tx][ty + i * 8];
        Th[(long)(bx + ty + i * 8) * K + by + tx] = __float2half(v);
    }
}

// ======================= persistent mma.sync fp16 GEMM (plain x plain, 1 mma/tile) =======================
// C[M,N] = A[M,K] @ B^T, B stored [N,K] row-major fp16.
// BM=128, BN=128, BK=32; 8 warps, warp tile 64x32; 4-stage cp.async (64KB), 2 CTA/SM.
// A/B smem tiles identical: 128 rows x 64B (4 chunks of 16B), phys_chunk = c ^ ((row>>1)&3).
#define T_TILE 8192
#define STAGE_BYTES (2 * T_TILE)
#define NSTAGE 4
#define GSM_TOTAL (NSTAGE * STAGE_BYTES)
#define PERSIST_GRID 296

__device__ __forceinline__ void load_tile64(uint32_t sbase, const __half* __restrict__ P,
                                            int K, long k0, int tid) {
    #pragma unroll
    for (int i = 0; i < 2; i++) {
        int idx = tid + i * 256;
        int row = idx >> 2, c = idx & 3;
        const __half* src = P + (long)row * K + k0 + c * 8;
        uint32_t dst = sbase + row * 64 + ((c ^ ((row >> 1) & 3)) << 4);
        cp16(dst, src);
    }
}

template <int MODE>
__global__ void __launch_bounds__(256, 2) gemm_mma_kernel(
    const __half* __restrict__ A,
    const __half* __restrict__ B0, const __half* __restrict__ B1,
    const __half* __restrict__ B2,
    const float* __restrict__ bias, const float* res,
    float* Cf0, float* Cf1, float* Cf2,
    __half* __restrict__ Ch,
    int M, int N, int K, int ntx, int nty, int ntz)
{
    extern __shared__ char smem[];
    uint32_t sb = smem_u32(smem);
    int tid = threadIdx.x;
    int wid = tid >> 5, lane = tid & 31;
    int warp_m = wid >> 2, warp_n = wid & 3;
    int m0 = warp_m * 64, n0 = warp_n * 32;

    int grp = lane >> 3, lr = lane & 7;
    int rowA0 = m0 + (grp & 1) * 8 + lr;
    int ccA   = grp >> 1;
    int rowB0 = n0 + (grp >> 1) * 8 + lr;
    int ccB   = grp & 1;
    int xA = (rowA0 >> 1) & 3;      // invariant under +16
    int xB = (rowB0 >> 1) & 3;
    int nc = K / 32;
    int ntot = ntx * nty * ntz;

    for (int t = blockIdx.x; t < ntot; t += gridDim.x) {
        int z   = t / (ntx * nty);
        int rem = t - z * (ntx * nty);
        int by  = rem / ntx;
        int bx  = rem - by * ntx;
        int row0 = by * 128, col0 = bx * 128;

        const __half* B  = (z == 0) ? B0 : (z == 1) ? B1 : B2;
        float* Cf = (z == 0) ? Cf0 : (z == 1) ? Cf1 : Cf2;

        const __half* pA = A + (long)row0 * K;
        const __half* pB = B + (long)col0 * K;

        float acc[4][4][4];
        #pragma unroll
        for (int i = 0; i < 4; i++)
            #pragma unroll
            for (int j = 0; j < 4; j++)
                #pragma unroll
                for (int q = 0; q < 4; q++) acc[i][j][q] = 0.f;

        __syncthreads();   // previous tile's readers done with smem

        #pragma unroll
        for (int p = 0; p < 3; p++) {
            uint32_t st = sb + p * STAGE_BYTES;
            load_tile64(st,          pA, K, (long)p * 32, tid);
            load_tile64(st + T_TILE, pB, K, (long)p * 32, tid);
            cp_commit();
        }

        int s_comp = 0, s_load = 3;
        for (int c = 0; c < nc; c++) {
            cp_wait<2>();
            __syncthreads();
            if (c + 3 < nc) {
                uint32_t st = sb + s_load * STAGE_BYTES;
                long k0 = (long)(c + 3) * 32;
                load_tile64(st,          pA, K, k0, tid);
                load_tile64(st + T_TILE, pB, K, k0, tid);
            }
            cp_commit();

            uint32_t sA = sb + s_comp * STAGE_BYTES;
            uint32_t sB = sA + T_TILE;
            #pragma unroll
            for (int ks = 0; ks < 2; ks++) {
                uint32_t af[4][4], bf[2][4];
                #pragma unroll
                for (int mt = 0; mt < 4; mt++) {
                    uint32_t base = sA + (rowA0 + mt * 16) * 64;
                    ldmx4(af[mt], base + (((ks * 2 + ccA) ^ xA) << 4));
                }
                #pragma unroll
                for (int np = 0; np < 2; np++) {
                    uint32_t base = sB + (rowB0 + np * 16) * 64;
                    ldmx4(bf[np], base + (((ks * 2 + ccB) ^ xB) << 4));
                }
                #pragma unroll
                for (int mt = 0; mt < 4; mt++)
                    #pragma unroll
                    for (int nt = 0; nt < 4; nt++)
                        mma16816h(acc[mt][nt], af[mt], &bf[nt >> 1][(nt & 1) * 2]);
            }
            s_comp = (s_comp + 1) & 3;
            s_load = (s_load + 1) & 3;
        }

        int r = lane >> 2, c2 = (lane & 3) * 2;
        #pragma unroll
        for (int mt = 0; mt < 4; mt++) {
            #pragma unroll
            for (int nt = 0; nt < 4; nt++) {
                long gr = row0 + m0 + mt * 16 + r;
                long gc = col0 + n0 + nt * 8 + c2;
                #pragma unroll
                for (int hrow = 0; hrow < 2; hrow++) {
                    long grr = gr + hrow * 8;
                    float v0 = acc[mt][nt][hrow * 2 + 0];
                    float v1 = acc[mt][nt][hrow * 2 + 1];
                    if (MODE == 0) {
                        *(float2*)(Cf + grr * N + gc) = make_float2(v0, v1);
                    } else if (MODE == 1) {
                        float2 b = *(const float2*)(bias + gc);
                        float2 rr = *(const float2*)(res + grr * N + gc);
                        *(float2*)(Cf + grr * N + gc) = make_float2(v0 + b.x + rr.x, v1 + b.y + rr.y);
                    } else {
                        *(uint32_t*)(Ch + grr * N + gc) = packh2(gelu_tanh(v0), gelu_tanh(v1));
                    }
                }
            }
        }
    }
}

// ======================= tensor-core flash attention (split-bf16, fp16 out) =======================
#define ASM_QH 0
#define ASM_QL 16384
#define ASM_KH 32768
#define ASM_KL 49152
#define ASM_VH 65536
#define ASM_VL 81920
#define ASM_KF 98304
#define ASM_VF 133120
#define ASM_TOTAL 167936

__device__ __forceinline__ void cvt_tile(uint32_t fbase, uint32_t hbase, uint32_t lbase, int tid) {
    int row = tid >> 1, half = tid & 1;
    uint32_t fr = fbase + row * 272;
    uint32_t hr = hbase + row * 128;
    uint32_t lr_ = lbase + row * 128;
    #pragma unroll
    for (int j = 0; j < 4; j++) {
        float4 f0, f1;
        asm volatile("ld.shared.v4.f32 {%0,%1,%2,%3}, [%4];"
                     : "=f"(f0.x), "=f"(f0.y), "=f"(f0.z), "=f"(f0.w)
                     : "r"(fr + (half * 8 + j * 2) * 16));
        asm volatile("ld.shared.v4.f32 {%0,%1,%2,%3}, [%4];"
                     : "=f"(f1.x), "=f"(f1.y), "=f"(f1.z), "=f"(f1.w)
                     : "r"(fr + (half * 8 + j * 2 + 1) * 16));
        float v[8] = {f0.x, f0.y, f0.z, f0.w, f1.x, f1.y, f1.z, f1.w};
        uint32_t hi[4], lo[4];
        #pragma unroll
        for (int q = 0; q < 4; q++) {
            float a = v[q * 2], b = v[q * 2 + 1];
            float ha = __bfloat162float(__float2bfloat16(a));
            float hb = __bfloat162float(__float2bfloat16(b));
            hi[q] = packbf2(ha, hb);
            lo[q] = packbf2(a - ha, b - hb);
        }
        int c = half * 4 + j;
        uint32_t sw = (uint32_t)((c ^ (row & 7)) << 4);
        asm volatile("st.shared.v4.b32 [%0], {%1,%2,%3,%4};"
                     :: "r"(hr + sw), "r"(hi[0]), "r"(hi[1]), "r"(hi[2]), "r"(hi[3]));
        asm volatile("st.shared.v4.b32 [%0], {%1,%2,%3,%4};"
                     :: "r"(lr_ + sw), "r"(lo[0]), "r"(lo[1]), "r"(lo[2]), "r"(lo[3]));
    }
}

__device__ __forceinline__ void stage_cp(uint32_t fbase, const float* __restrict__ src,
                                         int keyrow0, int h, int tid) {
    #pragma unroll
    for (int i = 0; i < 8; i++) {
        int idx = tid + i * 256;
        int r = idx >> 4, c = idx & 15;
        cp16(fbase + r * 272 + c * 16, src + (long)(keyrow0 + r) * HID + h * HDIM + c * 4);
    }
}

__global__ void __launch_bounds__(256) attn_mma_kernel(
    const float* __restrict__ Q, const float* __restrict__ K,
    const float* __restrict__ V, __half* __restrict__ O)
{
    extern __shared__ char smem[];
    uint32_t sb = smem_u32(smem);
    int tid = threadIdx.x;
    int w = tid >> 5, lane = tid & 31;
    int qb = blockIdx.x, h = blockIdx.y;

    int grp = lane >> 3, lr = lane & 7;
    int rowQ = w * 16 + (grp & 1) * 8 + lr;
    int ccQ  = grp >> 1;
    int xQ = rowQ & 7;
    int rowK_off = (grp >> 1) * 8 + lr;
    int ccK  = grp & 1;
    int rowV_off = (grp & 1) * 8 + lr;
    int ccV_off  = grp >> 1;

    {
        int row = tid >> 1, half = tid & 1;
        const float* src = Q + (long)(qb * 128 + row) * HID + h * HDIM + half * 32;
        uint32_t hr = sb + ASM_QH + row * 128;
        uint32_t lr2 = sb + ASM_QL + row * 128;
        #pragma unroll
        for (int j = 0; j < 4; j++) {
            float4 f0 = *(const float4*)(src + j * 8);
            float4 f1 = *(const float4*)(src + j * 8 + 4);
            float v[8] = {f0.x, f0.y, f0.z, f0.w, f1.x, f1.y, f1.z, f1.w};
            uint32_t hi[4], lo[4];
            #pragma unroll
            for (int q = 0; q < 4; q++) {
                float a = v[q * 2] * 0.125f, b = v[q * 2 + 1] * 0.125f;
                float ha = __bfloat162float(__float2bfloat16(a));
                float hb = __bfloat162float(__float2bfloat16(b));
                hi[q] = packbf2(ha, hb);
                lo[q] = packbf2(a - ha, b - hb);
            }
            int c = half * 4 + j;
            uint32_t sw = (uint32_t)((c ^ (row & 7)) << 4);
            asm volatile("st.shared.v4.b32 [%0], {%1,%2,%3,%4};"
                         :: "r"(hr + sw), "r"(hi[0]), "r"(hi[1]), "r"(hi[2]), "r"(hi[3]));
            asm volatile("st.shared.v4.b32 [%0], {%1,%2,%3,%4};"
                         :: "r"(lr2 + sw), "r"(lo[0]), "r"(lo[1]), "r"(lo[2]), "r"(lo[3]));
        }
    }
    stage_cp(sb + ASM_KF, K, 0, h, tid);
    stage_cp(sb + ASM_VF, V, 0, h, tid);
    cp_commit();
    __syncthreads();

    uint32_t qfh[4][4], qfl[4][4];
    #pragma unroll
    for (int ks = 0; ks < 4; ks++) {
        uint32_t base = sb + rowQ * 128;
        ldmx4(qfh[ks], base + ASM_QH + (((ks * 2 + ccQ) ^ xQ) << 4));
        ldmx4(qfl[ks], base + ASM_QL + (((ks * 2 + ccQ) ^ xQ) << 4));
    }

    float oacc[8][4];
    #pragma unroll
    for (int i = 0; i < 8; i++)
        #pragma unroll
        for (int q = 0; q < 4; q++) oacc[i][q] = 0.f;
    float m0 = -1e30f, m1 = -1e30f, l0 = 0.f, l1 = 0.f;

    int qg0 = qb * 128 + w * 16 + (lane >> 2);
    int qg1 = qg0 + 8;

    for (int kt = 0; kt <= qb; kt++) {
        cp_wait<0>();
        __syncthreads();
        cvt_tile(sb + ASM_KF, sb + ASM_KH, sb + ASM_KL, tid);
        cvt_tile(sb + ASM_VF, sb + ASM_VH, sb + ASM_VL, tid);
        __syncthreads();
        if (kt < qb) {
            stage_cp(sb + ASM_KF, K, (kt + 1) * 128, h, tid);
            stage_cp(sb + ASM_VF, V, (kt + 1) * 128, h, tid);
        }
        cp_commit();

        float sacc[16][4];
        #pragma unroll
        for (int i = 0; i < 16; i++)
            #pragma unroll
            for (int q = 0; q < 4; q++) sacc[i][q] = 0.f;

        #pragma unroll
        for (int ks = 0; ks < 4; ks++) {
            #pragma unroll
            for (int nb = 0; nb < 8; nb++) {
                int rowK = nb * 16 + rowK_off;
                uint32_t base = sb + rowK * 128;
                uint32_t off = (uint32_t)(((ks * 2 + ccK) ^ (rowK & 7)) << 4);
                uint32_t bkh[4], bkl[4];
                ldmx4(bkh, base + ASM_KH + off);
                ldmx4(bkl, base + ASM_KL + off);
                #pragma unroll
                for (int sub = 0; sub < 2; sub++) {
                    float* d = sacc[nb * 2 + sub];
                    mma16816(d, qfh[ks], &bkh[sub * 2]);
                    mma16816(d, qfh[ks], &bkl[sub * 2]);
                    mma16816(d, qfl[ks], &bkh[sub * 2]);
                }
            }
        }

        if (kt == qb) {
            #pragma unroll
            for (int nt = 0; nt < 16; nt++) {
                int kg = kt * 128 + nt * 8 + 2 * (lane & 3);
                #pragma unroll
                for (int e = 0; e < 2; e++) {
                    if (kg + e > qg0) sacc[nt][e]     = -1e30f;
                    if (kg + e > qg1) sacc[nt][2 + e] = -1e30f;
                }
            }
        }

        float rm0 = -1e30f, rm1 = -1e30f;
        #pragma unroll
        for (int nt = 0; nt < 16; nt++) {
            rm0 = fmaxf(rm0, fmaxf(sacc[nt][0], sacc[nt][1]));
            rm1 = fmaxf(rm1, fmaxf(sacc[nt][2], sacc[nt][3]));
        }
        rm0 = fmaxf(rm0, __shfl_xor_sync(0xFFFFFFFFu, rm0, 1));
        rm0 = fmaxf(rm0, __shfl_xor_sync(0xFFFFFFFFu, rm0, 2));
        rm1 = fmaxf(rm1, __shfl_xor_sync(0xFFFFFFFFu, rm1, 1));
        rm1 = fmaxf(rm1, __shfl_xor_sync(0xFFFFFFFFu, rm1, 2));
        float mn0 = fmaxf(m0, rm0), mn1 = fmaxf(m1, rm1);
        float al0 = __expf(m0 - mn0), al1 = __expf(m1 - mn1);
        m0 = mn0; m1 = mn1;

        float rs0 = 0.f, rs1 = 0.f;
        #pragma unroll
        for (int nt = 0; nt < 16; nt++) {
            sacc[nt][0] = __expf(sacc[nt][0] - mn0);
            sacc[nt][1] = __expf(sacc[nt][1] - mn0);
            sacc[nt][2] = __expf(sacc[nt][2] - mn1);
            sacc[nt][3] = __expf(sacc[nt][3] - mn1);
            rs0 += sacc[nt][0] + sacc[nt][1];
            rs1 += sacc[nt][2] + sacc[nt][3];
        }
        rs0 += __shfl_xor_sync(0xFFFFFFFFu, rs0, 1);
        rs0 += __shfl_xor_sync(0xFFFFFFFFu, rs0, 2);
        rs1 += __shfl_xor_sync(0xFFFFFFFFu, rs1, 1);
        rs1 += __shfl_xor_sync(0xFFFFFFFFu, rs1, 2);
        l0 = l0 * al0 + rs0;
        l1 = l1 * al1 + rs1;

        #pragma unroll
        for (int i = 0; i < 8; i++) {
            oacc[i][0] *= al0; oacc[i][1] *= al0;
            oacc[i][2] *= al1; oacc[i][3] *= al1;
        }

        #pragma unroll
        for (int ks2 = 0; ks2 < 8; ks2++) {
            uint32_t ah[4], al[4];
            {
                float p00 = sacc[2 * ks2][0],     p01 = sacc[2 * ks2][1];
                float p10 = sacc[2 * ks2][2],     p11 = sacc[2 * ks2][3];
                float p20 = sacc[2 * ks2 + 1][0], p21 = sacc[2 * ks2 + 1][1];
                float p30 = sacc[2 * ks2 + 1][2], p31 = sacc[2 * ks2 + 1][3];
                float h00 = __bfloat162float(__float2bfloat16(p00));
                float h01 = __bfloat162float(__float2bfloat16(p01));
                float h10 = __bfloat162float(__float2bfloat16(p10));
                float h11 = __bfloat162float(__float2bfloat16(p11));
                float h20 = __bfloat162float(__float2bfloat16(p20));
                float h21 = __bfloat162float(__float2bfloat16(p21));
                float h30 = __bfloat162float(__float2bfloat16(p30));
                float h31 = __bfloat162float(__float2bfloat16(p31));
                ah[0] = packbf2(h00, h01); ah[1] = packbf2(h10, h11);
                ah[2] = packbf2(h20, h21); ah[3] = packbf2(h30, h31);
                al[0] = packbf2(p00 - h00, p01 - h01);
                al[1] = packbf2(p10 - h10, p11 - h11);
                al[2] = packbf2(p20 - h20, p21 - h21);
                al[3] = packbf2(p30 - h30, p31 - h31);
            }
            #pragma unroll
            for (int db = 0; db < 4; db++) {
                int rowV = ks2 * 16 + rowV_off;
                int cc = db * 2 + ccV_off;
                uint32_t base = sb + rowV * 128;
                uint32_t off = (uint32_t)((cc ^ (rowV & 7)) << 4);
                uint32_t bvh[4], bvl[4];
                ldmx4t(bvh, base + ASM_VH + off);
                ldmx4t(bvl, base + ASM_VL + off);
                #pragma unroll
                for (int sub = 0; sub < 2; sub++) {
                    float* d = oacc[db * 2 + sub];
                    mma16816(d, ah, &bvh[sub * 2]);
                    mma16816(d, al, &bvh[sub * 2]);
                    mma16816(d, ah, &bvl[sub * 2]);
                }
            }
        }
    }

    float i0 = 1.0f / l0, i1 = 1.0f / l1;
    long gr0 = qb * 128 + w * 16 + (lane >> 2);
    long gc0 = h * HDIM + 2 * (lane & 3);
    #pragma unroll
    for (int nto = 0; nto < 8; nto++) {
        long gc = gc0 + nto * 8;
        *(uint32_t*)(O + gr0 * HID + gc)       = packh2(oacc[nto][0] * i0, oacc[nto][1] * i0);
        *(uint32_t*)(O + (gr0 + 8) * HID + gc) = packh2(oacc[nto][2] * i1, oacc[nto][3] * i1);
    }
}

// ======================= orchestration =======================
extern "C" void kernel_launch(void* const* d_in, const int* in_sizes, int n_in,
                              void* d_out, int out_size) {
    const float* emb = (const float*)d_in[0];
    const float* Wq = (const float*)d_in[2];
    const float* Wk = (const float*)d_in[3];
    const float* Wv = (const float*)d_in[4];
    const float* Wo = (const float*)d_in[5];
    const float* bo = (const float*)d_in[6];
    const float* W1 = (const float*)d_in[7];
    const float* W2 = (const float*)d_in[8];
    const float* b2 = (const float*)d_in[9];
    const float* g1 = (const float*)d_in[10];
    const float* g2 = (const float*)d_in[11];
    const float* gf = (const float*)d_in[12];
    float* out = (float*)d_out;

    float *px, *pq, *pk, *pv;
    __half *ph, *pctx, *pmid;
    __half *wq, *wk, *wv, *wo, *w1, *w2;
    cudaGetSymbolAddress((void**)&px,   g_x);
    cudaGetSymbolAddress((void**)&pq,   g_q);
    cudaGetSymbolAddress((void**)&pk,   g_k);
    cudaGetSymbolAddress((void**)&pv,   g_v);
    cudaGetSymbolAddress((void**)&ph,   g_h);
    cudaGetSymbolAddress((void**)&pctx, g_ctx);
    cudaGetSymbolAddress((void**)&pmid, g_mid);
    cudaGetSymbolAddress((void**)&wq, g_wqt);
    cudaGetSymbolAddress((void**)&wk, g_wkt);
    cudaGetSymbolAddress((void**)&wv, g_wvt);
    cudaGetSymbolAddress((void**)&wo, g_wot);
    cudaGetSymbolAddress((void**)&w1, g_w1t);
    cudaGetSymbolAddress((void**)&w2, g_w2t);

    cudaFuncSetAttribute(gemm_mma_kernel<0>, cudaFuncAttributeMaxDynamicSharedMemorySize, GSM_TOTAL);
    cudaFuncSetAttribute(gemm_mma_kernel<1>, cudaFuncAttributeMaxDynamicSharedMemorySize, GSM_TOTAL);
    cudaFuncSetAttribute(gemm_mma_kernel<2>, cudaFuncAttributeMaxDynamicSharedMemorySize, GSM_TOTAL);
    cudaFuncSetAttribute(attn_mma_kernel, cudaFuncAttributeMaxDynamicSharedMemorySize, ASM_TOTAL);

    {
        int n4 = SEQ * HID / 4;
        copy_kernel<<<(n4 + 255) / 256, 256>>>((const float4*)emb, (float4*)px, n4);
    }

    {
        dim3 b(32, 8);
        dim3 gHH(HID / 32, HID / 32);
        dim3 gW1(ISZ / 32, HID / 32);
        dim3 gW2(HID / 32, ISZ / 32);
        for (int l = 0; l < NLAYER; l++) {
            long oHH = (long)l * HID * HID, oHI = (long)l * HID * ISZ;
            wsplit_kernel<<<gHH, b>>>(Wq + oHH, wq + oHH, HID, HID);
            wsplit_kernel<<<gHH, b>>>(Wk + oHH, wk + oHH, HID, HID);
            wsplit_kernel<<<gHH, b>>>(Wv + oHH, wv + oHH, HID, HID);
            wsplit_kernel<<<gHH, b>>>(Wo + oHH, wo + oHH, HID, HID);
            wsplit_kernel<<<gW1, b>>>(W1 + oHI, w1 + oHI, HID, ISZ);
            wsplit_kernel<<<gW2, b>>>(W2 + oHI, w2 + oHI, ISZ, HID);
        }
    }

    dim3 gAttn(SEQ / 128, NHEAD);
    const int ntHH = (HID / 128) * (SEQ / 128);          // 256
    const int ntQKV = ntHH * 3;                          // 768
    const int ntHI = (ISZ / 128) * (SEQ / 128);          // 1024
    int gQKV = ntQKV < PERSIST_GRID ? ntQKV : PERSIST_GRID;
    int gHH  = ntHH  < PERSIST_GRID ? ntHH  : PERSIST_GRID;
    int gHI  = ntHI  < PERSIST_GRID ? ntHI  : PERSIST_GRID;

    for (int l = 0; l < NLAYER; l++) {
        long oHH = (long)l * HID * HID, oHI = (long)l * HID * ISZ;

        ln_kernel<1><<<SEQ, 256>>>(px, g1 + l * HID, nullptr, ph);
        gemm_mma_kernel<0><<<gQKV, 256, GSM_TOTAL>>>(ph,
            wq + oHH, wk + oHH, wv + oHH,
            nullptr, nullptr, pq, pk, pv, nullptr,
            SEQ, HID, HID, HID / 128, SEQ / 128, 3);
        attn_mma_kernel<<<gAttn, 256, ASM_TOTAL>>>(pq, pk, pv, pctx);
        gemm_mma_kernel<1><<<gHH, 256, GSM_TOTAL>>>(pctx,
            wo + oHH, nullptr, nullptr,
            bo + l * HID, px, px, nullptr, nullptr, nullptr,
            SEQ, HID, HID, HID / 128, SEQ / 128, 1);

        ln_kernel<1><<<SEQ, 256>>>(px, g2 + l * HID, nullptr, ph);
        gemm_mma_kernel<2><<<gHI, 256, GSM_TOTAL>>>(ph,
            w1 + oHI, nullptr, nullptr,
            nullptr, nullptr, nullptr, nullptr, nullptr, pmid,
            SEQ, ISZ, HID, ISZ / 128, SEQ / 128, 1);
        gemm_mma_kernel<1><<<gHH, 256, GSM_TOTAL>>>(pmid,
            w2 + oHI, nullptr, nullptr,
            b2 + l * HID, px, px, nullptr, nullptr, nullptr,
            SEQ, HID, ISZ, HID / 128, SEQ / 128, 1);
    }

    ln_kernel<0><<<SEQ, 256>>>(px, gf, out, nullptr);
}

// round 11
// speedup vs baseline: 8.0124x; 1.1729x over previous
#include <cuda_runtime.h>
#include <cuda_fp16.h>
#include <math.h>
#include <stdint.h>

#define SEQ 2048
#define HID 2048
#define NHEAD 32
#define HDIM 64
#define ISZ 8192
#define NLAYER 2

// ======================= scratch (static device arrays) =======================
__device__ float g_x  [SEQ * HID];
__device__ __half g_q  [SEQ * HID];
__device__ __half g_k  [SEQ * HID];
__device__ __half g_v  [SEQ * HID];
__device__ __half g_h  [SEQ * HID];
__device__ __half g_ctx[SEQ * HID];
__device__ __half g_mid[SEQ * ISZ];
// transposed weights: Wt[N][K], plain fp16
__device__ __half g_wqt[NLAYER * HID * HID];
__device__ __half g_wkt[NLAYER * HID * HID];
__device__ __half g_wvt[NLAYER * HID * HID];
__device__ __half g_wot[NLAYER * HID * HID];
__device__ __half g_w1t[NLAYER * HID * ISZ];
__device__ __half g_w2t[NLAYER * ISZ * HID];

// ======================= PTX helpers =======================
__device__ __forceinline__ uint32_t smem_u32(const void* p) {
    uint32_t a;
    asm("{ .reg .u64 t; cvta.to.shared.u64 t, %1; cvt.u32.u64 %0, t; }" : "=r"(a) : "l"(p));
    return a;
}
__device__ __forceinline__ void cp16(uint32_t dst, const void* src) {
    asm volatile("cp.async.cg.shared.global [%0], [%1], 16;" :: "r"(dst), "l"(src));
}
__device__ __forceinline__ void cp_commit() {
    asm volatile("cp.async.commit_group;" ::: "memory");
}
template <int N>
__device__ __forceinline__ void cp_wait() {
    asm volatile("cp.async.wait_group %0;" :: "n"(N) : "memory");
}
__device__ __forceinline__ void ldmx4(uint32_t* r, uint32_t addr) {
    asm volatile("ldmatrix.sync.aligned.m8n8.x4.shared.b16 {%0,%1,%2,%3}, [%4];"
                 : "=r"(r[0]), "=r"(r[1]), "=r"(r[2]), "=r"(r[3]) : "r"(addr));
}
__device__ __forceinline__ void ldmx4t(uint32_t* r, uint32_t addr) {
    asm volatile("ldmatrix.sync.aligned.m8n8.x4.trans.shared.b16 {%0,%1,%2,%3}, [%4];"
                 : "=r"(r[0]), "=r"(r[1]), "=r"(r[2]), "=r"(r[3]) : "r"(addr));
}
__device__ __forceinline__ void mma16816h(float* d, const uint32_t* a, const uint32_t* b) {
    asm volatile("mma.sync.aligned.m16n8k16.row.col.f32.f16.f16.f32 "
                 "{%0,%1,%2,%3}, {%4,%5,%6,%7}, {%8,%9}, {%0,%1,%2,%3};"
                 : "+f"(d[0]), "+f"(d[1]), "+f"(d[2]), "+f"(d[3])
                 : "r"(a[0]), "r"(a[1]), "r"(a[2]), "r"(a[3]), "r"(b[0]), "r"(b[1]));
}
__device__ __forceinline__ uint32_t packh2(float lo, float hi) {
    __half2 t = __floats2half2_rn(lo, hi);
    return *(uint32_t*)&t;
}

// ======================= small kernels =======================
__global__ void copy_kernel(const float4* __restrict__ in, float4* __restrict__ out, int n4) {
    int i = blockIdx.x * 256 + threadIdx.x;
    if (i < n4) out[i] = in[i];
}

__device__ __forceinline__ float gelu_tanh(float v) {
    float t = 0.7978845608028654f * v * (1.0f + 0.044715f * v * v);
    return 0.5f * v * (1.0f + tanhf(t));
}

template <int HALF>
__global__ void __launch_bounds__(256) ln_kernel(const float* __restrict__ x,
                                                 const float* __restrict__ gamma,
                                                 float* __restrict__ outf,
                                                 __half* __restrict__ oh) {
    __shared__ float sh[18];
    int row = blockIdx.x;
    const float* xr = x + (long)row * HID;
    float s = 0.f, s2 = 0.f;
    for (int i = threadIdx.x; i < HID; i += 256) {
        float v = xr[i];
        s += v; s2 += v * v;
    }
    #pragma unroll
    for (int o = 16; o; o >>= 1) {
        s  += __shfl_xor_sync(0xFFFFFFFFu, s,  o);
        s2 += __shfl_xor_sync(0xFFFFFFFFu, s2, o);
    }
    int w = threadIdx.x >> 5, lane = threadIdx.x & 31;
    if (lane == 0) { sh[w] = s; sh[8 + w] = s2; }
    __syncthreads();
    if (threadIdx.x < 32) {
        s  = (threadIdx.x < 8) ? sh[threadIdx.x]     : 0.f;
        s2 = (threadIdx.x < 8) ? sh[8 + threadIdx.x] : 0.f;
        #pragma unroll
        for (int o = 4; o; o >>= 1) {
            s  += __shfl_xor_sync(0xFFFFFFFFu, s,  o);
            s2 += __shfl_xor_sync(0xFFFFFFFFu, s2, o);
        }
        if (threadIdx.x == 0) {
            float mu = s * (1.0f / HID);
            float var = s2 * (1.0f / HID) - mu * mu;
            sh[16] = mu;
            sh[17] = rsqrtf(var + 1e-5f);
        }
    }
    __syncthreads();
    float mu = sh[16], inv = sh[17];
    for (int i = threadIdx.x; i < HID; i += 256) {
        float v = (xr[i] - mu) * inv * gamma[i];
        if (HALF) oh[(long)row * HID + i] = __float2half(v);
        else      outf[(long)row * HID + i] = v;
    }
}

// weight transpose: W[K,N] fp32 -> Th[N,K] fp16
__global__ void __launch_bounds__(256) wsplit_kernel(const float* __restrict__ W,
                                                     __half* __restrict__ Th,
                                                     int K, int N) {
    __shared__ float t[32][33];
    int bx = blockIdx.x * 32, by = blockIdx.y * 32;
    int tx = threadIdx.x, ty = threadIdx.y;
    #pragma unroll
    for (int i = 0; i < 4; i++)
        t[ty + i * 8][tx] = W[(long)(by + ty + i * 8) * N + bx + tx];
    __syncthreads();
    #pragma unroll
    for (int i = 0; i < 4; i++) {
        float v = t[tx][ty + i * 8];
        Th[(long)(bx + ty + i * 8) * K + by + tx] = __float2half(v);
    }
}

// ======================= persistent mma.sync fp16 GEMM =======================
// C[M,N] = A[M,K] @ B^T, B stored [N,K] row-major fp16.
// BM=128, BN=128, BK=32; 8 warps, warp tile 64x32; 4-stage cp.async (64KB), 2 CTA/SM.
// MODE 0: Ch = fp16(AB)  (z-fused, Ch0..2) ; MODE 1: Cf = AB + bias + res ; MODE 2: Ch = fp16(gelu(AB))
#define T_TILE 8192
#define STAGE_BYTES (2 * T_TILE)
#define NSTAGE 4
#define GSM_TOTAL (NSTAGE * STAGE_BYTES)
#define PERSIST_GRID 296

__device__ __forceinline__ void load_tile64(uint32_t sbase, const __half* __restrict__ P,
                                            int K, long k0, int tid) {
    #pragma unroll
    for (int i = 0; i < 2; i++) {
        int idx = tid + i * 256;
        int row = idx >> 2, c = idx & 3;
        const __half* src = P + (long)row * K + k0 + c * 8;
        uint32_t dst = sbase + row * 64 + ((c ^ ((row >> 1) & 3)) << 4);
        cp16(dst, src);
    }
}

template <int MODE>
__global__ void __launch_bounds__(256, 2) gemm_mma_kernel(
    const __half* __restrict__ A,
    const __half* __restrict__ B0, const __half* __restrict__ B1,
    const __half* __restrict__ B2,
    const float* __restrict__ bias, const float* res,
    float* Cf,
    __half* __restrict__ Ch0, __half* __restrict__ Ch1, __half* __restrict__ Ch2,
    int M, int N, int K, int ntx, int nty, int ntz)
{
    extern __shared__ char smem[];
    uint32_t sb = smem_u32(smem);
    int tid = threadIdx.x;
    int wid = tid >> 5, lane = tid & 31;
    int warp_m = wid >> 2, warp_n = wid & 3;
    int m0 = warp_m * 64, n0 = warp_n * 32;

    int grp = lane >> 3, lr = lane & 7;
    int rowA0 = m0 + (grp & 1) * 8 + lr;
    int ccA   = grp >> 1;
    int rowB0 = n0 + (grp >> 1) * 8 + lr;
    int ccB   = grp & 1;
    int xA = (rowA0 >> 1) & 3;
    int xB = (rowB0 >> 1) & 3;
    int nc = K / 32;
    int ntot = ntx * nty * ntz;

    for (int t = blockIdx.x; t < ntot; t += gridDim.x) {
        int z   = t / (ntx * nty);
        int rem = t - z * (ntx * nty);
        int by  = rem / ntx;
        int bx  = rem - by * ntx;
        int row0 = by * 128, col0 = bx * 128;

        const __half* B  = (z == 0) ? B0 : (z == 1) ? B1 : B2;
        __half* Ch = (z == 0) ? Ch0 : (z == 1) ? Ch1 : Ch2;

        const __half* pA = A + (long)row0 * K;
        const __half* pB = B + (long)col0 * K;

        float acc[4][4][4];
        #pragma unroll
        for (int i = 0; i < 4; i++)
            #pragma unroll
            for (int j = 0; j < 4; j++)
                #pragma unroll
                for (int q = 0; q < 4; q++) acc[i][j][q] = 0.f;

        __syncthreads();

        #pragma unroll
        for (int p = 0; p < 3; p++) {
            uint32_t st = sb + p * STAGE_BYTES;
            load_tile64(st,          pA, K, (long)p * 32, tid);
            load_tile64(st + T_TILE, pB, K, (long)p * 32, tid);
            cp_commit();
        }

        int s_comp = 0, s_load = 3;
        for (int c = 0; c < nc; c++) {
            cp_wait<2>();
            __syncthreads();
            if (c + 3 < nc) {
                uint32_t st = sb + s_load * STAGE_BYTES;
                long k0 = (long)(c + 3) * 32;
                load_tile64(st,          pA, K, k0, tid);
                load_tile64(st + T_TILE, pB, K, k0, tid);
            }
            cp_commit();

            uint32_t sA = sb + s_comp * STAGE_BYTES;
            uint32_t sB = sA + T_TILE;
            #pragma unroll
            for (int ks = 0; ks < 2; ks++) {
                uint32_t af[4][4], bf[2][4];
                #pragma unroll
                for (int mt = 0; mt < 4; mt++) {
                    uint32_t base = sA + (rowA0 + mt * 16) * 64;
                    ldmx4(af[mt], base + (((ks * 2 + ccA) ^ xA) << 4));
                }
                #pragma unroll
                for (int np = 0; np < 2; np++) {
                    uint32_t base = sB + (rowB0 + np * 16) * 64;
                    ldmx4(bf[np], base + (((ks * 2 + ccB) ^ xB) << 4));
                }
                #pragma unroll
                for (int mt = 0; mt < 4; mt++)
                    #pragma unroll
                    for (int nt = 0; nt < 4; nt++)
                        mma16816h(acc[mt][nt], af[mt], &bf[nt >> 1][(nt & 1) * 2]);
            }
            s_comp = (s_comp + 1) & 3;
            s_load = (s_load + 1) & 3;
        }

        int r = lane >> 2, c2 = (lane & 3) * 2;
        #pragma unroll
        for (int mt = 0; mt < 4; mt++) {
            #pragma unroll
            for (int nt = 0; nt < 4; nt++) {
                long gr = row0 + m0 + mt * 16 + r;
                long gc = col0 + n0 + nt * 8 + c2;
                #pragma unroll
                for (int hrow = 0; hrow < 2; hrow++) {
                    long grr = gr + hrow * 8;
                    float v0 = acc[mt][nt][hrow * 2 + 0];
                    float v1 = acc[mt][nt][hrow * 2 + 1];
                    if (MODE == 0) {
                        *(uint32_t*)(Ch + grr * N + gc) = packh2(v0, v1);
                    } else if (MODE == 1) {
                        float2 b = *(const float2*)(bias + gc);
                        float2 rr = *(const float2*)(res + grr * N + gc);
                        *(float2*)(Cf + grr * N + gc) = make_float2(v0 + b.x + rr.x, v1 + b.y + rr.y);
                    } else {
                        *(uint32_t*)(Ch + grr * N + gc) = packh2(gelu_tanh(v0), gelu_tanh(v1));
                    }
                }
            }
        }
    }
}

// ======================= tensor-core flash attention (plain fp16) =======================
// Grid: (SEQ/128, NHEAD), 256 threads = 8 warps; warp owns 16 rows x all 128 keys.
// Q,K,V fp16 in global -> swizzled smem via cp.async (no conversion). 1 mma per tile.
// SMEM: Q 16KB @0, K0 @16384, V0 @32768, K1 @49152, V1 @65536. Total 81920.
#define AS_Q  0
#define AS_K0 16384
#define AS_V0 32768
#define AS_K1 49152
#define AS_V1 65536
#define AS_TOTAL 81920

__device__ __forceinline__ void stage_h(uint32_t sbase, const __half* __restrict__ src,
                                        int row0, int h, int tid) {
    // 128 rows x 8 chunks(16B); 64 fp16 per row = 128B
    #pragma unroll
    for (int i = 0; i < 4; i++) {
        int idx = tid + i * 256;
        int r = idx >> 3, c = idx & 7;
        cp16(sbase + r * 128 + ((c ^ (r & 7)) << 4),
             src + (long)(row0 + r) * HID + h * HDIM + c * 8);
    }
}

__global__ void __launch_bounds__(256) attn_mma_kernel(
    const __half* __restrict__ Q, const __half* __restrict__ K,
    const __half* __restrict__ V, __half* __restrict__ O)
{
    extern __shared__ char smem[];
    uint32_t sb = smem_u32(smem);
    int tid = threadIdx.x;
    int w = tid >> 5, lane = tid & 31;
    int qb = blockIdx.x, h = blockIdx.y;

    int grp = lane >> 3, lr = lane & 7;
    int rowQ = w * 16 + (grp & 1) * 8 + lr;
    int ccQ  = grp >> 1;
    int xQ = rowQ & 7;
    int rowK_off = (grp >> 1) * 8 + lr;
    int ccK  = grp & 1;
    int rowV_off = (grp & 1) * 8 + lr;
    int ccV_off  = grp >> 1;

    // stage Q + first KV
    stage_h(sb + AS_Q,  Q, qb * 128, h, tid);
    stage_h(sb + AS_K0, K, 0,        h, tid);
    stage_h(sb + AS_V0, V, 0,        h, tid);
    cp_commit();
    cp_wait<0>();
    __syncthreads();

    // cache Q fragments
    uint32_t qf[4][4];
    #pragma unroll
    for (int ks = 0; ks < 4; ks++) {
        uint32_t base = sb + AS_Q + rowQ * 128;
        ldmx4(qf[ks], base + (((ks * 2 + ccQ) ^ xQ) << 4));
    }

    float oacc[8][4];
    #pragma unroll
    for (int i = 0; i < 8; i++)
        #pragma unroll
        for (int q = 0; q < 4; q++) oacc[i][q] = 0.f;
    float m0 = -1e30f, m1 = -1e30f, l0 = 0.f, l1 = 0.f;

    int qg0 = qb * 128 + w * 16 + (lane >> 2);
    int qg1 = qg0 + 8;
    const float scale = 0.125f;

    for (int kt = 0; kt <= qb; kt++) {
        uint32_t kb = sb + ((kt & 1) ? AS_K1 : AS_K0);
        uint32_t vb = sb + ((kt & 1) ? AS_V1 : AS_V0);
        // prefetch next KV into the other buffer (its readers finished at the
        // barrier that ended the previous iteration)
        if (kt < qb) {
            uint32_t kb2 = sb + ((kt & 1) ? AS_K0 : AS_K1);
            uint32_t vb2 = sb + ((kt & 1) ? AS_V0 : AS_V1);
            stage_h(kb2, K, (kt + 1) * 128, h, tid);
            stage_h(vb2, V, (kt + 1) * 128, h, tid);
            cp_commit();
        }

        // ---- S = Q @ K^T ----
        float sacc[16][4];
        #pragma unroll
        for (int i = 0; i < 16; i++)
            #pragma unroll
            for (int q = 0; q < 4; q++) sacc[i][q] = 0.f;

        #pragma unroll
        for (int ks = 0; ks < 4; ks++) {
            #pragma unroll
            for (int nb = 0; nb < 8; nb++) {
                int rowK = nb * 16 + rowK_off;
                uint32_t bk[4];
                ldmx4(bk, kb + rowK * 128 + (((ks * 2 + ccK) ^ (rowK & 7)) << 4));
                mma16816h(sacc[nb * 2 + 0], qf[ks], &bk[0]);
                mma16816h(sacc[nb * 2 + 1], qf[ks], &bk[2]);
            }
        }
        #pragma unroll
        for (int nt = 0; nt < 16; nt++) {
            sacc[nt][0] *= scale; sacc[nt][1] *= scale;
            sacc[nt][2] *= scale; sacc[nt][3] *= scale;
        }

        // ---- causal mask on diagonal tile ----
        if (kt == qb) {
            #pragma unroll
            for (int nt = 0; nt < 16; nt++) {
                int kg = kt * 128 + nt * 8 + 2 * (lane & 3);
                #pragma unroll
                for (int e = 0; e < 2; e++) {
                    if (kg + e > qg0) sacc[nt][e]     = -1e30f;
                    if (kg + e > qg1) sacc[nt][2 + e] = -1e30f;
                }
            }
        }

        // ---- online softmax ----
        float rm0 = -1e30f, rm1 = -1e30f;
        #pragma unroll
        for (int nt = 0; nt < 16; nt++) {
            rm0 = fmaxf(rm0, fmaxf(sacc[nt][0], sacc[nt][1]));
            rm1 = fmaxf(rm1, fmaxf(sacc[nt][2], sacc[nt][3]));
        }
        rm0 = fmaxf(rm0, __shfl_xor_sync(0xFFFFFFFFu, rm0, 1));
        rm0 = fmaxf(rm0, __shfl_xor_sync(0xFFFFFFFFu, rm0, 2));
        rm1 = fmaxf(rm1, __shfl_xor_sync(0xFFFFFFFFu, rm1, 1));
        rm1 = fmaxf(rm1, __shfl_xor_sync(0xFFFFFFFFu, rm1, 2));
        float mn0 = fmaxf(m0, rm0), mn1 = fmaxf(m1, rm1);
        float al0 = __expf(m0 - mn0), al1 = __expf(m1 - mn1);
        m0 = mn0; m1 = mn1;

        float rs0 = 0.f, rs1 = 0.f;
        #pragma unroll
        for (int nt = 0; nt < 16; nt++) {
            sacc[nt][0] = __expf(sacc[nt][0] - mn0);
            sacc[nt][1] = __expf(sacc[nt][1] - mn0);
            sacc[nt][2] = __expf(sacc[nt][2] - mn1);
            sacc[nt][3] = __expf(sacc[nt][3] - mn1);
            rs0 += sacc[nt][0] + sacc[nt][1];
            rs1 += sacc[nt][2] + sacc[nt][3];
        }
        rs0 += __shfl_xor_sync(0xFFFFFFFFu, rs0, 1);
        rs0 += __shfl_xor_sync(0xFFFFFFFFu, rs0, 2);
        rs1 += __shfl_xor_sync(0xFFFFFFFFu, rs1, 1);
        rs1 += __shfl_xor_sync(0xFFFFFFFFu, rs1, 2);
        l0 = l0 * al0 + rs0;
        l1 = l1 * al1 + rs1;

        #pragma unroll
        for (int i = 0; i < 8; i++) {
            oacc[i][0] *= al0; oacc[i][1] *= al0;
            oacc[i][2] *= al1; oacc[i][3] *= al1;
        }

        // ---- O += P @ V ----
        #pragma unroll
        for (int ks2 = 0; ks2 < 8; ks2++) {
            uint32_t ap[4];
            ap[0] = packh2(sacc[2 * ks2][0],     sacc[2 * ks2][1]);
            ap[1] = packh2(sacc[2 * ks2][2],     sacc[2 * ks2][3]);
            ap[2] = packh2(sacc[2 * ks2 + 1][0], sacc[2 * ks2 + 1][1]);
            ap[3] = packh2(sacc[2 * ks2 + 1][2], sacc[2 * ks2 + 1][3]);
            int rowV = ks2 * 16 + rowV_off;
            uint32_t vbase = vb + rowV * 128;
            #pragma unroll
            for (int db = 0; db < 4; db++) {
                int cc = db * 2 + ccV_off;
                uint32_t bv[4];
                ldmx4t(bv, vbase + ((cc ^ (rowV & 7)) << 4));
                mma16816h(oacc[db * 2 + 0], ap, &bv[0]);
                mma16816h(oacc[db * 2 + 1], ap, &bv[2]);
            }
        }

        if (kt < qb) {
            cp_wait<0>();
            __syncthreads();
        }
    }

    float i0 = 1.0f / l0, i1 = 1.0f / l1;
    long gr0 = qb * 128 + w * 16 + (lane >> 2);
    long gc0 = h * HDIM + 2 * (lane & 3);
    #pragma unroll
    for (int nto = 0; nto < 8; nto++) {
        long gc = gc0 + nto * 8;
        *(uint32_t*)(O + gr0 * HID + gc)       = packh2(oacc[nto][0] * i0, oacc[nto][1] * i0);
        *(uint32_t*)(O + (gr0 + 8) * HID + gc) = packh2(oacc[nto][2] * i1, oacc[nto][3] * i1);
    }
}

// ======================= orchestration =======================
extern "C" void kernel_launch(void* const* d_in, const int* in_sizes, int n_in,
                              void* d_out, int out_size) {
    const float* emb = (const float*)d_in[0];
    const float* Wq = (const float*)d_in[2];
    const float* Wk = (const float*)d_in[3];
    const float* Wv = (const float*)d_in[4];
    const float* Wo = (const float*)d_in[5];
    const float* bo = (const float*)d_in[6];
    const float* W1 = (const float*)d_in[7];
    const float* W2 = (const float*)d_in[8];
    const float* b2 = (const float*)d_in[9];
    const float* g1 = (const float*)d_in[10];
    const float* g2 = (const float*)d_in[11];
    const float* gf = (const float*)d_in[12];
    float* out = (float*)d_out;

    float* px;
    __half *pq, *pk, *pv, *ph, *pctx, *pmid;
    __half *wq, *wk, *wv, *wo, *w1, *w2;
    cudaGetSymbolAddress((void**)&px,   g_x);
    cudaGetSymbolAddress((void**)&pq,   g_q);
    cudaGetSymbolAddress((void**)&pk,   g_k);
    cudaGetSymbolAddress((void**)&pv,   g_v);
    cudaGetSymbolAddress((void**)&ph,   g_h);
    cudaGetSymbolAddress((void**)&pctx, g_ctx);
    cudaGetSymbolAddress((void**)&pmid, g_mid);
    cudaGetSymbolAddress((void**)&wq, g_wqt);
    cudaGetSymbolAddress((void**)&wk, g_wkt);
    cudaGetSymbolAddress((void**)&wv, g_wvt);
    cudaGetSymbolAddress((void**)&wo, g_wot);
    cudaGetSymbolAddress((void**)&w1, g_w1t);
    cudaGetSymbolAddress((void**)&w2, g_w2t);

    cudaFuncSetAttribute(gemm_mma_kernel<0>, cudaFuncAttributeMaxDynamicSharedMemorySize, GSM_TOTAL);
    cudaFuncSetAttribute(gemm_mma_kernel<1>, cudaFuncAttributeMaxDynamicSharedMemorySize, GSM_TOTAL);
    cudaFuncSetAttribute(gemm_mma_kernel<2>, cudaFuncAttributeMaxDynamicSharedMemorySize, GSM_TOTAL);
    cudaFuncSetAttribute(attn_mma_kernel, cudaFuncAttributeMaxDynamicSharedMemorySize, AS_TOTAL);

    {
        int n4 = SEQ * HID / 4;
        copy_kernel<<<(n4 + 255) / 256, 256>>>((const float4*)emb, (float4*)px, n4);
    }

    {
        dim3 b(32, 8);
        dim3 gHH(HID / 32, HID / 32);
        dim3 gW1(ISZ / 32, HID / 32);
        dim3 gW2(HID / 32, ISZ / 32);
        for (int l = 0; l < NLAYER; l++) {
            long oHH = (long)l * HID * HID, oHI = (long)l * HID * ISZ;
            wsplit_kernel<<<gHH, b>>>(Wq + oHH, wq + oHH, HID, HID);
            wsplit_kernel<<<gHH, b>>>(Wk + oHH, wk + oHH, HID, HID);
            wsplit_kernel<<<gHH, b>>>(Wv + oHH, wv + oHH, HID, HID);
            wsplit_kernel<<<gHH, b>>>(Wo + oHH, wo + oHH, HID, HID);
            wsplit_kernel<<<gW1, b>>>(W1 + oHI, w1 + oHI, HID, ISZ);
            wsplit_kernel<<<gW2, b>>>(W2 + oHI, w2 + oHI, ISZ, HID);
        }
    }

    dim3 gAttn(SEQ / 128, NHEAD);
    const int ntHH = (HID / 128) * (SEQ / 128);          // 256
    const int ntQKV = ntHH * 3;                          // 768
    const int ntHI = (ISZ / 128) * (SEQ / 128);          // 1024
    int gQKV = ntQKV < PERSIST_GRID ? ntQKV : PERSIST_GRID;
    int gHH  = ntHH  < PERSIST_GRID ? ntHH  : PERSIST_GRID;
    int gHI  = ntHI  < PERSIST_GRID ? ntHI  : PERSIST_GRID;

    for (int l = 0; l < NLAYER; l++) {
        long oHH = (long)l * HID * HID, oHI = (long)l * HID * ISZ;

        ln_kernel<1><<<SEQ, 256>>>(px, g1 + l * HID, nullptr, ph);
        gemm_mma_kernel<0><<<gQKV, 256, GSM_TOTAL>>>(ph,
            wq + oHH, wk + oHH, wv + oHH,
            nullptr, nullptr, nullptr, pq, pk, pv,
            SEQ, HID, HID, HID / 128, SEQ / 128, 3);
        attn_mma_kernel<<<gAttn, 256, AS_TOTAL>>>(pq, pk, pv, pctx);
        gemm_mma_kernel<1><<<gHH, 256, GSM_TOTAL>>>(pctx,
            wo + oHH, nullptr, nullptr,
            bo + l * HID, px, px, nullptr, nullptr, nullptr,
            SEQ, HID, HID, HID / 128, SEQ / 128, 1);

        ln_kernel<1><<<SEQ, 256>>>(px, g2 + l * HID, nullptr, ph);
        gemm_mma_kernel<2><<<gHI, 256, GSM_TOTAL>>>(ph,
            w1 + oHI, nullptr, nullptr,
            nullptr, nullptr, nullptr, pmid, nullptr, nullptr,
            SEQ, ISZ, HID, ISZ / 128, SEQ / 128, 1);
        gemm_mma_kernel<1><<<gHH, 256, GSM_TOTAL>>>(pmid,
            w2 + oHI, nullptr, nullptr,
            b2 + l * HID, px, px, nullptr, nullptr, nullptr,
            SEQ, HID, ISZ, HID / 128, SEQ / 128, 1);
    }

    ln_kernel<0><<<SEQ, 256>>>(px, gf, out, nullptr);
}

// round 12
// speedup vs baseline: 8.4733x; 1.0575x over previous
#include <cuda_runtime.h>
#include <cuda_fp16.h>
#include <math.h>
#include <stdint.h>

#define SEQ 2048
#define HID 2048
#define NHEAD 32
#define HDIM 64
#define ISZ 8192
#define NLAYER 2

// ======================= scratch (static device arrays) =======================
__device__ float g_x  [SEQ * HID];
__device__ __half g_q  [SEQ * HID];
__device__ __half g_k  [SEQ * HID];
__device__ __half g_v  [SEQ * HID];
__device__ __half g_h  [SEQ * HID];
__device__ __half g_ctx[SEQ * HID];
__device__ __half g_mid[SEQ * ISZ];
// transposed weights: Wt[N][K], plain fp16
__device__ __half g_wqt[NLAYER * HID * HID];
__device__ __half g_wkt[NLAYER * HID * HID];
__device__ __half g_wvt[NLAYER * HID * HID];
__device__ __half g_wot[NLAYER * HID * HID];
__device__ __half g_w1t[NLAYER * HID * ISZ];
__device__ __half g_w2t[NLAYER * ISZ * HID];

// ======================= PTX helpers =======================
__device__ __forceinline__ uint32_t smem_u32(const void* p) {
    uint32_t a;
    asm("{ .reg .u64 t; cvta.to.shared.u64 t, %1; cvt.u32.u64 %0, t; }" : "=r"(a) : "l"(p));
    return a;
}
__device__ __forceinline__ void cp16(uint32_t dst, const void* src) {
    asm volatile("cp.async.cg.shared.global [%0], [%1], 16;" :: "r"(dst), "l"(src));
}
__device__ __forceinline__ void cp_commit() {
    asm volatile("cp.async.commit_group;" ::: "memory");
}
template <int N>
__device__ __forceinline__ void cp_wait() {
    asm volatile("cp.async.wait_group %0;" :: "n"(N) : "memory");
}
__device__ __forceinline__ void ldmx4(uint32_t* r, uint32_t addr) {
    asm volatile("ldmatrix.sync.aligned.m8n8.x4.shared.b16 {%0,%1,%2,%3}, [%4];"
                 : "=r"(r[0]), "=r"(r[1]), "=r"(r[2]), "=r"(r[3]) : "r"(addr));
}
__device__ __forceinline__ void ldmx4t(uint32_t* r, uint32_t addr) {
    asm volatile("ldmatrix.sync.aligned.m8n8.x4.trans.shared.b16 {%0,%1,%2,%3}, [%4];"
                 : "=r"(r[0]), "=r"(r[1]), "=r"(r[2]), "=r"(r[3]) : "r"(addr));
}
__device__ __forceinline__ void mma16816h(float* d, const uint32_t* a, const uint32_t* b) {
    asm volatile("mma.sync.aligned.m16n8k16.row.col.f32.f16.f16.f32 "
                 "{%0,%1,%2,%3}, {%4,%5,%6,%7}, {%8,%9}, {%0,%1,%2,%3};"
                 : "+f"(d[0]), "+f"(d[1]), "+f"(d[2]), "+f"(d[3])
                 : "r"(a[0]), "r"(a[1]), "r"(a[2]), "r"(a[3]), "r"(b[0]), "r"(b[1]));
}
__device__ __forceinline__ uint32_t packh2(float lo, float hi) {
    __half2 t = __floats2half2_rn(lo, hi);
    return *(uint32_t*)&t;
}

// ======================= small kernels =======================
__global__ void copy_kernel(const float4* __restrict__ in, float4* __restrict__ out, int n4) {
    int i = blockIdx.x * 256 + threadIdx.x;
    if (i < n4) out[i] = in[i];
}

__device__ __forceinline__ float gelu_tanh(float v) {
    float t = 0.7978845608028654f * v * (1.0f + 0.044715f * v * v);
    return 0.5f * v * (1.0f + tanhf(t));
}

template <int HALF>
__global__ void __launch_bounds__(256) ln_kernel(const float* __restrict__ x,
                                                 const float* __restrict__ gamma,
                                                 float* __restrict__ outf,
                                                 __half* __restrict__ oh) {
    __shared__ float sh[18];
    int row = blockIdx.x;
    const float* xr = x + (long)row * HID;
    float s = 0.f, s2 = 0.f;
    for (int i = threadIdx.x; i < HID; i += 256) {
        float v = xr[i];
        s += v; s2 += v * v;
    }
    #pragma unroll
    for (int o = 16; o; o >>= 1) {
        s  += __shfl_xor_sync(0xFFFFFFFFu, s,  o);
        s2 += __shfl_xor_sync(0xFFFFFFFFu, s2, o);
    }
    int w = threadIdx.x >> 5, lane = threadIdx.x & 31;
    if (lane == 0) { sh[w] = s; sh[8 + w] = s2; }
    __syncthreads();
    if (threadIdx.x < 32) {
        s  = (threadIdx.x < 8) ? sh[threadIdx.x]     : 0.f;
        s2 = (threadIdx.x < 8) ? sh[8 + threadIdx.x] : 0.f;
        #pragma unroll
        for (int o = 4; o; o >>= 1) {
            s  += __shfl_xor_sync(0xFFFFFFFFu, s,  o);
            s2 += __shfl_xor_sync(0xFFFFFFFFu, s2, o);
        }
        if (threadIdx.x == 0) {
            float mu = s * (1.0f / HID);
            float var = s2 * (1.0f / HID) - mu * mu;
            sh[16] = mu;
            sh[17] = rsqrtf(var + 1e-5f);
        }
    }
    __syncthreads();
    float mu = sh[16], inv = sh[17];
    for (int i = threadIdx.x; i < HID; i += 256) {
        float v = (xr[i] - mu) * inv * gamma[i];
        if (HALF) oh[(long)row * HID + i] = __float2half(v);
        else      outf[(long)row * HID + i] = v;
    }
}

// weight transpose: W[K,N] fp32 -> Th[N,K] fp16
__global__ void __launch_bounds__(256) wsplit_kernel(const float* __restrict__ W,
                                                     __half* __restrict__ Th,
                                                     int K, int N) {
    __shared__ float t[32][33];
    int bx = blockIdx.x * 32, by = blockIdx.y * 32;
    int tx = threadIdx.x, ty = threadIdx.y;
    #pragma unroll
    for (int i = 0; i < 4; i++)
        t[ty + i * 8][tx] = W[(long)(by + ty + i * 8) * N + bx + tx];
    __syncthreads();
    #pragma unroll
    for (int i = 0; i < 4; i++) {
        float v = t[tx][ty + i * 8];
        Th[(long)(bx + ty + i * 8) * K + by + tx] = __float2half(v);
    }
}

// ======================= persistent mma.sync fp16 GEMM (64x64 warp tiles) =======================
// C[M,N] = A[M,K] @ B^T, B stored [N,K] row-major fp16.
// BM=128, BN=128, BK=32; 4 warps (128 thr), warp tile 64x64; 4-stage cp.async (64KB), 2 CTA/SM.
// MODE 0: Ch = fp16(AB)  (z-fused, Ch0..2) ; MODE 1: Cf = AB + bias + res ; MODE 2: Ch = fp16(gelu(AB))
#define T_TILE 8192
#define STAGE_BYTES (2 * T_TILE)
#define NSTAGE 4
#define GSM_TOTAL (NSTAGE * STAGE_BYTES)
#define PERSIST_GRID 296

__device__ __forceinline__ void load_tile64(uint32_t sbase, const __half* __restrict__ P,
                                            int K, long k0, int tid) {
    // 128 threads: 4 iters x 128 = 512 chunks (128 rows x 4 chunks of 16B)
    #pragma unroll
    for (int i = 0; i < 4; i++) {
        int idx = tid + i * 128;
        int row = idx >> 2, c = idx & 3;
        const __half* src = P + (long)row * K + k0 + c * 8;
        uint32_t dst = sbase + row * 64 + ((c ^ ((row >> 1) & 3)) << 4);
        cp16(dst, src);
    }
}

template <int MODE>
__global__ void __launch_bounds__(128, 2) gemm_mma_kernel(
    const __half* __restrict__ A,
    const __half* __restrict__ B0, const __half* __restrict__ B1,
    const __half* __restrict__ B2,
    const float* __restrict__ bias, const float* res,
    float* Cf,
    __half* __restrict__ Ch0, __half* __restrict__ Ch1, __half* __restrict__ Ch2,
    int M, int N, int K, int ntx, int nty, int ntz)
{
    extern __shared__ char smem[];
    uint32_t sb = smem_u32(smem);
    int tid = threadIdx.x;
    int wid = tid >> 5, lane = tid & 31;
    int warp_m = wid >> 1, warp_n = wid & 1;     // 2 x 2 warps
    int m0 = warp_m * 64, n0 = warp_n * 64;

    int grp = lane >> 3, lr = lane & 7;
    int rowA0 = m0 + (grp & 1) * 8 + lr;
    int ccA   = grp >> 1;
    int rowB0 = n0 + (grp >> 1) * 8 + lr;
    int ccB   = grp & 1;
    int xA = (rowA0 >> 1) & 3;                   // invariant under +16
    int xB = (rowB0 >> 1) & 3;
    int nc = K / 32;
    int ntot = ntx * nty * ntz;

    for (int t = blockIdx.x; t < ntot; t += gridDim.x) {
        int z   = t / (ntx * nty);
        int rem = t - z * (ntx * nty);
        int by  = rem / ntx;
        int bx  = rem - by * ntx;
        int row0 = by * 128, col0 = bx * 128;

        const __half* B  = (z == 0) ? B0 : (z == 1) ? B1 : B2;
        __half* Ch = (z == 0) ? Ch0 : (z == 1) ? Ch1 : Ch2;

        const __half* pA = A + (long)row0 * K;
        const __half* pB = B + (long)col0 * K;

        float acc[4][8][4];
        #pragma unroll
        for (int i = 0; i < 4; i++)
            #pragma unroll
            for (int j = 0; j < 8; j++)
                #pragma unroll
                for (int q = 0; q < 4; q++) acc[i][j][q] = 0.f;

        __syncthreads();   // previous tile's readers done with smem

        #pragma unroll
        for (int p = 0; p < 3; p++) {
            uint32_t st = sb + p * STAGE_BYTES;
            load_tile64(st,          pA, K, (long)p * 32, tid);
            load_tile64(st + T_TILE, pB, K, (long)p * 32, tid);
            cp_commit();
        }

        int s_comp = 0, s_load = 3;
        for (int c = 0; c < nc; c++) {
            cp_wait<2>();
            __syncthreads();
            if (c + 3 < nc) {
                uint32_t st = sb + s_load * STAGE_BYTES;
                long k0 = (long)(c + 3) * 32;
                load_tile64(st,          pA, K, k0, tid);
                load_tile64(st + T_TILE, pB, K, k0, tid);
            }
            cp_commit();

            uint32_t sA = sb + s_comp * STAGE_BYTES;
            uint32_t sB = sA + T_TILE;
            #pragma unroll
            for (int ks = 0; ks < 2; ks++) {
                uint32_t af[4][4], bf[4][4];
                #pragma unroll
                for (int mt = 0; mt < 4; mt++) {
                    uint32_t base = sA + (rowA0 + mt * 16) * 64;
                    ldmx4(af[mt], base + (((ks * 2 + ccA) ^ xA) << 4));
                }
                #pragma unroll
                for (int np = 0; np < 4; np++) {
                    uint32_t base = sB + (rowB0 + np * 16) * 64;
                    ldmx4(bf[np], base + (((ks * 2 + ccB) ^ xB) << 4));
                }
                #pragma unroll
                for (int mt = 0; mt < 4; mt++)
                    #pragma unroll
                    for (int nt = 0; nt < 8; nt++)
                        mma16816h(acc[mt][nt], af[mt], &bf[nt >> 1][(nt & 1) * 2]);
            }
            s_comp = (s_comp + 1) & 3;
            s_load = (s_load + 1) & 3;
        }

        int r = lane >> 2, c2 = (lane & 3) * 2;
        #pragma unroll
        for (int mt = 0; mt < 4; mt++) {
            #pragma unroll
            for (int nt = 0; nt < 8; nt++) {
                long gr = row0 + m0 + mt * 16 + r;
                long gc = col0 + n0 + nt * 8 + c2;
                #pragma unroll
                for (int hrow = 0; hrow < 2; hrow++) {
                    long grr = gr + hrow * 8;
                    float v0 = acc[mt][nt][hrow * 2 + 0];
                    float v1 = acc[mt][nt][hrow * 2 + 1];
                    if (MODE == 0) {
                        *(uint32_t*)(Ch + grr * N + gc) = packh2(v0, v1);
                    } else if (MODE == 1) {
                        float2 b = *(const float2*)(bias + gc);
                        float2 rr = *(const float2*)(res + grr * N + gc);
                        *(float2*)(Cf + grr * N + gc) = make_float2(v0 + b.x + rr.x, v1 + b.y + rr.y);
                    } else {
                        *(uint32_t*)(Ch + grr * N + gc) = packh2(gelu_tanh(v0), gelu_tanh(v1));
                    }
                }
            }
        }
    }
}

// ======================= tensor-core flash attention (plain fp16) =======================
#define AS_Q  0
#define AS_K0 16384
#define AS_V0 32768
#define AS_K1 49152
#define AS_V1 65536
#define AS_TOTAL 81920

__device__ __forceinline__ void stage_h(uint32_t sbase, const __half* __restrict__ src,
                                        int row0, int h, int tid) {
    #pragma unroll
    for (int i = 0; i < 4; i++) {
        int idx = tid + i * 256;
        int r = idx >> 3, c = idx & 7;
        cp16(sbase + r * 128 + ((c ^ (r & 7)) << 4),
             src + (long)(row0 + r) * HID + h * HDIM + c * 8);
    }
}

__global__ void __launch_bounds__(256) attn_mma_kernel(
    const __half* __restrict__ Q, const __half* __restrict__ K,
    const __half* __restrict__ V, __half* __restrict__ O)
{
    extern __shared__ char smem[];
    uint32_t sb = smem_u32(smem);
    int tid = threadIdx.x;
    int w = tid >> 5, lane = tid & 31;
    int qb = blockIdx.x, h = blockIdx.y;

    int grp = lane >> 3, lr = lane & 7;
    int rowQ = w * 16 + (grp & 1) * 8 + lr;
    int ccQ  = grp >> 1;
    int xQ = rowQ & 7;
    int rowK_off = (grp >> 1) * 8 + lr;
    int ccK  = grp & 1;
    int rowV_off = (grp & 1) * 8 + lr;
    int ccV_off  = grp >> 1;

    stage_h(sb + AS_Q,  Q, qb * 128, h, tid);
    stage_h(sb + AS_K0, K, 0,        h, tid);
    stage_h(sb + AS_V0, V, 0,        h, tid);
    cp_commit();
    cp_wait<0>();
    __syncthreads();

    uint32_t qf[4][4];
    #pragma unroll
    for (int ks = 0; ks < 4; ks++) {
        uint32_t base = sb + AS_Q + rowQ * 128;
        ldmx4(qf[ks], base + (((ks * 2 + ccQ) ^ xQ) << 4));
    }

    float oacc[8][4];
    #pragma unroll
    for (int i = 0; i < 8; i++)
        #pragma unroll
        for (int q = 0; q < 4; q++) oacc[i][q] = 0.f;
    float m0 = -1e30f, m1 = -1e30f, l0 = 0.f, l1 = 0.f;

    int qg0 = qb * 128 + w * 16 + (lane >> 2);
    int qg1 = qg0 + 8;
    const float scale = 0.125f;

    for (int kt = 0; kt <= qb; kt++) {
        uint32_t kb = sb + ((kt & 1) ? AS_K1 : AS_K0);
        uint32_t vb = sb + ((kt & 1) ? AS_V1 : AS_V0);
        if (kt < qb) {
            uint32_t kb2 = sb + ((kt & 1) ? AS_K0 : AS_K1);
            uint32_t vb2 = sb + ((kt & 1) ? AS_V0 : AS_V1);
            stage_h(kb2, K, (kt + 1) * 128, h, tid);
            stage_h(vb2, V, (kt + 1) * 128, h, tid);
            cp_commit();
        }

        float sacc[16][4];
        #pragma unroll
        for (int i = 0; i < 16; i++)
            #pragma unroll
            for (int q = 0; q < 4; q++) sacc[i][q] = 0.f;

        #pragma unroll
        for (int ks = 0; ks < 4; ks++) {
            #pragma unroll
            for (int nb = 0; nb < 8; nb++) {
                int rowK = nb * 16 + rowK_off;
                uint32_t bk[4];
                ldmx4(bk, kb + rowK * 128 + (((ks * 2 + ccK) ^ (rowK & 7)) << 4));
                mma16816h(sacc[nb * 2 + 0], qf[ks], &bk[0]);
                mma16816h(sacc[nb * 2 + 1], qf[ks], &bk[2]);
            }
        }
        #pragma unroll
        for (int nt = 0; nt < 16; nt++) {
            sacc[nt][0] *= scale; sacc[nt][1] *= scale;
            sacc[nt][2] *= scale; sacc[nt][3] *= scale;
        }

        if (kt == qb) {
            #pragma unroll
            for (int nt = 0; nt < 16; nt++) {
                int kg = kt * 128 + nt * 8 + 2 * (lane & 3);
                #pragma unroll
                for (int e = 0; e < 2; e++) {
                    if (kg + e > qg0) sacc[nt][e]     = -1e30f;
                    if (kg + e > qg1) sacc[nt][2 + e] = -1e30f;
                }
            }
        }

        float rm0 = -1e30f, rm1 = -1e30f;
        #pragma unroll
        for (int nt = 0; nt < 16; nt++) {
            rm0 = fmaxf(rm0, fmaxf(sacc[nt][0], sacc[nt][1]));
            rm1 = fmaxf(rm1, fmaxf(sacc[nt][2], sacc[nt][3]));
        }
        rm0 = fmaxf(rm0, __shfl_xor_sync(0xFFFFFFFFu, rm0, 1));
        rm0 = fmaxf(rm0, __shfl_xor_sync(0xFFFFFFFFu, rm0, 2));
        rm1 = fmaxf(rm1, __shfl_xor_sync(0xFFFFFFFFu, rm1, 1));
        rm1 = fmaxf(rm1, __shfl_xor_sync(0xFFFFFFFFu, rm1, 2));
        float mn0 = fmaxf(m0, rm0), mn1 = fmaxf(m1, rm1);
        float al0 = __expf(m0 - mn0), al1 = __expf(m1 - mn1);
        m0 = mn0; m1 = mn1;

        float rs0 = 0.f, rs1 = 0.f;
        #pragma unroll
        for (int nt = 0; nt < 16; nt++) {
            sacc[nt][0] = __expf(sacc[nt][0] - mn0);
            sacc[nt][1] = __expf(sacc[nt][1] - mn0);
            sacc[nt][2] = __expf(sacc[nt][2] - mn1);
            sacc[nt][3] = __expf(sacc[nt][3] - mn1);
            rs0 += sacc[nt][0] + sacc[nt][1];
            rs1 += sacc[nt][2] + sacc[nt][3];
        }
        rs0 += __shfl_xor_sync(0xFFFFFFFFu, rs0, 1);
        rs0 += __shfl_xor_sync(0xFFFFFFFFu, rs0, 2);
        rs1 += __shfl_xor_sync(0xFFFFFFFFu, rs1, 1);
        rs1 += __shfl_xor_sync(0xFFFFFFFFu, rs1, 2);
        l0 = l0 * al0 + rs0;
        l1 = l1 * al1 + rs1;

        #pragma unroll
        for (int i = 0; i < 8; i++) {
            oacc[i][0] *= al0; oacc[i][1] *= al0;
            oacc[i][2] *= al1; oacc[i][3] *= al1;
        }

        #pragma unroll
        for (int ks2 = 0; ks2 < 8; ks2++) {
            uint32_t ap[4];
            ap[0] = packh2(sacc[2 * ks2][0],     sacc[2 * ks2][1]);
            ap[1] = packh2(sacc[2 * ks2][2],     sacc[2 * ks2][3]);
            ap[2] = packh2(sacc[2 * ks2 + 1][0], sacc[2 * ks2 + 1][1]);
            ap[3] = packh2(sacc[2 * ks2 + 1][2], sacc[2 * ks2 + 1][3]);
            int rowV = ks2 * 16 + rowV_off;
            uint32_t vbase = vb + rowV * 128;
            #pragma unroll
            for (int db = 0; db < 4; db++) {
                int cc = db * 2 + ccV_off;
                uint32_t bv[4];
                ldmx4t(bv, vbase + ((cc ^ (rowV & 7)) << 4));
                mma16816h(oacc[db * 2 + 0], ap, &bv[0]);
                mma16816h(oacc[db * 2 + 1], ap, &bv[2]);
            }
        }

        if (kt < qb) {
            cp_wait<0>();
            __syncthreads();
        }
    }

    float i0 = 1.0f / l0, i1 = 1.0f / l1;
    long gr0 = qb * 128 + w * 16 + (lane >> 2);
    long gc0 = h * HDIM + 2 * (lane & 3);
    #pragma unroll
    for (int nto = 0; nto < 8; nto++) {
        long gc = gc0 + nto * 8;
        *(uint32_t*)(O + gr0 * HID + gc)       = packh2(oacc[nto][0] * i0, oacc[nto][1] * i0);
        *(uint32_t*)(O + (gr0 + 8) * HID + gc) = packh2(oacc[nto][2] * i1, oacc[nto][3] * i1);
    }
}

// ======================= orchestration =======================
extern "C" void kernel_launch(void* const* d_in, const int* in_sizes, int n_in,
                              void* d_out, int out_size) {
    const float* emb = (const float*)d_in[0];
    const float* Wq = (const float*)d_in[2];
    const float* Wk = (const float*)d_in[3];
    const float* Wv = (const float*)d_in[4];
    const float* Wo = (const float*)d_in[5];
    const float* bo = (const float*)d_in[6];
    const float* W1 = (const float*)d_in[7];
    const float* W2 = (const float*)d_in[8];
    const float* b2 = (const float*)d_in[9];
    const float* g1 = (const float*)d_in[10];
    const float* g2 = (const float*)d_in[11];
    const float* gf = (const float*)d_in[12];
    float* out = (float*)d_out;

    float* px;
    __half *pq, *pk, *pv, *ph, *pctx, *pmid;
    __half *wq, *wk, *wv, *wo, *w1, *w2;
    cudaGetSymbolAddress((void**)&px,   g_x);
    cudaGetSymbolAddress((void**)&pq,   g_q);
    cudaGetSymbolAddress((void**)&pk,   g_k);
    cudaGetSymbolAddress((void**)&pv,   g_v);
    cudaGetSymbolAddress((void**)&ph,   g_h);
    cudaGetSymbolAddress((void**)&pctx, g_ctx);
    cudaGetSymbolAddress((void**)&pmid, g_mid);
    cudaGetSymbolAddress((void**)&wq, g_wqt);
    cudaGetSymbolAddress((void**)&wk, g_wkt);
    cudaGetSymbolAddress((void**)&wv, g_wvt);
    cudaGetSymbolAddress((void**)&wo, g_wot);
    cudaGetSymbolAddress((void**)&w1, g_w1t);
    cudaGetSymbolAddress((void**)&w2, g_w2t);

    cudaFuncSetAttribute(gemm_mma_kernel<0>, cudaFuncAttributeMaxDynamicSharedMemorySize, GSM_TOTAL);
    cudaFuncSetAttribute(gemm_mma_kernel<1>, cudaFuncAttributeMaxDynamicSharedMemorySize, GSM_TOTAL);
    cudaFuncSetAttribute(gemm_mma_kernel<2>, cudaFuncAttributeMaxDynamicSharedMemorySize, GSM_TOTAL);
    cudaFuncSetAttribute(attn_mma_kernel, cudaFuncAttributeMaxDynamicSharedMemorySize, AS_TOTAL);

    {
        int n4 = SEQ * HID / 4;
        copy_kernel<<<(n4 + 255) / 256, 256>>>((const float4*)emb, (float4*)px, n4);
    }

    {
        dim3 b(32, 8);
        dim3 gHH(HID / 32, HID / 32);
        dim3 gW1(ISZ / 32, HID / 32);
        dim3 gW2(HID / 32, ISZ / 32);
        for (int l = 0; l < NLAYER; l++) {
            long oHH = (long)l * HID * HID, oHI = (long)l * HID * ISZ;
            wsplit_kernel<<<gHH, b>>>(Wq + oHH, wq + oHH, HID, HID);
            wsplit_kernel<<<gHH, b>>>(Wk + oHH, wk + oHH, HID, HID);
            wsplit_kernel<<<gHH, b>>>(Wv + oHH, wv + oHH, HID, HID);
            wsplit_kernel<<<gHH, b>>>(Wo + oHH, wo + oHH, HID, HID);
            wsplit_kernel<<<gW1, b>>>(W1 + oHI, w1 + oHI, HID, ISZ);
            wsplit_kernel<<<gW2, b>>>(W2 + oHI, w2 + oHI, ISZ, HID);
        }
    }

    dim3 gAttn(SEQ / 128, NHEAD);
    const int ntHH = (HID / 128) * (SEQ / 128);          // 256
    const int ntQKV = ntHH * 3;                          // 768
    const int ntHI = (ISZ / 128) * (SEQ / 128);          // 1024
    int gQKV = ntQKV < PERSIST_GRID ? ntQKV : PERSIST_GRID;
    int gHH  = ntHH  < PERSIST_GRID ? ntHH  : PERSIST_GRID;
    int gHI  = ntHI  < PERSIST_GRID ? ntHI  : PERSIST_GRID;

    for (int l = 0; l < NLAYER; l++) {
        long oHH = (long)l * HID * HID, oHI = (long)l * HID * ISZ;

        ln_kernel<1><<<SEQ, 256>>>(px, g1 + l * HID, nullptr, ph);
        gemm_mma_kernel<0><<<gQKV, 128, GSM_TOTAL>>>(ph,
            wq + oHH, wk + oHH, wv + oHH,
            nullptr, nullptr, nullptr, pq, pk, pv,
            SEQ, HID, HID, HID / 128, SEQ / 128, 3);
        attn_mma_kernel<<<gAttn, 256, AS_TOTAL>>>(pq, pk, pv, pctx);
        gemm_mma_kernel<1><<<gHH, 128, GSM_TOTAL>>>(pctx,
            wo + oHH, nullptr, nullptr,
            bo + l * HID, px, px, nullptr, nullptr, nullptr,
            SEQ, HID, HID, HID / 128, SEQ / 128, 1);

        ln_kernel<1><<<SEQ, 256>>>(px, g2 + l * HID, nullptr, ph);
        gemm_mma_kernel<2><<<gHI, 128, GSM_TOTAL>>>(ph,
            w1 + oHI, nullptr, nullptr,
            nullptr, nullptr, nullptr, pmid, nullptr, nullptr,
            SEQ, ISZ, HID, ISZ / 128, SEQ / 128, 1);
        gemm_mma_kernel<1><<<gHH, 128, GSM_TOTAL>>>(pmid,
            w2 + oHI, nullptr, nullptr,
            b2 + l * HID, px, px, nullptr, nullptr, nullptr,
            SEQ, HID, ISZ, HID / 128, SEQ / 128, 1);
    }

    ln_kernel<0><<<SEQ, 256>>>(px, gf, out, nullptr);
}

// round 13
// speedup vs baseline: 8.8544x; 1.0450x over previous
#include <cuda_runtime.h>
#include <cuda_fp16.h>
#include <math.h>
#include <stdint.h>

#define SEQ 2048
#define HID 2048
#define NHEAD 32
#define HDIM 64
#define ISZ 8192
#define NLAYER 2

// ======================= scratch (static device arrays) =======================
__device__ float g_x  [SEQ * HID];
__device__ __half g_q  [SEQ * HID];
__device__ __half g_k  [SEQ * HID];
__device__ __half g_v  [SEQ * HID];
__device__ __half g_h  [SEQ * HID];
__device__ __half g_ctx[SEQ * HID];
__device__ __half g_mid[SEQ * ISZ];
// transposed weights: Wt[N][K], plain fp16
__device__ __half g_wqt[NLAYER * HID * HID];
__device__ __half g_wkt[NLAYER * HID * HID];
__device__ __half g_wvt[NLAYER * HID * HID];
__device__ __half g_wot[NLAYER * HID * HID];
__device__ __half g_w1t[NLAYER * HID * ISZ];
__device__ __half g_w2t[NLAYER * ISZ * HID];

// ======================= PTX helpers =======================
__device__ __forceinline__ uint32_t smem_u32(const void* p) {
    uint32_t a;
    asm("{ .reg .u64 t; cvta.to.shared.u64 t, %1; cvt.u32.u64 %0, t; }" : "=r"(a) : "l"(p));
    return a;
}
__device__ __forceinline__ void cp16(uint32_t dst, const void* src) {
    asm volatile("cp.async.cg.shared.global [%0], [%1], 16;" :: "r"(dst), "l"(src));
}
__device__ __forceinline__ void cp_commit() {
    asm volatile("cp.async.commit_group;" ::: "memory");
}
template <int N>
__device__ __forceinline__ void cp_wait() {
    asm volatile("cp.async.wait_group %0;" :: "n"(N) : "memory");
}
__device__ __forceinline__ void ldmx4(uint32_t* r, uint32_t addr) {
    asm volatile("ldmatrix.sync.aligned.m8n8.x4.shared.b16 {%0,%1,%2,%3}, [%4];"
                 : "=r"(r[0]), "=r"(r[1]), "=r"(r[2]), "=r"(r[3]) : "r"(addr));
}
__device__ __forceinline__ void ldmx4t(uint32_t* r, uint32_t addr) {
    asm volatile("ldmatrix.sync.aligned.m8n8.x4.trans.shared.b16 {%0,%1,%2,%3}, [%4];"
                 : "=r"(r[0]), "=r"(r[1]), "=r"(r[2]), "=r"(r[3]) : "r"(addr));
}
__device__ __forceinline__ void mma16816h(float* d, const uint32_t* a, const uint32_t* b) {
    asm volatile("mma.sync.aligned.m16n8k16.row.col.f32.f16.f16.f32 "
                 "{%0,%1,%2,%3}, {%4,%5,%6,%7}, {%8,%9}, {%0,%1,%2,%3};"
                 : "+f"(d[0]), "+f"(d[1]), "+f"(d[2]), "+f"(d[3])
                 : "r"(a[0]), "r"(a[1]), "r"(a[2]), "r"(a[3]), "r"(b[0]), "r"(b[1]));
}
__device__ __forceinline__ uint32_t packh2(float lo, float hi) {
    __half2 t = __floats2half2_rn(lo, hi);
    return *(uint32_t*)&t;
}

// ======================= small kernels =======================
__global__ void copy_kernel(const float4* __restrict__ in, float4* __restrict__ out, int n4) {
    int i = blockIdx.x * 256 + threadIdx.x;
    if (i < n4) out[i] = in[i];
}

__device__ __forceinline__ float gelu_tanh(float v) {
    float t = 0.7978845608028654f * v * (1.0f + 0.044715f * v * v);
    return 0.5f * v * (1.0f + tanhf(t));
}

// layernorm: single global read (values kept in registers), vectorized I/O
template <int HALF>
__global__ void __launch_bounds__(256) ln_kernel(const float* __restrict__ x,
                                                 const float* __restrict__ gamma,
                                                 float* __restrict__ outf,
                                                 __half* __restrict__ oh) {
    __shared__ float sh[18];
    int row = blockIdx.x;
    const float4* xr4 = (const float4*)(x + (long)row * HID);
    const float4* g4  = (const float4*)gamma;
    float4 v[2];
    float s = 0.f, s2 = 0.f;
    #pragma unroll
    for (int i = 0; i < 2; i++) {
        v[i] = xr4[threadIdx.x + i * 256];
        s  += v[i].x + v[i].y + v[i].z + v[i].w;
        s2 += v[i].x * v[i].x + v[i].y * v[i].y + v[i].z * v[i].z + v[i].w * v[i].w;
    }
    #pragma unroll
    for (int o = 16; o; o >>= 1) {
        s  += __shfl_xor_sync(0xFFFFFFFFu, s,  o);
        s2 += __shfl_xor_sync(0xFFFFFFFFu, s2, o);
    }
    int w = threadIdx.x >> 5, lane = threadIdx.x & 31;
    if (lane == 0) { sh[w] = s; sh[8 + w] = s2; }
    __syncthreads();
    if (threadIdx.x < 32) {
        s  = (threadIdx.x < 8) ? sh[threadIdx.x]     : 0.f;
        s2 = (threadIdx.x < 8) ? sh[8 + threadIdx.x] : 0.f;
        #pragma unroll
        for (int o = 4; o; o >>= 1) {
            s  += __shfl_xor_sync(0xFFFFFFFFu, s,  o);
            s2 += __shfl_xor_sync(0xFFFFFFFFu, s2, o);
        }
        if (threadIdx.x == 0) {
            float mu = s * (1.0f / HID);
            float var = s2 * (1.0f / HID) - mu * mu;
            sh[16] = mu;
            sh[17] = rsqrtf(var + 1e-5f);
        }
    }
    __syncthreads();
    float mu = sh[16], inv = sh[17];
    #pragma unroll
    for (int i = 0; i < 2; i++) {
        int i4 = threadIdx.x + i * 256;
        float4 g = g4[i4];
        float a = (v[i].x - mu) * inv * g.x;
        float b = (v[i].y - mu) * inv * g.y;
        float c = (v[i].z - mu) * inv * g.z;
        float d = (v[i].w - mu) * inv * g.w;
        if (HALF) {
            uint2 p;
            p.x = packh2(a, b);
            p.y = packh2(c, d);
            *(uint2*)(oh + (long)row * HID + i4 * 4) = p;
        } else {
            *(float4*)(outf + (long)row * HID + i4 * 4) = make_float4(a, b, c, d);
        }
    }
}

// weight transpose: W[K,N] fp32 -> Th[N,K] fp16.
// Tile 64(K) x 32(N), 256 threads; coalesced float loads, coalesced __half2 stores.
__global__ void __launch_bounds__(256) wsplit_kernel(const float* __restrict__ W,
                                                     __half* __restrict__ Th,
                                                     int K, int N) {
    __shared__ float t[64][33];
    int bx = blockIdx.x * 32;   // N offset
    int by = blockIdx.y * 64;   // K offset
    int tid = threadIdx.x;
    int c = tid & 31, r0 = tid >> 5;
    #pragma unroll
    for (int i = 0; i < 8; i++)
        t[r0 + i * 8][c] = W[(long)(by + r0 + i * 8) * N + bx + c];
    __syncthreads();
    int kp = tid & 31, n0 = tid >> 5;
    #pragma unroll
    for (int i = 0; i < 4; i++) {
        int n = n0 + i * 8;
        __half2 v = __floats2half2_rn(t[kp * 2][n], t[kp * 2 + 1][n]);
        *(__half2*)(Th + (long)(bx + n) * K + by + kp * 2) = v;
    }
}

// ======================= persistent mma.sync fp16 GEMM (64x64 warp tiles) =======================
#define T_TILE 8192
#define STAGE_BYTES (2 * T_TILE)
#define NSTAGE 4
#define GSM_TOTAL (NSTAGE * STAGE_BYTES)
#define PERSIST_GRID 296

__device__ __forceinline__ void load_tile64(uint32_t sbase, const __half* __restrict__ P,
                                            int K, long k0, int tid) {
    #pragma unroll
    for (int i = 0; i < 4; i++) {
        int idx = tid + i * 128;
        int row = idx >> 2, c = idx & 3;
        const __half* src = P + (long)row * K + k0 + c * 8;
        uint32_t dst = sbase + row * 64 + ((c ^ ((row >> 1) & 3)) << 4);
        cp16(dst, src);
    }
}

template <int MODE>
__global__ void __launch_bounds__(128, 2) gemm_mma_kernel(
    const __half* __restrict__ A,
    const __half* __restrict__ B0, const __half* __restrict__ B1,
    const __half* __restrict__ B2,
    const float* __restrict__ bias, const float* res,
    float* Cf,
    __half* __restrict__ Ch0, __half* __restrict__ Ch1, __half* __restrict__ Ch2,
    int M, int N, int K, int ntx, int nty, int ntz)
{
    extern __shared__ char smem[];
    uint32_t sb = smem_u32(smem);
    int tid = threadIdx.x;
    int wid = tid >> 5, lane = tid & 31;
    int warp_m = wid >> 1, warp_n = wid & 1;
    int m0 = warp_m * 64, n0 = warp_n * 64;

    int grp = lane >> 3, lr = lane & 7;
    int rowA0 = m0 + (grp & 1) * 8 + lr;
    int ccA   = grp >> 1;
    int rowB0 = n0 + (grp >> 1) * 8 + lr;
    int ccB   = grp & 1;
    int xA = (rowA0 >> 1) & 3;
    int xB = (rowB0 >> 1) & 3;
    int nc = K / 32;
    int ntot = ntx * nty * ntz;

    for (int t = blockIdx.x; t < ntot; t += gridDim.x) {
        int z   = t / (ntx * nty);
        int rem = t - z * (ntx * nty);
        int by  = rem / ntx;
        int bx  = rem - by * ntx;
        int row0 = by * 128, col0 = bx * 128;

        const __half* B  = (z == 0) ? B0 : (z == 1) ? B1 : B2;
        __half* Ch = (z == 0) ? Ch0 : (z == 1) ? Ch1 : Ch2;

        const __half* pA = A + (long)row0 * K;
        const __half* pB = B + (long)col0 * K;

        float acc[4][8][4];
        #pragma unroll
        for (int i = 0; i < 4; i++)
            #pragma unroll
            for (int j = 0; j < 8; j++)
                #pragma unroll
                for (int q = 0; q < 4; q++) acc[i][j][q] = 0.f;

        __syncthreads();

        #pragma unroll
        for (int p = 0; p < 3; p++) {
            uint32_t st = sb + p * STAGE_BYTES;
            load_tile64(st,          pA, K, (long)p * 32, tid);
            load_tile64(st + T_TILE, pB, K, (long)p * 32, tid);
            cp_commit();
        }

        int s_comp = 0, s_load = 3;
        for (int c = 0; c < nc; c++) {
            cp_wait<2>();
            __syncthreads();
            if (c + 3 < nc) {
                uint32_t st = sb + s_load * STAGE_BYTES;
                long k0 = (long)(c + 3) * 32;
                load_tile64(st,          pA, K, k0, tid);
                load_tile64(st + T_TILE, pB, K, k0, tid);
            }
            cp_commit();

            uint32_t sA = sb + s_comp * STAGE_BYTES;
            uint32_t sB = sA + T_TILE;
            #pragma unroll
            for (int ks = 0; ks < 2; ks++) {
                uint32_t af[4][4], bf[4][4];
                #pragma unroll
                for (int mt = 0; mt < 4; mt++) {
                    uint32_t base = sA + (rowA0 + mt * 16) * 64;
                    ldmx4(af[mt], base + (((ks * 2 + ccA) ^ xA) << 4));
                }
                #pragma unroll
                for (int np = 0; np < 4; np++) {
                    uint32_t base = sB + (rowB0 + np * 16) * 64;
                    ldmx4(bf[np], base + (((ks * 2 + ccB) ^ xB) << 4));
                }
                #pragma unroll
                for (int mt = 0; mt < 4; mt++)
                    #pragma unroll
                    for (int nt = 0; nt < 8; nt++)
                        mma16816h(acc[mt][nt], af[mt], &bf[nt >> 1][(nt & 1) * 2]);
            }
            s_comp = (s_comp + 1) & 3;
            s_load = (s_load + 1) & 3;
        }

        int r = lane >> 2, c2 = (lane & 3) * 2;
        #pragma unroll
        for (int mt = 0; mt < 4; mt++) {
            #pragma unroll
            for (int nt = 0; nt < 8; nt++) {
                long gr = row0 + m0 + mt * 16 + r;
                long gc = col0 + n0 + nt * 8 + c2;
                #pragma unroll
                for (int hrow = 0; hrow < 2; hrow++) {
                    long grr = gr + hrow * 8;
                    float v0 = acc[mt][nt][hrow * 2 + 0];
                    float v1 = acc[mt][nt][hrow * 2 + 1];
                    if (MODE == 0) {
                        *(uint32_t*)(Ch + grr * N + gc) = packh2(v0, v1);
                    } else if (MODE == 1) {
                        float2 b = *(const float2*)(bias + gc);
                        float2 rr = *(const float2*)(res + grr * N + gc);
                        *(float2*)(Cf + grr * N + gc) = make_float2(v0 + b.x + rr.x, v1 + b.y + rr.y);
                    } else {
                        *(uint32_t*)(Ch + grr * N + gc) = packh2(gelu_tanh(v0), gelu_tanh(v1));
                    }
                }
            }
        }
    }
}

// ======================= tensor-core flash attention (plain fp16) =======================
#define AS_Q  0
#define AS_K0 16384
#define AS_V0 32768
#define AS_K1 49152
#define AS_V1 65536
#define AS_TOTAL 81920

__device__ __forceinline__ void stage_h(uint32_t sbase, const __half* __restrict__ src,
                                        int row0, int h, int tid) {
    #pragma unroll
    for (int i = 0; i < 4; i++) {
        int idx = tid + i * 256;
        int r = idx >> 3, c = idx & 7;
        cp16(sbase + r * 128 + ((c ^ (r & 7)) << 4),
             src + (long)(row0 + r) * HID + h * HDIM + c * 8);
    }
}

__global__ void __launch_bounds__(256) attn_mma_kernel(
    const __half* __restrict__ Q, const __half* __restrict__ K,
    const __half* __restrict__ V, __half* __restrict__ O)
{
    extern __shared__ char smem[];
    uint32_t sb = smem_u32(smem);
    int tid = threadIdx.x;
    int w = tid >> 5, lane = tid & 31;
    int qb = blockIdx.x, h = blockIdx.y;

    int grp = lane >> 3, lr = lane & 7;
    int rowQ = w * 16 + (grp & 1) * 8 + lr;
    int ccQ  = grp >> 1;
    int xQ = rowQ & 7;
    int rowK_off = (grp >> 1) * 8 + lr;
    int ccK  = grp & 1;
    int rowV_off = (grp & 1) * 8 + lr;
    int ccV_off  = grp >> 1;

    stage_h(sb + AS_Q,  Q, qb * 128, h, tid);
    stage_h(sb + AS_K0, K, 0,        h, tid);
    stage_h(sb + AS_V0, V, 0,        h, tid);
    cp_commit();
    cp_wait<0>();
    __syncthreads();

    uint32_t qf[4][4];
    #pragma unroll
    for (int ks = 0; ks < 4; ks++) {
        uint32_t base = sb + AS_Q + rowQ * 128;
        ldmx4(qf[ks], base + (((ks * 2 + ccQ) ^ xQ) << 4));
    }

    float oacc[8][4];
    #pragma unroll
    for (int i = 0; i < 8; i++)
        #pragma unroll
        for (int q = 0; q < 4; q++) oacc[i][q] = 0.f;
    float m0 = -1e30f, m1 = -1e30f, l0 = 0.f, l1 = 0.f;

    int qg0 = qb * 128 + w * 16 + (lane >> 2);
    int qg1 = qg0 + 8;
    const float scale = 0.125f;

    for (int kt = 0; kt <= qb; kt++) {
        uint32_t kb = sb + ((kt & 1) ? AS_K1 : AS_K0);
        uint32_t vb = sb + ((kt & 1) ? AS_V1 : AS_V0);
        if (kt < qb) {
            uint32_t kb2 = sb + ((kt & 1) ? AS_K0 : AS_K1);
            uint32_t vb2 = sb + ((kt & 1) ? AS_V0 : AS_V1);
            stage_h(kb2, K, (kt + 1) * 128, h, tid);
            stage_h(vb2, V, (kt + 1) * 128, h, tid);
            cp_commit();
        }

        float sacc[16][4];
        #pragma unroll
        for (int i = 0; i < 16; i++)
            #pragma unroll
            for (int q = 0; q < 4; q++) sacc[i][q] = 0.f;

        #pragma unroll
        for (int ks = 0; ks < 4; ks++) {
            #pragma unroll
            for (int nb = 0; nb < 8; nb++) {
                int rowK = nb * 16 + rowK_off;
                uint32_t bk[4];
                ldmx4(bk, kb + rowK * 128 + (((ks * 2 + ccK) ^ (rowK & 7)) << 4));
                mma16816h(sacc[nb * 2 + 0], qf[ks], &bk[0]);
                mma16816h(sacc[nb * 2 + 1], qf[ks], &bk[2]);
            }
        }
        #pragma unroll
        for (int nt = 0; nt < 16; nt++) {
            sacc[nt][0] *= scale; sacc[nt][1] *= scale;
            sacc[nt][2] *= scale; sacc[nt][3] *= scale;
        }

        if (kt == qb) {
            #pragma unroll
            for (int nt = 0; nt < 16; nt++) {
                int kg = kt * 128 + nt * 8 + 2 * (lane & 3);
                #pragma unroll
                for (int e = 0; e < 2; e++) {
                    if (kg + e > qg0) sacc[nt][e]     = -1e30f;
                    if (kg + e > qg1) sacc[nt][2 + e] = -1e30f;
                }
            }
        }

        float rm0 = -1e30f, rm1 = -1e30f;
        #pragma unroll
        for (int nt = 0; nt < 16; nt++) {
            rm0 = fmaxf(rm0, fmaxf(sacc[nt][0], sacc[nt][1]));
            rm1 = fmaxf(rm1, fmaxf(sacc[nt][2], sacc[nt][3]));
        }
        rm0 = fmaxf(rm0, __shfl_xor_sync(0xFFFFFFFFu, rm0, 1));
        rm0 = fmaxf(rm0, __shfl_xor_sync(0xFFFFFFFFu, rm0, 2));
        rm1 = fmaxf(rm1, __shfl_xor_sync(0xFFFFFFFFu, rm1, 1));
        rm1 = fmaxf(rm1, __shfl_xor_sync(0xFFFFFFFFu, rm1, 2));
        float mn0 = fmaxf(m0, rm0), mn1 = fmaxf(m1, rm1);
        float al0 = __expf(m0 - mn0), al1 = __expf(m1 - mn1);
        m0 = mn0; m1 = mn1;

        float rs0 = 0.f, rs1 = 0.f;
        #pragma unroll
        for (int nt = 0; nt < 16; nt++) {
            sacc[nt][0] = __expf(sacc[nt][0] - mn0);
            sacc[nt][1] = __expf(sacc[nt][1] - mn0);
            sacc[nt][2] = __expf(sacc[nt][2] - mn1);
            sacc[nt][3] = __expf(sacc[nt][3] - mn1);
            rs0 += sacc[nt][0] + sacc[nt][1];
            rs1 += sacc[nt][2] + sacc[nt][3];
        }
        rs0 += __shfl_xor_sync(0xFFFFFFFFu, rs0, 1);
        rs0 += __shfl_xor_sync(0xFFFFFFFFu, rs0, 2);
        rs1 += __shfl_xor_sync(0xFFFFFFFFu, rs1, 1);
        rs1 += __shfl_xor_sync(0xFFFFFFFFu, rs1, 2);
        l0 = l0 * al0 + rs0;
        l1 = l1 * al1 + rs1;

        #pragma unroll
        for (int i = 0; i < 8; i++) {
            oacc[i][0] *= al0; oacc[i][1] *= al0;
            oacc[i][2] *= al1; oacc[i][3] *= al1;
        }

        #pragma unroll
        for (int ks2 = 0; ks2 < 8; ks2++) {
            uint32_t ap[4];
            ap[0] = packh2(sacc[2 * ks2][0],     sacc[2 * ks2][1]);
            ap[1] = packh2(sacc[2 * ks2][2],     sacc[2 * ks2][3]);
            ap[2] = packh2(sacc[2 * ks2 + 1][0], sacc[2 * ks2 + 1][1]);
            ap[3] = packh2(sacc[2 * ks2 + 1][2], sacc[2 * ks2 + 1][3]);
            int rowV = ks2 * 16 + rowV_off;
            uint32_t vbase = vb + rowV * 128;
            #pragma unroll
            for (int db = 0; db < 4; db++) {
                int cc = db * 2 + ccV_off;
                uint32_t bv[4];
                ldmx4t(bv, vbase + ((cc ^ (rowV & 7)) << 4));
                mma16816h(oacc[db * 2 + 0], ap, &bv[0]);
                mma16816h(oacc[db * 2 + 1], ap, &bv[2]);
            }
        }

        if (kt < qb) {
            cp_wait<0>();
            __syncthreads();
        }
    }

    float i0 = 1.0f / l0, i1 = 1.0f / l1;
    long gr0 = qb * 128 + w * 16 + (lane >> 2);
    long gc0 = h * HDIM + 2 * (lane & 3);
    #pragma unroll
    for (int nto = 0; nto < 8; nto++) {
        long gc = gc0 + nto * 8;
        *(uint32_t*)(O + gr0 * HID + gc)       = packh2(oacc[nto][0] * i0, oacc[nto][1] * i0);
        *(uint32_t*)(O + (gr0 + 8) * HID + gc) = packh2(oacc[nto][2] * i1, oacc[nto][3] * i1);
    }
}

// ======================= orchestration =======================
extern "C" void kernel_launch(void* const* d_in, const int* in_sizes, int n_in,
                              void* d_out, int out_size) {
    const float* emb = (const float*)d_in[0];
    const float* Wq = (const float*)d_in[2];
    const float* Wk = (const float*)d_in[3];
    const float* Wv = (const float*)d_in[4];
    const float* Wo = (const float*)d_in[5];
    const float* bo = (const float*)d_in[6];
    const float* W1 = (const float*)d_in[7];
    const float* W2 = (const float*)d_in[8];
    const float* b2 = (const float*)d_in[9];
    const float* g1 = (const float*)d_in[10];
    const float* g2 = (const float*)d_in[11];
    const float* gf = (const float*)d_in[12];
    float* out = (float*)d_out;

    float* px;
    __half *pq, *pk, *pv, *ph, *pctx, *pmid;
    __half *wq, *wk, *wv, *wo, *w1, *w2;
    cudaGetSymbolAddress((void**)&px,   g_x);
    cudaGetSymbolAddress((void**)&pq,   g_q);
    cudaGetSymbolAddress((void**)&pk,   g_k);
    cudaGetSymbolAddress((void**)&pv,   g_v);
    cudaGetSymbolAddress((void**)&ph,   g_h);
    cudaGetSymbolAddress((void**)&pctx, g_ctx);
    cudaGetSymbolAddress((void**)&pmid, g_mid);
    cudaGetSymbolAddress((void**)&wq, g_wqt);
    cudaGetSymbolAddress((void**)&wk, g_wkt);
    cudaGetSymbolAddress((void**)&wv, g_wvt);
    cudaGetSymbolAddress((void**)&wo, g_wot);
    cudaGetSymbolAddress((void**)&w1, g_w1t);
    cudaGetSymbolAddress((void**)&w2, g_w2t);

    cudaFuncSetAttribute(gemm_mma_kernel<0>, cudaFuncAttributeMaxDynamicSharedMemorySize, GSM_TOTAL);
    cudaFuncSetAttribute(gemm_mma_kernel<1>, cudaFuncAttributeMaxDynamicSharedMemorySize, GSM_TOTAL);
    cudaFuncSetAttribute(gemm_mma_kernel<2>, cudaFuncAttributeMaxDynamicSharedMemorySize, GSM_TOTAL);
    cudaFuncSetAttribute(attn_mma_kernel, cudaFuncAttributeMaxDynamicSharedMemorySize, AS_TOTAL);

    {
        int n4 = SEQ * HID / 4;
        copy_kernel<<<(n4 + 255) / 256, 256>>>((const float4*)emb, (float4*)px, n4);
    }

    {
        // wsplit grid: (N/32, K/64)
        dim3 gHH(HID / 32, HID / 64);
        dim3 gW1(ISZ / 32, HID / 64);
        dim3 gW2(HID / 32, ISZ / 64);
        for (int l = 0; l < NLAYER; l++) {
            long oHH = (long)l * HID * HID, oHI = (long)l * HID * ISZ;
            wsplit_kernel<<<gHH, 256>>>(Wq + oHH, wq + oHH, HID, HID);
            wsplit_kernel<<<gHH, 256>>>(Wk + oHH, wk + oHH, HID, HID);
            wsplit_kernel<<<gHH, 256>>>(Wv + oHH, wv + oHH, HID, HID);
            wsplit_kernel<<<gHH, 256>>>(Wo + oHH, wo + oHH, HID, HID);
            wsplit_kernel<<<gW1, 256>>>(W1 + oHI, w1 + oHI, HID, ISZ);
            wsplit_kernel<<<gW2, 256>>>(W2 + oHI, w2 + oHI, ISZ, HID);
        }
    }

    dim3 gAttn(SEQ / 128, NHEAD);
    const int ntHH = (HID / 128) * (SEQ / 128);
    const int ntQKV = ntHH * 3;
    const int ntHI = (ISZ / 128) * (SEQ / 128);
    int gQKV = ntQKV < PERSIST_GRID ? ntQKV : PERSIST_GRID;
    int gHH  = ntHH  < PERSIST_GRID ? ntHH  : PERSIST_GRID;
    int gHI  = ntHI  < PERSIST_GRID ? ntHI  : PERSIST_GRID;

    for (int l = 0; l < NLAYER; l++) {
        long oHH = (long)l * HID * HID, oHI = (long)l * HID * ISZ;

        ln_kernel<1><<<SEQ, 256>>>(px, g1 + l * HID, nullptr, ph);
        gemm_mma_kernel<0><<<gQKV, 128, GSM_TOTAL>>>(ph,
            wq + oHH, wk + oHH, wv + oHH,
            nullptr, nullptr, nullptr, pq, pk, pv,
            SEQ, HID, HID, HID / 128, SEQ / 128, 3);
        attn_mma_kernel<<<gAttn, 256, AS_TOTAL>>>(pq, pk, pv, pctx);
        gemm_mma_kernel<1><<<gHH, 128, GSM_TOTAL>>>(pctx,
            wo + oHH, nullptr, nullptr,
            bo + l * HID, px, px, nullptr, nullptr, nullptr,
            SEQ, HID, HID, HID / 128, SEQ / 128, 1);

        ln_kernel<1><<<SEQ, 256>>>(px, g2 + l * HID, nullptr, ph);
        gemm_mma_kernel<2><<<gHI, 128, GSM_TOTAL>>>(ph,
            w1 + oHI, nullptr, nullptr,
            nullptr, nullptr, nullptr, pmid, nullptr, nullptr,
            SEQ, ISZ, HID, ISZ / 128, SEQ / 128, 1);
        gemm_mma_kernel<1><<<gHH, 128, GSM_TOTAL>>>(pmid,
            w2 + oHI, nullptr, nullptr,
            b2 + l * HID, px, px, nullptr, nullptr, nullptr,
            SEQ, HID, ISZ, HID / 128, SEQ / 128, 1);
    }

    ln_kernel<0><<<SEQ, 256>>>(px, gf, out, nullptr);
}

// round 14
// speedup vs baseline: 9.0183x; 1.0185x over previous
#include <cuda_runtime.h>
#include <cuda_fp16.h>
#include <math.h>
#include <stdint.h>

#define SEQ 2048
#define HID 2048
#define NHEAD 32
#define HDIM 64
#define ISZ 8192
#define NLAYER 2

// ======================= scratch (static device arrays) =======================
__device__ float g_x  [SEQ * HID];
__device__ __half g_q  [SEQ * HID];
__device__ __half g_k  [SEQ * HID];
__device__ __half g_v  [SEQ * HID];
__device__ __half g_h  [SEQ * HID];
__device__ __half g_ctx[SEQ * HID];
__device__ __half g_mid[SEQ * ISZ];
// transposed weights: Wt[N][K], plain fp16
__device__ __half g_wqt[NLAYER * HID * HID];
__device__ __half g_wkt[NLAYER * HID * HID];
__device__ __half g_wvt[NLAYER * HID * HID];
__device__ __half g_wot[NLAYER * HID * HID];
__device__ __half g_w1t[NLAYER * HID * ISZ];
__device__ __half g_w2t[NLAYER * ISZ * HID];

// ======================= PTX helpers =======================
__device__ __forceinline__ uint32_t smem_u32(const void* p) {
    uint32_t a;
    asm("{ .reg .u64 t; cvta.to.shared.u64 t, %1; cvt.u32.u64 %0, t; }" : "=r"(a) : "l"(p));
    return a;
}
__device__ __forceinline__ void cp16(uint32_t dst, const void* src) {
    asm volatile("cp.async.cg.shared.global [%0], [%1], 16;" :: "r"(dst), "l"(src));
}
__device__ __forceinline__ void cp_commit() {
    asm volatile("cp.async.commit_group;" ::: "memory");
}
template <int N>
__device__ __forceinline__ void cp_wait() {
    asm volatile("cp.async.wait_group %0;" :: "n"(N) : "memory");
}
__device__ __forceinline__ void ldmx4(uint32_t* r, uint32_t addr) {
    asm volatile("ldmatrix.sync.aligned.m8n8.x4.shared.b16 {%0,%1,%2,%3}, [%4];"
                 : "=r"(r[0]), "=r"(r[1]), "=r"(r[2]), "=r"(r[3]) : "r"(addr));
}
__device__ __forceinline__ void ldmx4t(uint32_t* r, uint32_t addr) {
    asm volatile("ldmatrix.sync.aligned.m8n8.x4.trans.shared.b16 {%0,%1,%2,%3}, [%4];"
                 : "=r"(r[0]), "=r"(r[1]), "=r"(r[2]), "=r"(r[3]) : "r"(addr));
}
__device__ __forceinline__ void mma16816h(float* d, const uint32_t* a, const uint32_t* b) {
    asm volatile("mma.sync.aligned.m16n8k16.row.col.f32.f16.f16.f32 "
                 "{%0,%1,%2,%3}, {%4,%5,%6,%7}, {%8,%9}, {%0,%1,%2,%3};"
                 : "+f"(d[0]), "+f"(d[1]), "+f"(d[2]), "+f"(d[3])
                 : "r"(a[0]), "r"(a[1]), "r"(a[2]), "r"(a[3]), "r"(b[0]), "r"(b[1]));
}
__device__ __forceinline__ uint32_t packh2(float lo, float hi) {
    __half2 t = __floats2half2_rn(lo, hi);
    return *(uint32_t*)&t;
}

// ======================= small kernels =======================
__device__ __forceinline__ float gelu_tanh(float v) {
    float t = 0.7978845608028654f * v * (1.0f + 0.044715f * v * v);
    return 0.5f * v * (1.0f + tanhf(t));
}

// layernorm: single global read (values in registers), vectorized I/O
template <int HALF>
__global__ void __launch_bounds__(256) ln_kernel(const float* __restrict__ x,
                                                 const float* __restrict__ gamma,
                                                 float* __restrict__ outf,
                                                 __half* __restrict__ oh) {
    __shared__ float sh[18];
    int row = blockIdx.x;
    const float4* xr4 = (const float4*)(x + (long)row * HID);
    const float4* g4  = (const float4*)gamma;
    float4 v[2];
    float s = 0.f, s2 = 0.f;
    #pragma unroll
    for (int i = 0; i < 2; i++) {
        v[i] = xr4[threadIdx.x + i * 256];
        s  += v[i].x + v[i].y + v[i].z + v[i].w;
        s2 += v[i].x * v[i].x + v[i].y * v[i].y + v[i].z * v[i].z + v[i].w * v[i].w;
    }
    #pragma unroll
    for (int o = 16; o; o >>= 1) {
        s  += __shfl_xor_sync(0xFFFFFFFFu, s,  o);
        s2 += __shfl_xor_sync(0xFFFFFFFFu, s2, o);
    }
    int w = threadIdx.x >> 5, lane = threadIdx.x & 31;
    if (lane == 0) { sh[w] = s; sh[8 + w] = s2; }
    __syncthreads();
    if (threadIdx.x < 32) {
        s  = (threadIdx.x < 8) ? sh[threadIdx.x]     : 0.f;
        s2 = (threadIdx.x < 8) ? sh[8 + threadIdx.x] : 0.f;
        #pragma unroll
        for (int o = 4; o; o >>= 1) {
            s  += __shfl_xor_sync(0xFFFFFFFFu, s,  o);
            s2 += __shfl_xor_sync(0xFFFFFFFFu, s2, o);
        }
        if (threadIdx.x == 0) {
            float mu = s * (1.0f / HID);
            float var = s2 * (1.0f / HID) - mu * mu;
            sh[16] = mu;
            sh[17] = rsqrtf(var + 1e-5f);
        }
    }
    __syncthreads();
    float mu = sh[16], inv = sh[17];
    #pragma unroll
    for (int i = 0; i < 2; i++) {
        int i4 = threadIdx.x + i * 256;
        float4 g = g4[i4];
        float a = (v[i].x - mu) * inv * g.x;
        float b = (v[i].y - mu) * inv * g.y;
        float c = (v[i].z - mu) * inv * g.z;
        float d = (v[i].w - mu) * inv * g.w;
        if (HALF) {
            uint2 p;
            p.x = packh2(a, b);
            p.y = packh2(c, d);
            *(uint2*)(oh + (long)row * HID + i4 * 4) = p;
        } else {
            *(float4*)(outf + (long)row * HID + i4 * 4) = make_float4(a, b, c, d);
        }
    }
}

// ======================= batched weight transpose (single launch) =======================
// For each of NW weight matrices: W[K,N] fp32 -> Th[N,K] fp16.
// Tile 64(K) x 32(N), 256 threads; coalesced loads, coalesced __half2 stores.
#define NW 12
struct WDesc {
    const float* src[NW];
    __half* dst[NW];
    int K[NW];
    int N[NW];
    int off[NW + 1];   // tile prefix offsets
};

__global__ void __launch_bounds__(256) wsplit_all_kernel(WDesc d) {
    int bid = blockIdx.x;
    int m = 0;
    #pragma unroll
    for (int i = 0; i < NW; i++)
        if (bid >= d.off[i + 1]) m = i + 1;
    int local = bid - d.off[m];
    int K = d.K[m], N = d.N[m];
    int tiles_x = N >> 5;
    int by = (local / tiles_x) << 6;   // K offset
    int bx = (local % tiles_x) << 5;   // N offset
    const float* W = d.src[m];
    __half* Th = d.dst[m];

    __shared__ float t[64][33];
    int tid = threadIdx.x;
    int c = tid & 31, r0 = tid >> 5;
    #pragma unroll
    for (int i = 0; i < 8; i++)
        t[r0 + i * 8][c] = W[(long)(by + r0 + i * 8) * N + bx + c];
    __syncthreads();
    int kp = tid & 31, n0 = tid >> 5;
    #pragma unroll
    for (int i = 0; i < 4; i++) {
        int n = n0 + i * 8;
        __half2 v = __floats2half2_rn(t[kp * 2][n], t[kp * 2 + 1][n]);
        *(__half2*)(Th + (long)(bx + n) * K + by + kp * 2) = v;
    }
}

// ======================= persistent mma.sync fp16 GEMM (64x64 warp tiles) =======================
#define T_TILE 8192
#define STAGE_BYTES (2 * T_TILE)
#define NSTAGE 4
#define GSM_TOTAL (NSTAGE * STAGE_BYTES)
#define PERSIST_GRID 296

__device__ __forceinline__ void load_tile64(uint32_t sbase, const __half* __restrict__ P,
                                            int K, long k0, int tid) {
    #pragma unroll
    for (int i = 0; i < 4; i++) {
        int idx = tid + i * 128;
        int row = idx >> 2, c = idx & 3;
        const __half* src = P + (long)row * K + k0 + c * 8;
        uint32_t dst = sbase + row * 64 + ((c ^ ((row >> 1) & 3)) << 4);
        cp16(dst, src);
    }
}

template <int MODE>
__global__ void __launch_bounds__(128, 2) gemm_mma_kernel(
    const __half* __restrict__ A,
    const __half* __restrict__ B0, const __half* __restrict__ B1,
    const __half* __restrict__ B2,
    const float* __restrict__ bias, const float* res,
    float* Cf,
    __half* __restrict__ Ch0, __half* __restrict__ Ch1, __half* __restrict__ Ch2,
    int M, int N, int K, int ntx, int nty, int ntz)
{
    extern __shared__ char smem[];
    uint32_t sb = smem_u32(smem);
    int tid = threadIdx.x;
    int wid = tid >> 5, lane = tid & 31;
    int warp_m = wid >> 1, warp_n = wid & 1;
    int m0 = warp_m * 64, n0 = warp_n * 64;

    int grp = lane >> 3, lr = lane & 7;
    int rowA0 = m0 + (grp & 1) * 8 + lr;
    int ccA   = grp >> 1;
    int rowB0 = n0 + (grp >> 1) * 8 + lr;
    int ccB   = grp & 1;
    int xA = (rowA0 >> 1) & 3;
    int xB = (rowB0 >> 1) & 3;
    int nc = K / 32;
    int ntot = ntx * nty * ntz;

    for (int t = blockIdx.x; t < ntot; t += gridDim.x) {
        int z   = t / (ntx * nty);
        int rem = t - z * (ntx * nty);
        int by  = rem / ntx;
        int bx  = rem - by * ntx;
        int row0 = by * 128, col0 = bx * 128;

        const __half* B  = (z == 0) ? B0 : (z == 1) ? B1 : B2;
        __half* Ch = (z == 0) ? Ch0 : (z == 1) ? Ch1 : Ch2;

        const __half* pA = A + (long)row0 * K;
        const __half* pB = B + (long)col0 * K;

        float acc[4][8][4];
        #pragma unroll
        for (int i = 0; i < 4; i++)
            #pragma unroll
            for (int j = 0; j < 8; j++)
                #pragma unroll
                for (int q = 0; q < 4; q++) acc[i][j][q] = 0.f;

        __syncthreads();

        #pragma unroll
        for (int p = 0; p < 3; p++) {
            uint32_t st = sb + p * STAGE_BYTES;
            load_tile64(st,          pA, K, (long)p * 32, tid);
            load_tile64(st + T_TILE, pB, K, (long)p * 32, tid);
            cp_commit();
        }

        int s_comp = 0, s_load = 3;
        for (int c = 0; c < nc; c++) {
            cp_wait<2>();
            __syncthreads();
            if (c + 3 < nc) {
                uint32_t st = sb + s_load * STAGE_BYTES;
                long k0 = (long)(c + 3) * 32;
                load_tile64(st,          pA, K, k0, tid);
                load_tile64(st + T_TILE, pB, K, k0, tid);
            }
            cp_commit();

            uint32_t sA = sb + s_comp * STAGE_BYTES;
            uint32_t sB = sA + T_TILE;
            #pragma unroll
            for (int ks = 0; ks < 2; ks++) {
                uint32_t af[4][4], bf[4][4];
                #pragma unroll
                for (int mt = 0; mt < 4; mt++) {
                    uint32_t base = sA + (rowA0 + mt * 16) * 64;
                    ldmx4(af[mt], base + (((ks * 2 + ccA) ^ xA) << 4));
                }
                #pragma unroll
                for (int np = 0; np < 4; np++) {
                    uint32_t base = sB + (rowB0 + np * 16) * 64;
                    ldmx4(bf[np], base + (((ks * 2 + ccB) ^ xB) << 4));
                }
                #pragma unroll
                for (int mt = 0; mt < 4; mt++)
                    #pragma unroll
                    for (int nt = 0; nt < 8; nt++)
                        mma16816h(acc[mt][nt], af[mt], &bf[nt >> 1][(nt & 1) * 2]);
            }
            s_comp = (s_comp + 1) & 3;
            s_load = (s_load + 1) & 3;
        }

        int r = lane >> 2, c2 = (lane & 3) * 2;
        #pragma unroll
        for (int mt = 0; mt < 4; mt++) {
            #pragma unroll
            for (int nt = 0; nt < 8; nt++) {
                long gr = row0 + m0 + mt * 16 + r;
                long gc = col0 + n0 + nt * 8 + c2;
                #pragma unroll
                for (int hrow = 0; hrow < 2; hrow++) {
                    long grr = gr + hrow * 8;
                    float v0 = acc[mt][nt][hrow * 2 + 0];
                    float v1 = acc[mt][nt][hrow * 2 + 1];
                    if (MODE == 0) {
                        *(uint32_t*)(Ch + grr * N + gc) = packh2(v0, v1);
                    } else if (MODE == 1) {
                        float2 b = *(const float2*)(bias + gc);
                        float2 rr = *(const float2*)(res + grr * N + gc);
                        *(float2*)(Cf + grr * N + gc) = make_float2(v0 + b.x + rr.x, v1 + b.y + rr.y);
                    } else {
                        *(uint32_t*)(Ch + grr * N + gc) = packh2(gelu_tanh(v0), gelu_tanh(v1));
                    }
                }
            }
        }
    }
}

// ======================= tensor-core flash attention (plain fp16) =======================
#define AS_Q  0
#define AS_K0 16384
#define AS_V0 32768
#define AS_K1 49152
#define AS_V1 65536
#define AS_TOTAL 81920

__device__ __forceinline__ void stage_h(uint32_t sbase, const __half* __restrict__ src,
                                        int row0, int h, int tid) {
    #pragma unroll
    for (int i = 0; i < 4; i++) {
        int idx = tid + i * 256;
        int r = idx >> 3, c = idx & 7;
        cp16(sbase + r * 128 + ((c ^ (r & 7)) << 4),
             src + (long)(row0 + r) * HID + h * HDIM + c * 8);
    }
}

__global__ void __launch_bounds__(256) attn_mma_kernel(
    const __half* __restrict__ Q, const __half* __restrict__ K,
    const __half* __restrict__ V, __half* __restrict__ O)
{
    extern __shared__ char smem[];
    uint32_t sb = smem_u32(smem);
    int tid = threadIdx.x;
    int w = tid >> 5, lane = tid & 31;
    int qb = blockIdx.x, h = blockIdx.y;

    int grp = lane >> 3, lr = lane & 7;
    int rowQ = w * 16 + (grp & 1) * 8 + lr;
    int ccQ  = grp >> 1;
    int xQ = rowQ & 7;
    int rowK_off = (grp >> 1) * 8 + lr;
    int ccK  = grp & 1;
    int rowV_off = (grp & 1) * 8 + lr;
    int ccV_off  = grp >> 1;

    stage_h(sb + AS_Q,  Q, qb * 128, h, tid);
    stage_h(sb + AS_K0, K, 0,        h, tid);
    stage_h(sb + AS_V0, V, 0,        h, tid);
    cp_commit();
    cp_wait<0>();
    __syncthreads();

    uint32_t qf[4][4];
    #pragma unroll
    for (int ks = 0; ks < 4; ks++) {
        uint32_t base = sb + AS_Q + rowQ * 128;
        ldmx4(qf[ks], base + (((ks * 2 + ccQ) ^ xQ) << 4));
    }

    float oacc[8][4];
    #pragma unroll
    for (int i = 0; i < 8; i++)
        #pragma unroll
        for (int q = 0; q < 4; q++) oacc[i][q] = 0.f;
    float m0 = -1e30f, m1 = -1e30f, l0 = 0.f, l1 = 0.f;

    int qg0 = qb * 128 + w * 16 + (lane >> 2);
    int qg1 = qg0 + 8;
    const float scale = 0.125f;

    for (int kt = 0; kt <= qb; kt++) {
        uint32_t kb = sb + ((kt & 1) ? AS_K1 : AS_K0);
        uint32_t vb = sb + ((kt & 1) ? AS_V1 : AS_V0);
        if (kt < qb) {
            uint32_t kb2 = sb + ((kt & 1) ? AS_K0 : AS_K1);
            uint32_t vb2 = sb + ((kt & 1) ? AS_V0 : AS_V1);
            stage_h(kb2, K, (kt + 1) * 128, h, tid);
            stage_h(vb2, V, (kt + 1) * 128, h, tid);
            cp_commit();
        }

        float sacc[16][4];
        #pragma unroll
        for (int i = 0; i < 16; i++)
            #pragma unroll
            for (int q = 0; q < 4; q++) sacc[i][q] = 0.f;

        #pragma unroll
        for (int ks = 0; ks < 4; ks++) {
            #pragma unroll
            for (int nb = 0; nb < 8; nb++) {
                int rowK = nb * 16 + rowK_off;
                uint32_t bk[4];
                ldmx4(bk, kb + rowK * 128 + (((ks * 2 + ccK) ^ (rowK & 7)) << 4));
                mma16816h(sacc[nb * 2 + 0], qf[ks], &bk[0]);
                mma16816h(sacc[nb * 2 + 1], qf[ks], &bk[2]);
            }
        }
        #pragma unroll
        for (int nt = 0; nt < 16; nt++) {
            sacc[nt][0] *= scale; sacc[nt][1] *= scale;
            sacc[nt][2] *= scale; sacc[nt][3] *= scale;
        }

        if (kt == qb) {
            #pragma unroll
            for (int nt = 0; nt < 16; nt++) {
                int kg = kt * 128 + nt * 8 + 2 * (lane & 3);
                #pragma unroll
                for (int e = 0; e < 2; e++) {
                    if (kg + e > qg0) sacc[nt][e]     = -1e30f;
                    if (kg + e > qg1) sacc[nt][2 + e] = -1e30f;
                }
            }
        }

        float rm0 = -1e30f, rm1 = -1e30f;
        #pragma unroll
        for (int nt = 0; nt < 16; nt++) {
            rm0 = fmaxf(rm0, fmaxf(sacc[nt][0], sacc[nt][1]));
            rm1 = fmaxf(rm1, fmaxf(sacc[nt][2], sacc[nt][3]));
        }
        rm0 = fmaxf(rm0, __shfl_xor_sync(0xFFFFFFFFu, rm0, 1));
        rm0 = fmaxf(rm0, __shfl_xor_sync(0xFFFFFFFFu, rm0, 2));
        rm1 = fmaxf(rm1, __shfl_xor_sync(0xFFFFFFFFu, rm1, 1));
        rm1 = fmaxf(rm1, __shfl_xor_sync(0xFFFFFFFFu, rm1, 2));
        float mn0 = fmaxf(m0, rm0), mn1 = fmaxf(m1, rm1);
        float al0 = __expf(m0 - mn0), al1 = __expf(m1 - mn1);
        m0 = mn0; m1 = mn1;

        float rs0 = 0.f, rs1 = 0.f;
        #pragma unroll
        for (int nt = 0; nt < 16; nt++) {
            sacc[nt][0] = __expf(sacc[nt][0] - mn0);
            sacc[nt][1] = __expf(sacc[nt][1] - mn0);
            sacc[nt][2] = __expf(sacc[nt][2] - mn1);
            sacc[nt][3] = __expf(sacc[nt][3] - mn1);
            rs0 += sacc[nt][0] + sacc[nt][1];
            rs1 += sacc[nt][2] + sacc[nt][3];
        }
        rs0 += __shfl_xor_sync(0xFFFFFFFFu, rs0, 1);
        rs0 += __shfl_xor_sync(0xFFFFFFFFu, rs0, 2);
        rs1 += __shfl_xor_sync(0xFFFFFFFFu, rs1, 1);
        rs1 += __shfl_xor_sync(0xFFFFFFFFu, rs1, 2);
        l0 = l0 * al0 + rs0;
        l1 = l1 * al1 + rs1;

        #pragma unroll
        for (int i = 0; i < 8; i++) {
            oacc[i][0] *= al0; oacc[i][1] *= al0;
            oacc[i][2] *= al1; oacc[i][3] *= al1;
        }

        #pragma unroll
        for (int ks2 = 0; ks2 < 8; ks2++) {
            uint32_t ap[4];
            ap[0] = packh2(sacc[2 * ks2][0],     sacc[2 * ks2][1]);
            ap[1] = packh2(sacc[2 * ks2][2],     sacc[2 * ks2][3]);
            ap[2] = packh2(sacc[2 * ks2 + 1][0], sacc[2 * ks2 + 1][1]);
            ap[3] = packh2(sacc[2 * ks2 + 1][2], sacc[2 * ks2 + 1][3]);
            int rowV = ks2 * 16 + rowV_off;
            uint32_t vbase = vb + rowV * 128;
            #pragma unroll
            for (int db = 0; db < 4; db++) {
                int cc = db * 2 + ccV_off;
                uint32_t bv[4];
                ldmx4t(bv, vbase + ((cc ^ (rowV & 7)) << 4));
                mma16816h(oacc[db * 2 + 0], ap, &bv[0]);
                mma16816h(oacc[db * 2 + 1], ap, &bv[2]);
            }
        }

        if (kt < qb) {
            cp_wait<0>();
            __syncthreads();
        }
    }

    float i0 = 1.0f / l0, i1 = 1.0f / l1;
    long gr0 = qb * 128 + w * 16 + (lane >> 2);
    long gc0 = h * HDIM + 2 * (lane & 3);
    #pragma unroll
    for (int nto = 0; nto < 8; nto++) {
        long gc = gc0 + nto * 8;
        *(uint32_t*)(O + gr0 * HID + gc)       = packh2(oacc[nto][0] * i0, oacc[nto][1] * i0);
        *(uint32_t*)(O + (gr0 + 8) * HID + gc) = packh2(oacc[nto][2] * i1, oacc[nto][3] * i1);
    }
}

// ======================= orchestration =======================
extern "C" void kernel_launch(void* const* d_in, const int* in_sizes, int n_in,
                              void* d_out, int out_size) {
    const float* emb = (const float*)d_in[0];
    const float* Wq = (const float*)d_in[2];
    const float* Wk = (const float*)d_in[3];
    const float* Wv = (const float*)d_in[4];
    const float* Wo = (const float*)d_in[5];
    const float* bo = (const float*)d_in[6];
    const float* W1 = (const float*)d_in[7];
    const float* W2 = (const float*)d_in[8];
    const float* b2 = (const float*)d_in[9];
    const float* g1 = (const float*)d_in[10];
    const float* g2 = (const float*)d_in[11];
    const float* gf = (const float*)d_in[12];
    float* out = (float*)d_out;

    float* px;
    __half *pq, *pk, *pv, *ph, *pctx, *pmid;
    __half *wq, *wk, *wv, *wo, *w1, *w2;
    cudaGetSymbolAddress((void**)&px,   g_x);
    cudaGetSymbolAddress((void**)&pq,   g_q);
    cudaGetSymbolAddress((void**)&pk,   g_k);
    cudaGetSymbolAddress((void**)&pv,   g_v);
    cudaGetSymbolAddress((void**)&ph,   g_h);
    cudaGetSymbolAddress((void**)&pctx, g_ctx);
    cudaGetSymbolAddress((void**)&pmid, g_mid);
    cudaGetSymbolAddress((void**)&wq, g_wqt);
    cudaGetSymbolAddress((void**)&wk, g_wkt);
    cudaGetSymbolAddress((void**)&wv, g_wvt);
    cudaGetSymbolAddress((void**)&wo, g_wot);
    cudaGetSymbolAddress((void**)&w1, g_w1t);
    cudaGetSymbolAddress((void**)&w2, g_w2t);

    cudaFuncSetAttribute(gemm_mma_kernel<0>, cudaFuncAttributeMaxDynamicSharedMemorySize, GSM_TOTAL);
    cudaFuncSetAttribute(gemm_mma_kernel<1>, cudaFuncAttributeMaxDynamicSharedMemorySize, GSM_TOTAL);
    cudaFuncSetAttribute(gemm_mma_kernel<2>, cudaFuncAttributeMaxDynamicSharedMemorySize, GSM_TOTAL);
    cudaFuncSetAttribute(attn_mma_kernel, cudaFuncAttributeMaxDynamicSharedMemorySize, AS_TOTAL);

    // ---- single batched weight transpose launch ----
    {
        WDesc d;
        const int tHH = (HID / 64) * (HID / 32);   // 2048
        const int tW1 = (HID / 64) * (ISZ / 32);   // 8192
        const int tW2 = (ISZ / 64) * (HID / 32);   // 8192
        int idx = 0, off = 0;
        for (int l = 0; l < NLAYER; l++) {
            long oHH = (long)l * HID * HID, oHI = (long)l * HID * ISZ;
            const float* srcs[6] = {Wq + oHH, Wk + oHH, Wv + oHH, Wo + oHH, W1 + oHI, W2 + oHI};
            __half* dsts[6]      = {wq + oHH, wk + oHH, wv + oHH, wo + oHH, w1 + oHI, w2 + oHI};
            int Ks[6] = {HID, HID, HID, HID, HID, ISZ};
            int Ns[6] = {HID, HID, HID, HID, ISZ, HID};
            int Ts[6] = {tHH, tHH, tHH, tHH, tW1, tW2};
            for (int j = 0; j < 6; j++) {
                d.src[idx] = srcs[j]; d.dst[idx] = dsts[j];
                d.K[idx] = Ks[j]; d.N[idx] = Ns[j];
                d.off[idx] = off; off += Ts[j];
                idx++;
            }
        }
        d.off[NW] = off;
        wsplit_all_kernel<<<off, 256>>>(d);
    }

    dim3 gAttn(SEQ / 128, NHEAD);
    const int ntHH = (HID / 128) * (SEQ / 128);
    const int ntQKV = ntHH * 3;
    const int ntHI = (ISZ / 128) * (SEQ / 128);
    int gQKV = ntQKV < PERSIST_GRID ? ntQKV : PERSIST_GRID;
    int gHH  = ntHH  < PERSIST_GRID ? ntHH  : PERSIST_GRID;
    int gHI  = ntHI  < PERSIST_GRID ? ntHI  : PERSIST_GRID;

    for (int l = 0; l < NLAYER; l++) {
        long oHH = (long)l * HID * HID, oHI = (long)l * HID * ISZ;
        const float* xin = (l == 0) ? emb : px;   // layer0 reads emb directly (no copy)

        ln_kernel<1><<<SEQ, 256>>>(xin, g1 + l * HID, nullptr, ph);
        gemm_mma_kernel<0><<<gQKV, 128, GSM_TOTAL>>>(ph,
            wq + oHH, wk + oHH, wv + oHH,
            nullptr, nullptr, nullptr, pq, pk, pv,
            SEQ, HID, HID, HID / 128, SEQ / 128, 3);
        attn_mma_kernel<<<gAttn, 256, AS_TOTAL>>>(pq, pk, pv, pctx);
        // x = xin + ctx @ Wo + bo   (writes px; res = emb for layer 0)
        gemm_mma_kernel<1><<<gHH, 128, GSM_TOTAL>>>(pctx,
            wo + oHH, nullptr, nullptr,
            bo + l * HID, xin, px, nullptr, nullptr, nullptr,
            SEQ, HID, HID, HID / 128, SEQ / 128, 1);

        ln_kernel<1><<<SEQ, 256>>>(px, g2 + l * HID, nullptr, ph);
        gemm_mma_kernel<2><<<gHI, 128, GSM_TOTAL>>>(ph,
            w1 + oHI, nullptr, nullptr,
            nullptr, nullptr, nullptr, pmid, nullptr, nullptr,
            SEQ, ISZ, HID, ISZ / 128, SEQ / 128, 1);
        gemm_mma_kernel<1><<<gHH, 128, GSM_TOTAL>>>(pmid,
            w2 + oHI, nullptr, nullptr,
            b2 + l * HID, px, px, nullptr, nullptr, nullptr,
            SEQ, HID, ISZ, HID / 128, SEQ / 128, 1);
    }

    ln_kernel<0><<<SEQ, 256>>>(px, gf, out, nullptr);
}